// round 2
// baseline (speedup 1.0000x reference)
#include <cuda_runtime.h>
#include <cuda_bf16.h>
#include <cstddef>
#include <cstdint>

// Problem constants
#define BB 2
#define TT 8192
#define HH 8
#define DKV 128
#define HID 1024
#define CHUNK 64
#define NCH 128           // TT / CHUNK
#define MROWS (BB*TT)     // 16384
#define FMROWS (BB*TT*HH) // 131072
#define EPS 1e-5f

// -------- scratch (no cudaMalloc allowed) --------
__device__ float g_bufQ[MROWS * HID];   // q proj -> later q feature-mapped
__device__ float g_bufK[MROWS * HID];
__device__ float g_bufV[MROWS * HID];
__device__ float g_tmpA[MROWS * HID];   // fm branch 1
__device__ float g_tmpB[MROWS * HID];   // fm branch 2
__device__ float g_bufO[MROWS * HID];   // attention output (post-RMSNorm)
__device__ float g_kv[(size_t)BB * NCH * HH * DKV * DKV]; // 33.5M floats

// ============================================================
// Generic SGEMM: C[M,N] = A[M,K] @ W[N,K]^T (+ bias[N])
// BM=BN=128, BK=8, 256 threads, 8x8 per thread.
// Requires M%128==0, N%128==0, K%8==0 (true for all calls here).
// ============================================================
#define SG_PAD 132
__global__ __launch_bounds__(256) void sgemm_bt_kernel(
    const float* __restrict__ A, const float* __restrict__ W,
    const float* __restrict__ bias, float* __restrict__ C,
    int M, int N, int K)
{
    __shared__ float As[8][SG_PAD];
    __shared__ float Ws[8][SG_PAD];

    const int tid = threadIdx.x;
    const int tx = tid & 15;
    const int ty = tid >> 4;
    const int bm0 = blockIdx.y * 128;
    const int bn0 = blockIdx.x * 128;

    const int lr = tid >> 1;        // 0..127
    const int lc = (tid & 1) * 4;   // 0 or 4

    const float* Ap = A + (size_t)(bm0 + lr) * K + lc;
    const float* Wp = W + (size_t)(bn0 + lr) * K + lc;

    float acc[8][8];
#pragma unroll
    for (int i = 0; i < 8; i++)
#pragma unroll
        for (int j = 0; j < 8; j++) acc[i][j] = 0.f;

    for (int k0 = 0; k0 < K; k0 += 8) {
        float4 av = *(const float4*)(Ap + k0);
        float4 wv = *(const float4*)(Wp + k0);
        As[lc + 0][lr] = av.x; As[lc + 1][lr] = av.y;
        As[lc + 2][lr] = av.z; As[lc + 3][lr] = av.w;
        Ws[lc + 0][lr] = wv.x; Ws[lc + 1][lr] = wv.y;
        Ws[lc + 2][lr] = wv.z; Ws[lc + 3][lr] = wv.w;
        __syncthreads();
#pragma unroll
        for (int k = 0; k < 8; k++) {
            float a[8], b[8];
            *(float4*)(a)     = *(const float4*)&As[k][ty * 8];
            *(float4*)(a + 4) = *(const float4*)&As[k][ty * 8 + 4];
            *(float4*)(b)     = *(const float4*)&Ws[k][tx * 8];
            *(float4*)(b + 4) = *(const float4*)&Ws[k][tx * 8 + 4];
#pragma unroll
            for (int i = 0; i < 8; i++)
#pragma unroll
                for (int j = 0; j < 8; j++)
                    acc[i][j] += a[i] * b[j];
        }
        __syncthreads();
    }

    float bv[8];
#pragma unroll
    for (int j = 0; j < 8; j++)
        bv[j] = bias ? bias[bn0 + tx * 8 + j] : 0.f;

#pragma unroll
    for (int i = 0; i < 8; i++) {
        size_t row = (size_t)(bm0 + ty * 8 + i);
        float* cp = C + row * N + bn0 + tx * 8;
        float4 v0, v1;
        v0.x = acc[i][0] + bv[0]; v0.y = acc[i][1] + bv[1];
        v0.z = acc[i][2] + bv[2]; v0.w = acc[i][3] + bv[3];
        v1.x = acc[i][4] + bv[4]; v1.y = acc[i][5] + bv[5];
        v1.z = acc[i][6] + bv[6]; v1.w = acc[i][7] + bv[7];
        *(float4*)(cp)     = v0;
        *(float4*)(cp + 4) = v1;
    }
}

// ============================================================
// Hadamard: out = a * b * scale
// ============================================================
__global__ void hadamard_kernel(const float* __restrict__ a,
                                const float* __restrict__ b,
                                float* __restrict__ out, float scale)
{
    size_t i = ((size_t)blockIdx.x * blockDim.x + threadIdx.x) * 4;
    float4 av = *(const float4*)(a + i);
    float4 bv = *(const float4*)(b + i);
    float4 ov;
    ov.x = av.x * bv.x * scale;
    ov.y = av.y * bv.y * scale;
    ov.z = av.z * bv.z * scale;
    ov.w = av.w * bv.w * scale;
    *(float4*)(out + i) = ov;
}

// ============================================================
// Per-chunk kv = k_c^T @ v_c : [128,128] per (b,n,h)
// grid = B*NCH*H blocks, 256 threads, 8x8 per thread over 128x128
// ============================================================
__global__ __launch_bounds__(256) void chunk_kv_kernel(
    const float* __restrict__ k, const float* __restrict__ v,
    float* __restrict__ kv)
{
    extern __shared__ float sm[];
    float* ks = sm;              // [64][128]
    float* vs = sm + 64 * 128;   // [64][128]

    const int bid = blockIdx.x;
    const int h = bid % HH;
    const int n = (bid / HH) % NCH;
    const int b = bid / (HH * NCH);
    const size_t base = (((size_t)b * TT + (size_t)n * CHUNK) * HH + h) * DKV;

    const int tid = threadIdx.x;
    for (int off = tid * 4; off < 64 * 128; off += 256 * 4) {
        int c = off >> 7, d = off & 127;
        *(float4*)&ks[off] = *(const float4*)&k[base + (size_t)c * (HH * DKV) + d];
        *(float4*)&vs[off] = *(const float4*)&v[base + (size_t)c * (HH * DKV) + d];
    }
    __syncthreads();

    const int tx = tid & 15, ty = tid >> 4;
    float acc[8][8];
#pragma unroll
    for (int i = 0; i < 8; i++)
#pragma unroll
        for (int j = 0; j < 8; j++) acc[i][j] = 0.f;

    for (int c = 0; c < 64; c++) {
        float a[8], bb[8];
        *(float4*)(a)      = *(const float4*)&ks[c * 128 + ty * 8];
        *(float4*)(a + 4)  = *(const float4*)&ks[c * 128 + ty * 8 + 4];
        *(float4*)(bb)     = *(const float4*)&vs[c * 128 + tx * 8];
        *(float4*)(bb + 4) = *(const float4*)&vs[c * 128 + tx * 8 + 4];
#pragma unroll
        for (int i = 0; i < 8; i++)
#pragma unroll
            for (int j = 0; j < 8; j++)
                acc[i][j] += a[i] * bb[j];
    }

    float* outp = kv + (size_t)bid * (DKV * DKV);
#pragma unroll
    for (int i = 0; i < 8; i++) {
        float* cp = outp + (ty * 8 + i) * 128 + tx * 8;
        *(float4*)(cp)     = make_float4(acc[i][0], acc[i][1], acc[i][2], acc[i][3]);
        *(float4*)(cp + 4) = make_float4(acc[i][4], acc[i][5], acc[i][6], acc[i][7]);
    }
}

// ============================================================
// Exclusive prefix over chunks, element-parallel.
// B*H*16384 = 262144 independent scan lines of length NCH.
// In-place: kv[n] becomes S entering chunk n.
// ============================================================
__global__ void scan_kv_kernel(float* __restrict__ kv)
{
    int gid = blockIdx.x * blockDim.x + threadIdx.x;   // 0..262143
    int e = gid & 16383;
    int h = (gid >> 14) % HH;
    int b = gid / (16384 * HH);
    size_t idx = (((size_t)b * NCH) * HH + h) * 16384 + e;
    const size_t stride = (size_t)HH * 16384;
    float acc = 0.f;
#pragma unroll 4
    for (int n = 0; n < NCH; n++) {
        float x = kv[idx];
        kv[idx] = acc;
        acc += x;
        idx += stride;
    }
}

// ============================================================
// Per-chunk output: o = tril(q k^T) v + q @ S, fused RMSNorm.
// grid = B*NCH*H, 256 threads. Dynamic smem ~178KB.
// ============================================================
__global__ __launch_bounds__(256) void chunk_out_kernel(
    const float* __restrict__ q, const float* __restrict__ k,
    const float* __restrict__ v, const float* __restrict__ kvS,
    const float* __restrict__ rms_w, float* __restrict__ o)
{
    extern __shared__ float sm[];
    float* qT = sm;                   // [128][65] transposed
    float* kT = qT + 128 * 65;        // [128][65] transposed
    float* vs = kT + 128 * 65;        // [64][128]
    float* Ss = vs + 64 * 128;        // [128][128]
    float* AT = Ss + 128 * 128;       // [64][65] (A transposed: AT[c][r])
    float* rw = AT + 64 * 65;         // [128]

    const int bid = blockIdx.x;
    const int h = bid % HH;
    const int n = (bid / HH) % NCH;
    const int b = bid / (HH * NCH);
    const size_t base = (((size_t)b * TT + (size_t)n * CHUNK) * HH + h) * DKV;

    const int tid = threadIdx.x;

    // load q, k transposed (coalesced gmem reads, conflict-free smem writes)
    for (int off = tid; off < 64 * 128; off += 256) {
        int c = off >> 7, d = off & 127;
        qT[d * 65 + c] = q[base + (size_t)c * (HH * DKV) + d];
        kT[d * 65 + c] = k[base + (size_t)c * (HH * DKV) + d];
    }
    // v natural
    for (int off = tid * 4; off < 64 * 128; off += 256 * 4) {
        int c = off >> 7, d = off & 127;
        *(float4*)&vs[off] = *(const float4*)&v[base + (size_t)c * (HH * DKV) + d];
    }
    // S natural
    {
        const float* Sg = kvS + (size_t)bid * (DKV * DKV);
        for (int off = tid * 4; off < 128 * 128; off += 256 * 4)
            *(float4*)&Ss[off] = *(const float4*)&Sg[off];
    }
    if (tid < 128) rw[tid] = rms_w[tid];
    __syncthreads();

    const int tx = tid & 15, ty = tid >> 4;

    // ---- phase A: A[r][c] = dot(q[r], k[c]); store AT[c][r] masked ----
    {
        float accA[4][4];
#pragma unroll
        for (int i = 0; i < 4; i++)
#pragma unroll
            for (int j = 0; j < 4; j++) accA[i][j] = 0.f;
        for (int d = 0; d < 128; d++) {
            float a[4], bb[4];
#pragma unroll
            for (int i = 0; i < 4; i++) a[i] = qT[d * 65 + ty * 4 + i];
#pragma unroll
            for (int j = 0; j < 4; j++) bb[j] = kT[d * 65 + tx * 4 + j];
#pragma unroll
            for (int i = 0; i < 4; i++)
#pragma unroll
                for (int j = 0; j < 4; j++)
                    accA[i][j] += a[i] * bb[j];
        }
#pragma unroll
        for (int i = 0; i < 4; i++) {
            int r = ty * 4 + i;
#pragma unroll
            for (int j = 0; j < 4; j++) {
                int c = tx * 4 + j;
                AT[c * 65 + r] = (c <= r) ? accA[i][j] : 0.f;
            }
        }
    }
    __syncthreads();

    // ---- phase B: o[r][col] = sum_k q[r][k]*S[k][col] + sum_c A[r][c]*v[c][col]
    float acc[4][8];
#pragma unroll
    for (int i = 0; i < 4; i++)
#pragma unroll
        for (int j = 0; j < 8; j++) acc[i][j] = 0.f;

    for (int kk = 0; kk < 128; kk++) {
        float a[4], bb[8];
#pragma unroll
        for (int i = 0; i < 4; i++) a[i] = qT[kk * 65 + ty * 4 + i];
        *(float4*)(bb)     = *(const float4*)&Ss[kk * 128 + tx * 8];
        *(float4*)(bb + 4) = *(const float4*)&Ss[kk * 128 + tx * 8 + 4];
#pragma unroll
        for (int i = 0; i < 4; i++)
#pragma unroll
            for (int j = 0; j < 8; j++)
                acc[i][j] += a[i] * bb[j];
    }
    for (int c = 0; c < 64; c++) {
        float a[4], bb[8];
#pragma unroll
        for (int i = 0; i < 4; i++) a[i] = AT[c * 65 + ty * 4 + i];
        *(float4*)(bb)     = *(const float4*)&vs[c * 128 + tx * 8];
        *(float4*)(bb + 4) = *(const float4*)&vs[c * 128 + tx * 8 + 4];
#pragma unroll
        for (int i = 0; i < 4; i++)
#pragma unroll
            for (int j = 0; j < 8; j++)
                acc[i][j] += a[i] * bb[j];
    }

    // ---- RMSNorm per row (reduce across the 16 tx lanes sharing a row) ----
#pragma unroll
    for (int i = 0; i < 4; i++) {
        float s = 0.f;
#pragma unroll
        for (int j = 0; j < 8; j++) s += acc[i][j] * acc[i][j];
        s += __shfl_xor_sync(0xffffffffu, s, 1);
        s += __shfl_xor_sync(0xffffffffu, s, 2);
        s += __shfl_xor_sync(0xffffffffu, s, 4);
        s += __shfl_xor_sync(0xffffffffu, s, 8);
        float scale = rsqrtf(s * (1.0f / 128.0f) + EPS);
#pragma unroll
        for (int j = 0; j < 8; j++)
            acc[i][j] *= scale * rw[tx * 8 + j];
    }

    // ---- write o ----
#pragma unroll
    for (int i = 0; i < 4; i++) {
        int r = ty * 4 + i;
        float* op = o + base + (size_t)r * (HH * DKV) + tx * 8;
        *(float4*)(op)     = make_float4(acc[i][0], acc[i][1], acc[i][2], acc[i][3]);
        *(float4*)(op + 4) = make_float4(acc[i][4], acc[i][5], acc[i][6], acc[i][7]);
    }
}

// ============================================================
// Launch
// ============================================================
extern "C" void kernel_launch(void* const* d_in, const int* in_sizes, int n_in,
                              void* d_out, int out_size)
{
    const float* x      = (const float*)d_in[0];
    const float* Wq     = (const float*)d_in[1];
    const float* Wk     = (const float*)d_in[2];
    const float* Wv     = (const float*)d_in[3];
    const float* fmq_w1 = (const float*)d_in[4];
    const float* fmq_b1 = (const float*)d_in[5];
    const float* fmq_w2 = (const float*)d_in[6];
    const float* fmq_b2 = (const float*)d_in[7];
    const float* fmk_w1 = (const float*)d_in[8];
    const float* fmk_b1 = (const float*)d_in[9];
    const float* fmk_w2 = (const float*)d_in[10];
    const float* fmk_b2 = (const float*)d_in[11];
    const float* rms_w  = (const float*)d_in[12];
    const float* Wo     = (const float*)d_in[13];
    float* out = (float*)d_out;

    float *bQ, *bK, *bV, *tA, *tB, *bO, *bKV;
    cudaGetSymbolAddress((void**)&bQ, g_bufQ);
    cudaGetSymbolAddress((void**)&bK, g_bufK);
    cudaGetSymbolAddress((void**)&bV, g_bufV);
    cudaGetSymbolAddress((void**)&tA, g_tmpA);
    cudaGetSymbolAddress((void**)&tB, g_tmpB);
    cudaGetSymbolAddress((void**)&bO, g_bufO);
    cudaGetSymbolAddress((void**)&bKV, g_kv);

    const int smem_kv  = 2 * 64 * 128 * 4;                       // 64 KB
    const int smem_out = (2 * 128 * 65 + 64 * 128 + 128 * 128 + 64 * 65 + 128) * 4; // 182016 B
    cudaFuncSetAttribute(chunk_kv_kernel,  cudaFuncAttributeMaxDynamicSharedMemorySize, smem_kv);
    cudaFuncSetAttribute(chunk_out_kernel, cudaFuncAttributeMaxDynamicSharedMemorySize, smem_out);

    dim3 gBig(HID / 128, MROWS / 128);   // (8, 128)
    dim3 gFm(1, FMROWS / 128);           // (1, 1024)

    // projections
    sgemm_bt_kernel<<<gBig, 256>>>(x, Wq, nullptr, bQ, MROWS, HID, HID);
    sgemm_bt_kernel<<<gBig, 256>>>(x, Wk, nullptr, bK, MROWS, HID, HID);
    sgemm_bt_kernel<<<gBig, 256>>>(x, Wv, nullptr, bV, MROWS, HID, HID);

    // q feature map: (q@w1^T+b1)*(q@w2^T+b2)*scale  -> bQ
    sgemm_bt_kernel<<<gFm, 256>>>(bQ, fmq_w1, fmq_b1, tA, FMROWS, DKV, DKV);
    sgemm_bt_kernel<<<gFm, 256>>>(bQ, fmq_w2, fmq_b2, tB, FMROWS, DKV, DKV);
    const float scale = 0.08838834764831845f; // 128^-0.5
    hadamard_kernel<<<(MROWS * HID) / (256 * 4), 256>>>(tA, tB, bQ, scale);

    // k feature map -> bK
    sgemm_bt_kernel<<<gFm, 256>>>(bK, fmk_w1, fmk_b1, tA, FMROWS, DKV, DKV);
    sgemm_bt_kernel<<<gFm, 256>>>(bK, fmk_w2, fmk_b2, tB, FMROWS, DKV, DKV);
    hadamard_kernel<<<(MROWS * HID) / (256 * 4), 256>>>(tA, tB, bK, 1.0f);

    // chunked linear attention
    const int nBlk = BB * NCH * HH; // 2048
    chunk_kv_kernel<<<nBlk, 256, smem_kv>>>(bK, bV, bKV);
    scan_kv_kernel<<<(BB * HH * 16384) / 256, 256>>>(bKV);
    chunk_out_kernel<<<nBlk, 256, smem_out>>>(bQ, bK, bV, bKV, rms_w, bO);

    // output projection
    sgemm_bt_kernel<<<gBig, 256>>>(bO, Wo, nullptr, out, MROWS, HID, HID);
}

// round 6
// speedup vs baseline: 1.7289x; 1.7289x over previous
#include <cuda_runtime.h>
#include <cuda_bf16.h>
#include <cstddef>
#include <cstdint>

// Problem constants
#define BB 2
#define TT 8192
#define HH 8
#define DKV 128
#define HID 1024
#define CHUNK 64
#define NCH 128           // TT / CHUNK
#define MROWS (BB*TT)     // 16384
#define FMROWS (BB*TT*HH) // 131072
#define EPS 1e-5f
#define K3BIG (3*HID)     // 3072
#define K3FM  (3*DKV)     // 384

// -------- fp32 scratch --------
__device__ float g_bufQ[MROWS * HID];
__device__ float g_bufK[MROWS * HID];
__device__ float g_bufV[MROWS * HID];
__device__ float g_tmpA[MROWS * HID];
__device__ float g_tmpB[MROWS * HID];
__device__ float g_bufO[MROWS * HID];
__device__ float g_kv[(size_t)BB * NCH * HH * DKV * DKV];

// -------- bf16 split scratch --------
__device__ __nv_bfloat16 g_xs [(size_t)MROWS * K3BIG];
__device__ __nv_bfloat16 g_ws [(size_t)4 * HID * K3BIG];     // Wq,Wk,Wv,Wo (hi|lo|hi)
__device__ __nv_bfloat16 g_fmw[(size_t)4 * DKV * K3FM];      // fm weights (hi|lo|hi)
__device__ __nv_bfloat16 g_q1s[(size_t)FMROWS * K3FM];
__device__ __nv_bfloat16 g_k1s[(size_t)FMROWS * K3FM];
__device__ __nv_bfloat16 g_os [(size_t)MROWS * K3BIG];

__device__ __forceinline__ uint32_t smem_u32(const void* p) {
    uint32_t a;
    asm("{ .reg .u64 t; cvta.to.shared.u64 t, %1; cvt.u32.u64 %0, t; }"
        : "=r"(a) : "l"(p));
    return a;
}

// ============================================================
// split3: fp32 [R,K] -> bf16 [R,3K]
//   mode 0 (activations): [hi | hi | lo]
//   mode 1 (weights):     [hi | lo | hi]
// Dot over 3K gives AhWh + AhWl + AlWh  (drops only AlWl ~ 2^-18)
// ============================================================
__global__ void split3_kernel(const float* __restrict__ in,
                              __nv_bfloat16* __restrict__ out,
                              int log2K, size_t total, int mode)
{
    size_t i = ((size_t)blockIdx.x * blockDim.x + threadIdx.x) * 2;
    if (i >= total) return;
    const int K = 1 << log2K;
    size_t r = i >> log2K;
    int c = (int)(i & (size_t)(K - 1));
    float2 x = *(const float2*)(in + i);
    __nv_bfloat16 h0 = __float2bfloat16(x.x);
    __nv_bfloat16 h1 = __float2bfloat16(x.y);
    __nv_bfloat16 l0 = __float2bfloat16(x.x - __bfloat162float(h0));
    __nv_bfloat16 l1 = __float2bfloat16(x.y - __bfloat162float(h1));
    __nv_bfloat162 hv; hv.x = h0; hv.y = h1;
    __nv_bfloat162 lv; lv.x = l0; lv.y = l1;
    __nv_bfloat16* o = out + r * (size_t)(3 * K) + c;
    *(__nv_bfloat162*)(o) = hv;
    if (mode == 0) {
        *(__nv_bfloat162*)(o + K)     = hv;
        *(__nv_bfloat162*)(o + 2 * K) = lv;
    } else {
        *(__nv_bfloat162*)(o + K)     = lv;
        *(__nv_bfloat162*)(o + 2 * K) = hv;
    }
}

// ============================================================
// Tensor-core GEMM (mma.sync, baseline PTX — assembles at compute_103):
// C[M,N] = A[M,K] @ B[N,K]^T (+bias), bf16 in, fp32 out.
// CTA tile 128x128, BK=32, 8 warps (warp tile 32x64), cp.async
// double buffering, ldmatrix + m16n8k16 bf16 mma, fp32 accum.
// grid = (N/128, M/128), 256 threads. K % 32 == 0.
// ============================================================
#define SROW 40          // smem row stride in bf16 (32 data + 8 pad = 80B)
#define STAGE_HALF (128 * SROW)

__global__ __launch_bounds__(256) void mma_gemm_kernel(
    const __nv_bfloat16* __restrict__ A,
    const __nv_bfloat16* __restrict__ B,
    const float* __restrict__ bias,
    float* __restrict__ C,
    int N, int K)
{
    __shared__ __nv_bfloat16 sA[2][STAGE_HALF];
    __shared__ __nv_bfloat16 sB[2][STAGE_HALF];

    const int tid = threadIdx.x;
    const int lane = tid & 31;
    const int wid = tid >> 5;
    const int warp_m = (wid & 3) * 32;
    const int warp_n = (wid >> 2) * 64;
    const int bm0 = blockIdx.y * 128;
    const int bn0 = blockIdx.x * 128;
    const int NC = K >> 5;

    const size_t rowb = (size_t)K * 2;
    const char* Ag = (const char*)A + (size_t)bm0 * rowb;
    const char* Bg = (const char*)B + (size_t)bn0 * rowb;

    const uint32_t sAb = smem_u32(sA);
    const uint32_t sBb = smem_u32(sB);

    // per-thread load coords: 2 x 16B segments per tile per stage
    const int ch0 = tid;            // 0..255
    const int ch1 = tid + 256;      // 256..511
    const int r0 = ch0 >> 2, g0 = ch0 & 3;
    const int r1 = ch1 >> 2, g1 = ch1 & 3;

    auto load_stage = [&](int kc, int s) {
        const size_t koff = (size_t)kc * 64;
        uint32_t sa0 = sAb + (uint32_t)(s * STAGE_HALF * 2 + r0 * 80 + g0 * 16);
        uint32_t sa1 = sAb + (uint32_t)(s * STAGE_HALF * 2 + r1 * 80 + g1 * 16);
        uint32_t sb0 = sBb + (uint32_t)(s * STAGE_HALF * 2 + r0 * 80 + g0 * 16);
        uint32_t sb1 = sBb + (uint32_t)(s * STAGE_HALF * 2 + r1 * 80 + g1 * 16);
        const void* ga0 = Ag + (size_t)r0 * rowb + koff + g0 * 16;
        const void* ga1 = Ag + (size_t)r1 * rowb + koff + g1 * 16;
        const void* gb0 = Bg + (size_t)r0 * rowb + koff + g0 * 16;
        const void* gb1 = Bg + (size_t)r1 * rowb + koff + g1 * 16;
        asm volatile("cp.async.cg.shared.global [%0], [%1], 16;" :: "r"(sa0), "l"(ga0));
        asm volatile("cp.async.cg.shared.global [%0], [%1], 16;" :: "r"(sa1), "l"(ga1));
        asm volatile("cp.async.cg.shared.global [%0], [%1], 16;" :: "r"(sb0), "l"(gb0));
        asm volatile("cp.async.cg.shared.global [%0], [%1], 16;" :: "r"(sb1), "l"(gb1));
        asm volatile("cp.async.commit_group;");
    };

    float acc[2][8][4];
#pragma unroll
    for (int mt = 0; mt < 2; mt++)
#pragma unroll
        for (int nt = 0; nt < 8; nt++)
#pragma unroll
            for (int j = 0; j < 4; j++) acc[mt][nt][j] = 0.f;

    load_stage(0, 0);
    load_stage(1, 1);

    const int lm = lane & 15;
    const int lk = lane >> 4;
    const uint32_t aFragBase = sAb + (uint32_t)((warp_m + lm) * 80 + lk * 16);
    const uint32_t bFragBase = sBb + (uint32_t)((warp_n + lm) * 80 + lk * 16);

    for (int kc = 0; kc < NC; kc++) {
        const int s = kc & 1;
        if (kc + 1 < NC) asm volatile("cp.async.wait_group 1;");
        else             asm volatile("cp.async.wait_group 0;");
        __syncthreads();

        const uint32_t aSt = aFragBase + (uint32_t)(s * STAGE_HALF * 2);
        const uint32_t bSt = bFragBase + (uint32_t)(s * STAGE_HALF * 2);
#pragma unroll
        for (int ks = 0; ks < 2; ks++) {
            uint32_t a[2][4], bf[4][4];
#pragma unroll
            for (int mt = 0; mt < 2; mt++) {
                uint32_t ad = aSt + (uint32_t)(mt * 16 * 80 + ks * 32);
                asm volatile("ldmatrix.sync.aligned.m8n8.x4.shared.b16 {%0,%1,%2,%3}, [%4];"
                             : "=r"(a[mt][0]), "=r"(a[mt][1]), "=r"(a[mt][2]), "=r"(a[mt][3])
                             : "r"(ad));
            }
#pragma unroll
            for (int ng = 0; ng < 4; ng++) {
                uint32_t bd = bSt + (uint32_t)(ng * 16 * 80 + ks * 32);
                asm volatile("ldmatrix.sync.aligned.m8n8.x4.shared.b16 {%0,%1,%2,%3}, [%4];"
                             : "=r"(bf[ng][0]), "=r"(bf[ng][1]), "=r"(bf[ng][2]), "=r"(bf[ng][3])
                             : "r"(bd));
            }
#pragma unroll
            for (int mt = 0; mt < 2; mt++)
#pragma unroll
                for (int nt = 0; nt < 8; nt++) {
                    const int g = nt >> 1, sel = nt & 1;
                    asm volatile(
                        "mma.sync.aligned.m16n8k16.row.col.f32.bf16.bf16.f32 "
                        "{%0,%1,%2,%3}, {%4,%5,%6,%7}, {%8,%9}, {%0,%1,%2,%3};"
                        : "+f"(acc[mt][nt][0]), "+f"(acc[mt][nt][1]),
                          "+f"(acc[mt][nt][2]), "+f"(acc[mt][nt][3])
                        : "r"(a[mt][0]), "r"(a[mt][1]), "r"(a[mt][2]), "r"(a[mt][3]),
                          "r"(bf[g][sel]), "r"(bf[g][sel + 2]));
                }
        }
        __syncthreads();
        if (kc + 2 < NC) load_stage(kc + 2, s);
    }

    // epilogue
    const int erow = bm0 + warp_m + (lane >> 2);
    const int ecol0 = bn0 + warp_n + (lane & 3) * 2;
#pragma unroll
    for (int nt = 0; nt < 8; nt++) {
        const int col = ecol0 + nt * 8;
        float bx = 0.f, by = 0.f;
        if (bias) { bx = bias[col]; by = bias[col + 1]; }
#pragma unroll
        for (int mt = 0; mt < 2; mt++) {
            const int row = erow + mt * 16;
            float2 v0 = make_float2(acc[mt][nt][0] + bx, acc[mt][nt][1] + by);
            float2 v1 = make_float2(acc[mt][nt][2] + bx, acc[mt][nt][3] + by);
            *(float2*)(C + (size_t)row * N + col)       = v0;
            *(float2*)(C + (size_t)(row + 8) * N + col) = v1;
        }
    }
}

// ============================================================
// Hadamard: out = a * b * scale
// ============================================================
__global__ void hadamard_kernel(const float* __restrict__ a,
                                const float* __restrict__ b,
                                float* __restrict__ out, float scale)
{
    size_t i = ((size_t)blockIdx.x * blockDim.x + threadIdx.x) * 4;
    float4 av = *(const float4*)(a + i);
    float4 bv = *(const float4*)(b + i);
    float4 ov;
    ov.x = av.x * bv.x * scale;
    ov.y = av.y * bv.y * scale;
    ov.z = av.z * bv.z * scale;
    ov.w = av.w * bv.w * scale;
    *(float4*)(out + i) = ov;
}

// ============================================================
// Per-chunk kv = k_c^T @ v_c : [128,128] per (b,n,h)
// ============================================================
__global__ __launch_bounds__(256) void chunk_kv_kernel(
    const float* __restrict__ k, const float* __restrict__ v,
    float* __restrict__ kv)
{
    extern __shared__ float sm[];
    float* ks = sm;
    float* vs = sm + 64 * 128;

    const int bid = blockIdx.x;
    const int h = bid % HH;
    const int n = (bid / HH) % NCH;
    const int b = bid / (HH * NCH);
    const size_t base = (((size_t)b * TT + (size_t)n * CHUNK) * HH + h) * DKV;

    const int tid = threadIdx.x;
    for (int off = tid * 4; off < 64 * 128; off += 256 * 4) {
        int c = off >> 7, d = off & 127;
        *(float4*)&ks[off] = *(const float4*)&k[base + (size_t)c * (HH * DKV) + d];
        *(float4*)&vs[off] = *(const float4*)&v[base + (size_t)c * (HH * DKV) + d];
    }
    __syncthreads();

    const int tx = tid & 15, ty = tid >> 4;
    float acc[8][8];
#pragma unroll
    for (int i = 0; i < 8; i++)
#pragma unroll
        for (int j = 0; j < 8; j++) acc[i][j] = 0.f;

    for (int c = 0; c < 64; c++) {
        float a[8], bb[8];
        *(float4*)(a)      = *(const float4*)&ks[c * 128 + ty * 8];
        *(float4*)(a + 4)  = *(const float4*)&ks[c * 128 + ty * 8 + 4];
        *(float4*)(bb)     = *(const float4*)&vs[c * 128 + tx * 8];
        *(float4*)(bb + 4) = *(const float4*)&vs[c * 128 + tx * 8 + 4];
#pragma unroll
        for (int i = 0; i < 8; i++)
#pragma unroll
            for (int j = 0; j < 8; j++)
                acc[i][j] += a[i] * bb[j];
    }

    float* outp = kv + (size_t)bid * (DKV * DKV);
#pragma unroll
    for (int i = 0; i < 8; i++) {
        float* cp = outp + (ty * 8 + i) * 128 + tx * 8;
        *(float4*)(cp)     = make_float4(acc[i][0], acc[i][1], acc[i][2], acc[i][3]);
        *(float4*)(cp + 4) = make_float4(acc[i][4], acc[i][5], acc[i][6], acc[i][7]);
    }
}

// ============================================================
// Exclusive prefix over chunks (in-place)
// ============================================================
__global__ void scan_kv_kernel(float* __restrict__ kv)
{
    int gid = blockIdx.x * blockDim.x + threadIdx.x;
    int e = gid & 16383;
    int h = (gid >> 14) % HH;
    int b = gid / (16384 * HH);
    size_t idx = (((size_t)b * NCH) * HH + h) * 16384 + e;
    const size_t stride = (size_t)HH * 16384;
    float acc = 0.f;
#pragma unroll 4
    for (int n = 0; n < NCH; n++) {
        float x = kv[idx];
        kv[idx] = acc;
        acc += x;
        idx += stride;
    }
}

// ============================================================
// Per-chunk output: o = tril(q k^T) v + q @ S, fused RMSNorm
// ============================================================
__global__ __launch_bounds__(256) void chunk_out_kernel(
    const float* __restrict__ q, const float* __restrict__ k,
    const float* __restrict__ v, const float* __restrict__ kvS,
    const float* __restrict__ rms_w, float* __restrict__ o)
{
    extern __shared__ float sm[];
    float* qT = sm;
    float* kT = qT + 128 * 65;
    float* vs = kT + 128 * 65;
    float* Ss = vs + 64 * 128;
    float* AT = Ss + 128 * 128;
    float* rw = AT + 64 * 65;

    const int bid = blockIdx.x;
    const int h = bid % HH;
    const int n = (bid / HH) % NCH;
    const int b = bid / (HH * NCH);
    const size_t base = (((size_t)b * TT + (size_t)n * CHUNK) * HH + h) * DKV;

    const int tid = threadIdx.x;

    for (int off = tid; off < 64 * 128; off += 256) {
        int c = off >> 7, d = off & 127;
        qT[d * 65 + c] = q[base + (size_t)c * (HH * DKV) + d];
        kT[d * 65 + c] = k[base + (size_t)c * (HH * DKV) + d];
    }
    for (int off = tid * 4; off < 64 * 128; off += 256 * 4) {
        int c = off >> 7, d = off & 127;
        *(float4*)&vs[off] = *(const float4*)&v[base + (size_t)c * (HH * DKV) + d];
    }
    {
        const float* Sg = kvS + (size_t)bid * (DKV * DKV);
        for (int off = tid * 4; off < 128 * 128; off += 256 * 4)
            *(float4*)&Ss[off] = *(const float4*)&Sg[off];
    }
    if (tid < 128) rw[tid] = rms_w[tid];
    __syncthreads();

    const int tx = tid & 15, ty = tid >> 4;

    {
        float accA[4][4];
#pragma unroll
        for (int i = 0; i < 4; i++)
#pragma unroll
            for (int j = 0; j < 4; j++) accA[i][j] = 0.f;
        for (int d = 0; d < 128; d++) {
            float a[4], bb[4];
#pragma unroll
            for (int i = 0; i < 4; i++) a[i] = qT[d * 65 + ty * 4 + i];
#pragma unroll
            for (int j = 0; j < 4; j++) bb[j] = kT[d * 65 + tx * 4 + j];
#pragma unroll
            for (int i = 0; i < 4; i++)
#pragma unroll
                for (int j = 0; j < 4; j++)
                    accA[i][j] += a[i] * bb[j];
        }
#pragma unroll
        for (int i = 0; i < 4; i++) {
            int r = ty * 4 + i;
#pragma unroll
            for (int j = 0; j < 4; j++) {
                int c = tx * 4 + j;
                AT[c * 65 + r] = (c <= r) ? accA[i][j] : 0.f;
            }
        }
    }
    __syncthreads();

    float acc[4][8];
#pragma unroll
    for (int i = 0; i < 4; i++)
#pragma unroll
        for (int j = 0; j < 8; j++) acc[i][j] = 0.f;

    for (int kk = 0; kk < 128; kk++) {
        float a[4], bb[8];
#pragma unroll
        for (int i = 0; i < 4; i++) a[i] = qT[kk * 65 + ty * 4 + i];
        *(float4*)(bb)     = *(const float4*)&Ss[kk * 128 + tx * 8];
        *(float4*)(bb + 4) = *(const float4*)&Ss[kk * 128 + tx * 8 + 4];
#pragma unroll
        for (int i = 0; i < 4; i++)
#pragma unroll
            for (int j = 0; j < 8; j++)
                acc[i][j] += a[i] * bb[j];
    }
    for (int c = 0; c < 64; c++) {
        float a[4], bb[8];
#pragma unroll
        for (int i = 0; i < 4; i++) a[i] = AT[c * 65 + ty * 4 + i];
        *(float4*)(bb)     = *(const float4*)&vs[c * 128 + tx * 8];
        *(float4*)(bb + 4) = *(const float4*)&vs[c * 128 + tx * 8 + 4];
#pragma unroll
        for (int i = 0; i < 4; i++)
#pragma unroll
            for (int j = 0; j < 8; j++)
                acc[i][j] += a[i] * bb[j];
    }

#pragma unroll
    for (int i = 0; i < 4; i++) {
        float s = 0.f;
#pragma unroll
        for (int j = 0; j < 8; j++) s += acc[i][j] * acc[i][j];
        s += __shfl_xor_sync(0xffffffffu, s, 1);
        s += __shfl_xor_sync(0xffffffffu, s, 2);
        s += __shfl_xor_sync(0xffffffffu, s, 4);
        s += __shfl_xor_sync(0xffffffffu, s, 8);
        float scale = rsqrtf(s * (1.0f / 128.0f) + EPS);
#pragma unroll
        for (int j = 0; j < 8; j++)
            acc[i][j] *= scale * rw[tx * 8 + j];
    }

#pragma unroll
    for (int i = 0; i < 4; i++) {
        int r = ty * 4 + i;
        float* op = o + base + (size_t)r * (HH * DKV) + tx * 8;
        *(float4*)(op)     = make_float4(acc[i][0], acc[i][1], acc[i][2], acc[i][3]);
        *(float4*)(op + 4) = make_float4(acc[i][4], acc[i][5], acc[i][6], acc[i][7]);
    }
}

// ============================================================
// Launch
// ============================================================
extern "C" void kernel_launch(void* const* d_in, const int* in_sizes, int n_in,
                              void* d_out, int out_size)
{
    const float* x      = (const float*)d_in[0];
    const float* Wq     = (const float*)d_in[1];
    const float* Wk     = (const float*)d_in[2];
    const float* Wv     = (const float*)d_in[3];
    const float* fmq_w1 = (const float*)d_in[4];
    const float* fmq_b1 = (const float*)d_in[5];
    const float* fmq_w2 = (const float*)d_in[6];
    const float* fmq_b2 = (const float*)d_in[7];
    const float* fmk_w1 = (const float*)d_in[8];
    const float* fmk_b1 = (const float*)d_in[9];
    const float* fmk_w2 = (const float*)d_in[10];
    const float* fmk_b2 = (const float*)d_in[11];
    const float* rms_w  = (const float*)d_in[12];
    const float* Wo     = (const float*)d_in[13];
    float* out = (float*)d_out;

    float *bQ, *bK, *bV, *tA, *tB, *bO, *bKV;
    cudaGetSymbolAddress((void**)&bQ, g_bufQ);
    cudaGetSymbolAddress((void**)&bK, g_bufK);
    cudaGetSymbolAddress((void**)&bV, g_bufV);
    cudaGetSymbolAddress((void**)&tA, g_tmpA);
    cudaGetSymbolAddress((void**)&tB, g_tmpB);
    cudaGetSymbolAddress((void**)&bO, g_bufO);
    cudaGetSymbolAddress((void**)&bKV, g_kv);

    __nv_bfloat16 *xs, *ws, *fmw, *q1s, *k1s, *os;
    cudaGetSymbolAddress((void**)&xs,  g_xs);
    cudaGetSymbolAddress((void**)&ws,  g_ws);
    cudaGetSymbolAddress((void**)&fmw, g_fmw);
    cudaGetSymbolAddress((void**)&q1s, g_q1s);
    cudaGetSymbolAddress((void**)&k1s, g_k1s);
    cudaGetSymbolAddress((void**)&os,  g_os);

    const int smem_kv  = 2 * 64 * 128 * 4;
    const int smem_out = (2 * 128 * 65 + 64 * 128 + 128 * 128 + 64 * 65 + 128) * 4;
    cudaFuncSetAttribute(chunk_kv_kernel,  cudaFuncAttributeMaxDynamicSharedMemorySize, smem_kv);
    cudaFuncSetAttribute(chunk_out_kernel, cudaFuncAttributeMaxDynamicSharedMemorySize, smem_out);

    const size_t wsz = (size_t)HID * K3BIG;
    const size_t fsz = (size_t)DKV * K3FM;

    // ---- split conversions (mode 0 = activations, mode 1 = weights) ----
    split3_kernel<<<(MROWS * HID) / 512, 256>>>(x, xs, 10, (size_t)MROWS * HID, 0);
    split3_kernel<<<(HID * HID) / 512, 256>>>(Wq, ws + 0 * wsz, 10, (size_t)HID * HID, 1);
    split3_kernel<<<(HID * HID) / 512, 256>>>(Wk, ws + 1 * wsz, 10, (size_t)HID * HID, 1);
    split3_kernel<<<(HID * HID) / 512, 256>>>(Wv, ws + 2 * wsz, 10, (size_t)HID * HID, 1);
    split3_kernel<<<(HID * HID) / 512, 256>>>(Wo, ws + 3 * wsz, 10, (size_t)HID * HID, 1);
    split3_kernel<<<(DKV * DKV) / 512, 256>>>(fmq_w1, fmw + 0 * fsz, 7, (size_t)DKV * DKV, 1);
    split3_kernel<<<(DKV * DKV) / 512, 256>>>(fmq_w2, fmw + 1 * fsz, 7, (size_t)DKV * DKV, 1);
    split3_kernel<<<(DKV * DKV) / 512, 256>>>(fmk_w1, fmw + 2 * fsz, 7, (size_t)DKV * DKV, 1);
    split3_kernel<<<(DKV * DKV) / 512, 256>>>(fmk_w2, fmw + 3 * fsz, 7, (size_t)DKV * DKV, 1);

    // ---- projections (tensor) ----
    dim3 gBig(HID / 128, MROWS / 128);   // (8, 128)
    mma_gemm_kernel<<<gBig, 256>>>(xs, ws + 0 * wsz, nullptr, bQ, HID, K3BIG);
    mma_gemm_kernel<<<gBig, 256>>>(xs, ws + 1 * wsz, nullptr, bK, HID, K3BIG);
    mma_gemm_kernel<<<gBig, 256>>>(xs, ws + 2 * wsz, nullptr, bV, HID, K3BIG);

    // ---- feature maps (tensor) ----
    dim3 gFm(1, FMROWS / 128);           // (1, 1024)
    const float scale = 0.08838834764831845f; // 128^-0.5

    split3_kernel<<<(MROWS * HID) / 512, 256>>>(bQ, q1s, 7, (size_t)MROWS * HID, 0);
    mma_gemm_kernel<<<gFm, 256>>>(q1s, fmw + 0 * fsz, fmq_b1, tA, DKV, K3FM);
    mma_gemm_kernel<<<gFm, 256>>>(q1s, fmw + 1 * fsz, fmq_b2, tB, DKV, K3FM);
    hadamard_kernel<<<(MROWS * HID) / 1024, 256>>>(tA, tB, bQ, scale);

    split3_kernel<<<(MROWS * HID) / 512, 256>>>(bK, k1s, 7, (size_t)MROWS * HID, 0);
    mma_gemm_kernel<<<gFm, 256>>>(k1s, fmw + 2 * fsz, fmk_b1, tA, DKV, K3FM);
    mma_gemm_kernel<<<gFm, 256>>>(k1s, fmw + 3 * fsz, fmk_b2, tB, DKV, K3FM);
    hadamard_kernel<<<(MROWS * HID) / 1024, 256>>>(tA, tB, bK, 1.0f);

    // ---- chunked linear attention (fp32) ----
    const int nBlk = BB * NCH * HH;
    chunk_kv_kernel<<<nBlk, 256, smem_kv>>>(bK, bV, bKV);
    scan_kv_kernel<<<(BB * HH * 16384) / 256, 256>>>(bKV);
    chunk_out_kernel<<<nBlk, 256, smem_out>>>(bQ, bK, bV, bKV, rms_w, bO);

    // ---- output projection (tensor) ----
    split3_kernel<<<(MROWS * HID) / 512, 256>>>(bO, os, 10, (size_t)MROWS * HID, 0);
    mma_gemm_kernel<<<gBig, 256>>>(os, ws + 3 * wsz, nullptr, out, HID, K3BIG);
}

// round 7
// speedup vs baseline: 1.7479x; 1.0110x over previous
#include <cuda_runtime.h>
#include <cuda_bf16.h>
#include <cstddef>
#include <cstdint>

// Problem constants
#define BB 2
#define TT 8192
#define HH 8
#define DKV 128
#define HID 1024
#define CHUNK 64
#define NCH 128           // TT / CHUNK
#define MROWS (BB*TT)     // 16384
#define FMROWS (BB*TT*HH) // 131072
#define EPS 1e-5f
#define K3BIG (3*HID)     // 3072
#define K3FM  (3*DKV)     // 384

// -------- fp32 scratch --------
__device__ float g_bufQ[MROWS * HID];   // q after feature map (attention input)
__device__ float g_bufK[MROWS * HID];   // k after feature map
__device__ float g_bufV[MROWS * HID];   // v projection
__device__ float g_tmpA[MROWS * HID];   // fm branch 1 output
__device__ float g_kv[(size_t)BB * NCH * HH * DKV * DKV];

// -------- bf16 split scratch --------
__device__ __nv_bfloat16 g_xs [(size_t)MROWS * K3BIG];       // x split (activation mode)
__device__ __nv_bfloat16 g_ws [(size_t)4 * HID * K3BIG];     // Wq,Wk,Wv,Wo (hi|lo|hi)
__device__ __nv_bfloat16 g_fmw[(size_t)4 * DKV * K3FM];      // fm weights (hi|lo|hi)
__device__ __nv_bfloat16 g_q1s[(size_t)FMROWS * K3FM];       // q proj split (hi|hi|lo)
__device__ __nv_bfloat16 g_k1s[(size_t)FMROWS * K3FM];       // k proj split
__device__ __nv_bfloat16 g_os [(size_t)MROWS * K3BIG];       // attention out split

__device__ __forceinline__ uint32_t smem_u32(const void* p) {
    uint32_t a;
    asm("{ .reg .u64 t; cvta.to.shared.u64 t, %1; cvt.u32.u64 %0, t; }"
        : "=r"(a) : "l"(p));
    return a;
}

// ============================================================
// split3: fp32 [R,K] -> bf16 [R,3K]
//   mode 0 (activations): [hi | hi | lo]
//   mode 1 (weights):     [hi | lo | hi]
// ============================================================
__global__ void split3_kernel(const float* __restrict__ in,
                              __nv_bfloat16* __restrict__ out,
                              int log2K, size_t total, int mode)
{
    size_t i = ((size_t)blockIdx.x * blockDim.x + threadIdx.x) * 2;
    if (i >= total) return;
    const int K = 1 << log2K;
    size_t r = i >> log2K;
    int c = (int)(i & (size_t)(K - 1));
    float2 x = *(const float2*)(in + i);
    __nv_bfloat16 h0 = __float2bfloat16(x.x);
    __nv_bfloat16 h1 = __float2bfloat16(x.y);
    __nv_bfloat16 l0 = __float2bfloat16(x.x - __bfloat162float(h0));
    __nv_bfloat16 l1 = __float2bfloat16(x.y - __bfloat162float(h1));
    __nv_bfloat162 hv; hv.x = h0; hv.y = h1;
    __nv_bfloat162 lv; lv.x = l0; lv.y = l1;
    __nv_bfloat16* o = out + r * (size_t)(3 * K) + c;
    *(__nv_bfloat162*)(o) = hv;
    if (mode == 0) {
        *(__nv_bfloat162*)(o + K)     = hv;
        *(__nv_bfloat162*)(o + 2 * K) = lv;
    } else {
        *(__nv_bfloat162*)(o + K)     = lv;
        *(__nv_bfloat162*)(o + 2 * K) = hv;
    }
}

// ============================================================
// Tensor-core GEMM: C[M,N] = A[M,K] @ B[N,K]^T (+bias)
// 128x128 CTA tile, BK=32, 3-stage cp.async ring, 8 warps (32x64),
// ldmatrix + m16n8k16 bf16 mma, fp32 accum.
// Epilogues:
//   EPI==0: C fp32 (+bias)
//   EPI==1: C fp32 = (acc+bias) * mulsrc * mulscale   (fm hadamard fuse)
//   EPI==2: split-bf16 out, N=1024 reshaped to 8 heads x 384 cols [hi|hi|lo]
// ============================================================
#define ASTAGE 10240            // 128 rows x 80B
#define STAGEB 20480            // A + B per stage
#define GEMM_SMEM (3 * STAGEB)  // 61440

template<int EPI>
__global__ __launch_bounds__(256) void mma_gemm_kernel(
    const __nv_bfloat16* __restrict__ A,
    const __nv_bfloat16* __restrict__ B,
    const float* __restrict__ bias,
    float* __restrict__ Cf,
    const float* __restrict__ mulsrc, float mulscale,
    __nv_bfloat16* __restrict__ Cbf,
    int N, int K)
{
    extern __shared__ __align__(16) char dynsm[];
    const uint32_t sBase = smem_u32(dynsm);

    const int tid = threadIdx.x;
    const int lane = tid & 31;
    const int wid = tid >> 5;
    const int warp_m = (wid & 3) * 32;
    const int warp_n = (wid >> 2) * 64;
    const int bm0 = blockIdx.y * 128;
    const int bn0 = blockIdx.x * 128;
    const int NC = K >> 5;

    const size_t rowb = (size_t)K * 2;
    const char* Ag = (const char*)A + (size_t)bm0 * rowb;
    const char* Bg = (const char*)B + (size_t)bn0 * rowb;

    // loader coords: 2 segs per tile per thread (A and B each)
    const int r0 = tid >> 2, g0 = tid & 3;
    const int r1 = (tid + 256) >> 2, g1 = (tid + 256) & 3;

    auto load_stage = [&](int kc, int s) {
        const size_t koff = (size_t)kc * 64;
        const uint32_t ab = sBase + (uint32_t)(s * STAGEB);
        const uint32_t bb = ab + ASTAGE;
        uint32_t sa0 = ab + (uint32_t)(r0 * 80 + g0 * 16);
        uint32_t sa1 = ab + (uint32_t)(r1 * 80 + g1 * 16);
        uint32_t sb0 = bb + (uint32_t)(r0 * 80 + g0 * 16);
        uint32_t sb1 = bb + (uint32_t)(r1 * 80 + g1 * 16);
        const void* ga0 = Ag + (size_t)r0 * rowb + koff + g0 * 16;
        const void* ga1 = Ag + (size_t)r1 * rowb + koff + g1 * 16;
        const void* gb0 = Bg + (size_t)r0 * rowb + koff + g0 * 16;
        const void* gb1 = Bg + (size_t)r1 * rowb + koff + g1 * 16;
        asm volatile("cp.async.cg.shared.global [%0], [%1], 16;" :: "r"(sa0), "l"(ga0));
        asm volatile("cp.async.cg.shared.global [%0], [%1], 16;" :: "r"(sa1), "l"(ga1));
        asm volatile("cp.async.cg.shared.global [%0], [%1], 16;" :: "r"(sb0), "l"(gb0));
        asm volatile("cp.async.cg.shared.global [%0], [%1], 16;" :: "r"(sb1), "l"(gb1));
        asm volatile("cp.async.commit_group;");
    };

    float acc[2][8][4];
#pragma unroll
    for (int mt = 0; mt < 2; mt++)
#pragma unroll
        for (int nt = 0; nt < 8; nt++)
#pragma unroll
            for (int j = 0; j < 4; j++) acc[mt][nt][j] = 0.f;

    load_stage(0, 0);
    load_stage(1, 1);

    const int lm = lane & 15;
    const int lk = lane >> 4;
    const uint32_t aOff = (uint32_t)((warp_m + lm) * 80 + lk * 16);
    const uint32_t bOff = (uint32_t)(ASTAGE + (warp_n + lm) * 80 + lk * 16);

    for (int kc = 0; kc < NC; kc++) {
        const int s = kc % 3;
        if (kc + 1 < NC) asm volatile("cp.async.wait_group 1;");
        else             asm volatile("cp.async.wait_group 0;");
        __syncthreads();
        if (kc + 2 < NC) load_stage(kc + 2, (kc + 2) % 3);

        const uint32_t aSt = sBase + (uint32_t)(s * STAGEB) + aOff;
        const uint32_t bSt = sBase + (uint32_t)(s * STAGEB) + bOff;

        uint32_t a[2][2][4], bf[2][4][4];
#pragma unroll
        for (int ks = 0; ks < 2; ks++) {
#pragma unroll
            for (int mt = 0; mt < 2; mt++) {
                uint32_t ad = aSt + (uint32_t)(mt * 16 * 80 + ks * 32);
                asm volatile("ldmatrix.sync.aligned.m8n8.x4.shared.b16 {%0,%1,%2,%3}, [%4];"
                             : "=r"(a[ks][mt][0]), "=r"(a[ks][mt][1]),
                               "=r"(a[ks][mt][2]), "=r"(a[ks][mt][3])
                             : "r"(ad));
            }
#pragma unroll
            for (int ng = 0; ng < 4; ng++) {
                uint32_t bd = bSt + (uint32_t)(ng * 16 * 80 + ks * 32);
                asm volatile("ldmatrix.sync.aligned.m8n8.x4.shared.b16 {%0,%1,%2,%3}, [%4];"
                             : "=r"(bf[ks][ng][0]), "=r"(bf[ks][ng][1]),
                               "=r"(bf[ks][ng][2]), "=r"(bf[ks][ng][3])
                             : "r"(bd));
            }
        }
#pragma unroll
        for (int ks = 0; ks < 2; ks++)
#pragma unroll
            for (int mt = 0; mt < 2; mt++)
#pragma unroll
                for (int nt = 0; nt < 8; nt++) {
                    const int g = nt >> 1, sel = nt & 1;
                    asm volatile(
                        "mma.sync.aligned.m16n8k16.row.col.f32.bf16.bf16.f32 "
                        "{%0,%1,%2,%3}, {%4,%5,%6,%7}, {%8,%9}, {%0,%1,%2,%3};"
                        : "+f"(acc[mt][nt][0]), "+f"(acc[mt][nt][1]),
                          "+f"(acc[mt][nt][2]), "+f"(acc[mt][nt][3])
                        : "r"(a[ks][mt][0]), "r"(a[ks][mt][1]),
                          "r"(a[ks][mt][2]), "r"(a[ks][mt][3]),
                          "r"(bf[ks][g][sel]), "r"(bf[ks][g][sel + 2]));
                }
    }

    // ---- epilogue ----
    const int erow = bm0 + warp_m + (lane >> 2);
    const int ecol0 = bn0 + warp_n + (lane & 3) * 2;
#pragma unroll
    for (int nt = 0; nt < 8; nt++) {
        const int col = ecol0 + nt * 8;
        float bx = 0.f, by = 0.f;
        if (bias) { bx = bias[col]; by = bias[col + 1]; }
#pragma unroll
        for (int mt = 0; mt < 2; mt++) {
#pragma unroll
            for (int half = 0; half < 2; half++) {
                const int row = erow + mt * 16 + half * 8;
                float vx = acc[mt][nt][half * 2 + 0] + bx;
                float vy = acc[mt][nt][half * 2 + 1] + by;
                if (EPI == 0) {
                    *(float2*)(Cf + (size_t)row * N + col) = make_float2(vx, vy);
                } else if (EPI == 1) {
                    float2 m = *(const float2*)(mulsrc + (size_t)row * N + col);
                    *(float2*)(Cf + (size_t)row * N + col) =
                        make_float2(vx * m.x * mulscale, vy * m.y * mulscale);
                } else {
                    // split8: N=1024 -> rows of 8 heads x 384 cols [hi|hi|lo]
                    const int rr = row * 8 + (col >> 7);
                    const int cc = col & 127;
                    __nv_bfloat16 h0 = __float2bfloat16(vx);
                    __nv_bfloat16 h1 = __float2bfloat16(vy);
                    __nv_bfloat16 l0 = __float2bfloat16(vx - __bfloat162float(h0));
                    __nv_bfloat16 l1 = __float2bfloat16(vy - __bfloat162float(h1));
                    __nv_bfloat162 hv; hv.x = h0; hv.y = h1;
                    __nv_bfloat162 lv; lv.x = l0; lv.y = l1;
                    __nv_bfloat16* p = Cbf + (size_t)rr * 384 + cc;
                    *(__nv_bfloat162*)(p)       = hv;
                    *(__nv_bfloat162*)(p + 128) = hv;
                    *(__nv_bfloat162*)(p + 256) = lv;
                }
            }
        }
    }
}

// ============================================================
// Per-chunk kv = k_c^T @ v_c : [128,128] per (b,n,h)
// ============================================================
__global__ __launch_bounds__(256) void chunk_kv_kernel(
    const float* __restrict__ k, const float* __restrict__ v,
    float* __restrict__ kv)
{
    extern __shared__ float sm[];
    float* ks = sm;
    float* vs = sm + 64 * 128;

    const int bid = blockIdx.x;
    const int h = bid % HH;
    const int n = (bid / HH) % NCH;
    const int b = bid / (HH * NCH);
    const size_t base = (((size_t)b * TT + (size_t)n * CHUNK) * HH + h) * DKV;

    const int tid = threadIdx.x;
    for (int off = tid * 4; off < 64 * 128; off += 256 * 4) {
        int c = off >> 7, d = off & 127;
        *(float4*)&ks[off] = *(const float4*)&k[base + (size_t)c * (HH * DKV) + d];
        *(float4*)&vs[off] = *(const float4*)&v[base + (size_t)c * (HH * DKV) + d];
    }
    __syncthreads();

    const int tx = tid & 15, ty = tid >> 4;
    float acc[8][8];
#pragma unroll
    for (int i = 0; i < 8; i++)
#pragma unroll
        for (int j = 0; j < 8; j++) acc[i][j] = 0.f;

    for (int c = 0; c < 64; c++) {
        float a[8], bb[8];
        *(float4*)(a)      = *(const float4*)&ks[c * 128 + ty * 8];
        *(float4*)(a + 4)  = *(const float4*)&ks[c * 128 + ty * 8 + 4];
        *(float4*)(bb)     = *(const float4*)&vs[c * 128 + tx * 8];
        *(float4*)(bb + 4) = *(const float4*)&vs[c * 128 + tx * 8 + 4];
#pragma unroll
        for (int i = 0; i < 8; i++)
#pragma unroll
            for (int j = 0; j < 8; j++)
                acc[i][j] += a[i] * bb[j];
    }

    float* outp = kv + (size_t)bid * (DKV * DKV);
#pragma unroll
    for (int i = 0; i < 8; i++) {
        float* cp = outp + (ty * 8 + i) * 128 + tx * 8;
        *(float4*)(cp)     = make_float4(acc[i][0], acc[i][1], acc[i][2], acc[i][3]);
        *(float4*)(cp + 4) = make_float4(acc[i][4], acc[i][5], acc[i][6], acc[i][7]);
    }
}

// ============================================================
// Exclusive prefix over chunks (in-place)
// ============================================================
__global__ void scan_kv_kernel(float* __restrict__ kv)
{
    int gid = blockIdx.x * blockDim.x + threadIdx.x;
    int e = gid & 16383;
    int h = (gid >> 14) % HH;
    int b = gid / (16384 * HH);
    size_t idx = (((size_t)b * NCH) * HH + h) * 16384 + e;
    const size_t stride = (size_t)HH * 16384;
    float acc = 0.f;
#pragma unroll 4
    for (int n = 0; n < NCH; n++) {
        float x = kv[idx];
        kv[idx] = acc;
        acc += x;
        idx += stride;
    }
}

// ============================================================
// Per-chunk output: o = tril(q k^T) v + q @ S, fused RMSNorm,
// epilogue writes split-bf16 os rows [hi(1024)|hi|lo]
// ============================================================
__global__ __launch_bounds__(256) void chunk_out_kernel(
    const float* __restrict__ q, const float* __restrict__ k,
    const float* __restrict__ v, const float* __restrict__ kvS,
    const float* __restrict__ rms_w, __nv_bfloat16* __restrict__ os)
{
    extern __shared__ float sm[];
    float* qT = sm;
    float* kT = qT + 128 * 65;
    float* vs = kT + 128 * 65;
    float* Ss = vs + 64 * 128;
    float* AT = Ss + 128 * 128;
    float* rw = AT + 64 * 65;

    const int bid = blockIdx.x;
    const int h = bid % HH;
    const int n = (bid / HH) % NCH;
    const int b = bid / (HH * NCH);
    const size_t base = (((size_t)b * TT + (size_t)n * CHUNK) * HH + h) * DKV;

    const int tid = threadIdx.x;

    for (int off = tid; off < 64 * 128; off += 256) {
        int c = off >> 7, d = off & 127;
        qT[d * 65 + c] = q[base + (size_t)c * (HH * DKV) + d];
        kT[d * 65 + c] = k[base + (size_t)c * (HH * DKV) + d];
    }
    for (int off = tid * 4; off < 64 * 128; off += 256 * 4) {
        int c = off >> 7, d = off & 127;
        *(float4*)&vs[off] = *(const float4*)&v[base + (size_t)c * (HH * DKV) + d];
    }
    {
        const float* Sg = kvS + (size_t)bid * (DKV * DKV);
        for (int off = tid * 4; off < 128 * 128; off += 256 * 4)
            *(float4*)&Ss[off] = *(const float4*)&Sg[off];
    }
    if (tid < 128) rw[tid] = rms_w[tid];
    __syncthreads();

    const int tx = tid & 15, ty = tid >> 4;

    {
        float accA[4][4];
#pragma unroll
        for (int i = 0; i < 4; i++)
#pragma unroll
            for (int j = 0; j < 4; j++) accA[i][j] = 0.f;
        for (int d = 0; d < 128; d++) {
            float a[4], bb[4];
#pragma unroll
            for (int i = 0; i < 4; i++) a[i] = qT[d * 65 + ty * 4 + i];
#pragma unroll
            for (int j = 0; j < 4; j++) bb[j] = kT[d * 65 + tx * 4 + j];
#pragma unroll
            for (int i = 0; i < 4; i++)
#pragma unroll
                for (int j = 0; j < 4; j++)
                    accA[i][j] += a[i] * bb[j];
        }
#pragma unroll
        for (int i = 0; i < 4; i++) {
            int r = ty * 4 + i;
#pragma unroll
            for (int j = 0; j < 4; j++) {
                int c = tx * 4 + j;
                AT[c * 65 + r] = (c <= r) ? accA[i][j] : 0.f;
            }
        }
    }
    __syncthreads();

    float acc[4][8];
#pragma unroll
    for (int i = 0; i < 4; i++)
#pragma unroll
        for (int j = 0; j < 8; j++) acc[i][j] = 0.f;

    for (int kk = 0; kk < 128; kk++) {
        float a[4], bb[8];
#pragma unroll
        for (int i = 0; i < 4; i++) a[i] = qT[kk * 65 + ty * 4 + i];
        *(float4*)(bb)     = *(const float4*)&Ss[kk * 128 + tx * 8];
        *(float4*)(bb + 4) = *(const float4*)&Ss[kk * 128 + tx * 8 + 4];
#pragma unroll
        for (int i = 0; i < 4; i++)
#pragma unroll
            for (int j = 0; j < 8; j++)
                acc[i][j] += a[i] * bb[j];
    }
    for (int c = 0; c < 64; c++) {
        float a[4], bb[8];
#pragma unroll
        for (int i = 0; i < 4; i++) a[i] = AT[c * 65 + ty * 4 + i];
        *(float4*)(bb)     = *(const float4*)&vs[c * 128 + tx * 8];
        *(float4*)(bb + 4) = *(const float4*)&vs[c * 128 + tx * 8 + 4];
#pragma unroll
        for (int i = 0; i < 4; i++)
#pragma unroll
            for (int j = 0; j < 8; j++)
                acc[i][j] += a[i] * bb[j];
    }

#pragma unroll
    for (int i = 0; i < 4; i++) {
        float s = 0.f;
#pragma unroll
        for (int j = 0; j < 8; j++) s += acc[i][j] * acc[i][j];
        s += __shfl_xor_sync(0xffffffffu, s, 1);
        s += __shfl_xor_sync(0xffffffffu, s, 2);
        s += __shfl_xor_sync(0xffffffffu, s, 4);
        s += __shfl_xor_sync(0xffffffffu, s, 8);
        float scale = rsqrtf(s * (1.0f / 128.0f) + EPS);
#pragma unroll
        for (int j = 0; j < 8; j++)
            acc[i][j] *= scale * rw[tx * 8 + j];
    }

    // write split bf16: row R (of 16384), cols h*128 + tx*8 + j in each 1024 block
#pragma unroll
    for (int i = 0; i < 4; i++) {
        int r = ty * 4 + i;
        size_t R = (size_t)b * TT + (size_t)n * CHUNK + r;
        __nv_bfloat16* p = os + R * 3072 + h * 128 + tx * 8;
#pragma unroll
        for (int j = 0; j < 8; j += 2) {
            float vx = acc[i][j], vy = acc[i][j + 1];
            __nv_bfloat16 h0 = __float2bfloat16(vx);
            __nv_bfloat16 h1 = __float2bfloat16(vy);
            __nv_bfloat16 l0 = __float2bfloat16(vx - __bfloat162float(h0));
            __nv_bfloat16 l1 = __float2bfloat16(vy - __bfloat162float(h1));
            __nv_bfloat162 hv; hv.x = h0; hv.y = h1;
            __nv_bfloat162 lv; lv.x = l0; lv.y = l1;
            *(__nv_bfloat162*)(p + j)        = hv;
            *(__nv_bfloat162*)(p + 1024 + j) = hv;
            *(__nv_bfloat162*)(p + 2048 + j) = lv;
        }
    }
}

// ============================================================
// Launch
// ============================================================
extern "C" void kernel_launch(void* const* d_in, const int* in_sizes, int n_in,
                              void* d_out, int out_size)
{
    const float* x      = (const float*)d_in[0];
    const float* Wq     = (const float*)d_in[1];
    const float* Wk     = (const float*)d_in[2];
    const float* Wv     = (const float*)d_in[3];
    const float* fmq_w1 = (const float*)d_in[4];
    const float* fmq_b1 = (const float*)d_in[5];
    const float* fmq_w2 = (const float*)d_in[6];
    const float* fmq_b2 = (const float*)d_in[7];
    const float* fmk_w1 = (const float*)d_in[8];
    const float* fmk_b1 = (const float*)d_in[9];
    const float* fmk_w2 = (const float*)d_in[10];
    const float* fmk_b2 = (const float*)d_in[11];
    const float* rms_w  = (const float*)d_in[12];
    const float* Wo     = (const float*)d_in[13];
    float* out = (float*)d_out;

    float *bQ, *bK, *bV, *tA, *bKV;
    cudaGetSymbolAddress((void**)&bQ, g_bufQ);
    cudaGetSymbolAddress((void**)&bK, g_bufK);
    cudaGetSymbolAddress((void**)&bV, g_bufV);
    cudaGetSymbolAddress((void**)&tA, g_tmpA);
    cudaGetSymbolAddress((void**)&bKV, g_kv);

    __nv_bfloat16 *xs, *ws, *fmw, *q1s, *k1s, *os;
    cudaGetSymbolAddress((void**)&xs,  g_xs);
    cudaGetSymbolAddress((void**)&ws,  g_ws);
    cudaGetSymbolAddress((void**)&fmw, g_fmw);
    cudaGetSymbolAddress((void**)&q1s, g_q1s);
    cudaGetSymbolAddress((void**)&k1s, g_k1s);
    cudaGetSymbolAddress((void**)&os,  g_os);

    const int smem_kv  = 2 * 64 * 128 * 4;
    const int smem_out = (2 * 128 * 65 + 64 * 128 + 128 * 128 + 64 * 65 + 128) * 4;
    cudaFuncSetAttribute(chunk_kv_kernel,  cudaFuncAttributeMaxDynamicSharedMemorySize, smem_kv);
    cudaFuncSetAttribute(chunk_out_kernel, cudaFuncAttributeMaxDynamicSharedMemorySize, smem_out);
    cudaFuncSetAttribute(mma_gemm_kernel<0>, cudaFuncAttributeMaxDynamicSharedMemorySize, GEMM_SMEM);
    cudaFuncSetAttribute(mma_gemm_kernel<1>, cudaFuncAttributeMaxDynamicSharedMemorySize, GEMM_SMEM);
    cudaFuncSetAttribute(mma_gemm_kernel<2>, cudaFuncAttributeMaxDynamicSharedMemorySize, GEMM_SMEM);

    const size_t wsz = (size_t)HID * K3BIG;
    const size_t fsz = (size_t)DKV * K3FM;

    // ---- splits (x + weights only) ----
    split3_kernel<<<(MROWS * HID) / 512, 256>>>(x, xs, 10, (size_t)MROWS * HID, 0);
    split3_kernel<<<(HID * HID) / 512, 256>>>(Wq, ws + 0 * wsz, 10, (size_t)HID * HID, 1);
    split3_kernel<<<(HID * HID) / 512, 256>>>(Wk, ws + 1 * wsz, 10, (size_t)HID * HID, 1);
    split3_kernel<<<(HID * HID) / 512, 256>>>(Wv, ws + 2 * wsz, 10, (size_t)HID * HID, 1);
    split3_kernel<<<(HID * HID) / 512, 256>>>(Wo, ws + 3 * wsz, 10, (size_t)HID * HID, 1);
    split3_kernel<<<(DKV * DKV) / 512, 256>>>(fmq_w1, fmw + 0 * fsz, 7, (size_t)DKV * DKV, 1);
    split3_kernel<<<(DKV * DKV) / 512, 256>>>(fmq_w2, fmw + 1 * fsz, 7, (size_t)DKV * DKV, 1);
    split3_kernel<<<(DKV * DKV) / 512, 256>>>(fmk_w1, fmw + 2 * fsz, 7, (size_t)DKV * DKV, 1);
    split3_kernel<<<(DKV * DKV) / 512, 256>>>(fmk_w2, fmw + 3 * fsz, 7, (size_t)DKV * DKV, 1);

    // ---- projections: Q/K write split-bf16 fm input directly, V fp32 ----
    dim3 gBig(HID / 128, MROWS / 128);   // (8, 128)
    mma_gemm_kernel<2><<<gBig, 256, GEMM_SMEM>>>(xs, ws + 0 * wsz, nullptr, nullptr, nullptr, 0.f, q1s, HID, K3BIG);
    mma_gemm_kernel<2><<<gBig, 256, GEMM_SMEM>>>(xs, ws + 1 * wsz, nullptr, nullptr, nullptr, 0.f, k1s, HID, K3BIG);
    mma_gemm_kernel<0><<<gBig, 256, GEMM_SMEM>>>(xs, ws + 2 * wsz, nullptr, bV, nullptr, 0.f, nullptr, HID, K3BIG);

    // ---- feature maps: branch1 fp32, branch2 fused hadamard ----
    dim3 gFm(1, FMROWS / 128);           // (1, 1024)
    const float scale = 0.08838834764831845f; // 128^-0.5
    mma_gemm_kernel<0><<<gFm, 256, GEMM_SMEM>>>(q1s, fmw + 0 * fsz, fmq_b1, tA, nullptr, 0.f, nullptr, DKV, K3FM);
    mma_gemm_kernel<1><<<gFm, 256, GEMM_SMEM>>>(q1s, fmw + 1 * fsz, fmq_b2, bQ, tA, scale, nullptr, DKV, K3FM);
    mma_gemm_kernel<0><<<gFm, 256, GEMM_SMEM>>>(k1s, fmw + 2 * fsz, fmk_b1, tA, nullptr, 0.f, nullptr, DKV, K3FM);
    mma_gemm_kernel<1><<<gFm, 256, GEMM_SMEM>>>(k1s, fmw + 3 * fsz, fmk_b2, bK, tA, 1.0f, nullptr, DKV, K3FM);

    // ---- chunked linear attention (fp32, split-bf16 epilogue) ----
    const int nBlk = BB * NCH * HH;
    chunk_kv_kernel<<<nBlk, 256, smem_kv>>>(bK, bV, bKV);
    scan_kv_kernel<<<(BB * HH * 16384) / 256, 256>>>(bKV);
    chunk_out_kernel<<<nBlk, 256, smem_out>>>(bQ, bK, bV, bKV, rms_w, os);

    // ---- output projection ----
    mma_gemm_kernel<0><<<gBig, 256, GEMM_SMEM>>>(os, ws + 3 * wsz, nullptr, out, nullptr, 0.f, nullptr, HID, K3BIG);
}

// round 10
// speedup vs baseline: 1.7853x; 1.0214x over previous
#include <cuda_runtime.h>
#include <cuda_bf16.h>
#include <cstddef>
#include <cstdint>

// Problem constants
#define BB 2
#define TT 8192
#define HH 8
#define DKV 128
#define HID 1024
#define CHUNK 64
#define NCH 128           // TT / CHUNK
#define MROWS (BB*TT)     // 16384
#define FMROWS (BB*TT*HH) // 131072
#define EPS 1e-5f
#define K3BIG (3*HID)     // 3072
#define K3FM  (3*DKV)     // 384

// -------- fp32 scratch --------
__device__ float g_bufQ[MROWS * HID];   // q after feature map
__device__ float g_bufK[MROWS * HID];   // k after feature map
__device__ float g_bufV[MROWS * HID];   // v projection
__device__ float g_kv[(size_t)BB * NCH * HH * DKV * DKV];

// -------- bf16 split scratch --------
__device__ __nv_bfloat16 g_xs [(size_t)MROWS * K3BIG];       // x split (act mode)
__device__ __nv_bfloat16 g_ws [(size_t)4 * HID * K3BIG];     // Wq,Wk,Wv,Wo (hi|lo|hi)
__device__ __nv_bfloat16 g_q1s[(size_t)FMROWS * K3FM];       // q proj split (hi|hi|lo)
__device__ __nv_bfloat16 g_k1s[(size_t)FMROWS * K3FM];
__device__ __nv_bfloat16 g_os [(size_t)MROWS * K3BIG];       // attention out split
__device__ __nv_bfloat16 g_fmwI[2][256 * K3FM];              // interleaved fm weights
__device__ float g_fmbI[2][256];                             // interleaved fm biases

__device__ __forceinline__ uint32_t smem_u32(const void* p) {
    uint32_t a;
    asm("{ .reg .u64 t; cvta.to.shared.u64 t, %1; cvt.u32.u64 %0, t; }"
        : "=r"(a) : "l"(p));
    return a;
}

// ============================================================
// split3: fp32 [R,K] -> bf16 [R,3K]
//   mode 0 (activations): [hi | hi | lo]
//   mode 1 (weights):     [hi | lo | hi]
// ============================================================
__global__ void split3_kernel(const float* __restrict__ in,
                              __nv_bfloat16* __restrict__ out,
                              int log2K, size_t total, int mode)
{
    size_t i = ((size_t)blockIdx.x * blockDim.x + threadIdx.x) * 2;
    if (i >= total) return;
    const int K = 1 << log2K;
    size_t r = i >> log2K;
    int c = (int)(i & (size_t)(K - 1));
    float2 x = *(const float2*)(in + i);
    __nv_bfloat16 h0 = __float2bfloat16(x.x);
    __nv_bfloat16 h1 = __float2bfloat16(x.y);
    __nv_bfloat16 l0 = __float2bfloat16(x.x - __bfloat162float(h0));
    __nv_bfloat16 l1 = __float2bfloat16(x.y - __bfloat162float(h1));
    __nv_bfloat162 hv; hv.x = h0; hv.y = h1;
    __nv_bfloat162 lv; lv.x = l0; lv.y = l1;
    __nv_bfloat16* o = out + r * (size_t)(3 * K) + c;
    *(__nv_bfloat162*)(o) = hv;
    if (mode == 0) {
        *(__nv_bfloat162*)(o + K)     = hv;
        *(__nv_bfloat162*)(o + 2 * K) = lv;
    } else {
        *(__nv_bfloat162*)(o + K)     = lv;
        *(__nv_bfloat162*)(o + 2 * K) = hv;
    }
}

// ============================================================
// fm weight interleave: rows alternate w1/w2, each split [hi|lo|hi]
// ============================================================
__global__ void fm_interleave_kernel(const float* __restrict__ w1,
                                     const float* __restrict__ w2,
                                     const float* __restrict__ b1,
                                     const float* __restrict__ b2,
                                     __nv_bfloat16* __restrict__ outW,
                                     float* __restrict__ outB)
{
    int idx = blockIdx.x * 256 + threadIdx.x;   // 0..32767
    int rp = idx >> 7;                          // 0..255
    int c  = idx & 127;
    const float* w = (rp & 1) ? w2 : w1;
    int sr = rp >> 1;
    float v = w[sr * 128 + c];
    __nv_bfloat16 h = __float2bfloat16(v);
    __nv_bfloat16 l = __float2bfloat16(v - __bfloat162float(h));
    __nv_bfloat16* o = outW + (size_t)rp * K3FM + c;
    o[0] = h; o[128] = l; o[256] = h;
    if (c == 0) outB[rp] = ((rp & 1) ? b2 : b1)[sr];
}

// ============================================================
// Tensor-core GEMM: C[M,N] = A[M,K] @ B[N,K]^T (+bias)
// 128x128 CTA tile, BK=32, 4-stage cp.async ring, 8 warps (32x64),
// ldmatrix + m16n8k16 bf16 mma, fp32 accum. 2 CTAs/SM target.
// Epilogues:
//   EPI==0: C fp32 (+bias)
//   EPI==2: split-bf16, N=1024 reshaped to 8 heads x 384 [hi|hi|lo]
//   EPI==3: fm fused: even/odd col pairs multiplied -> fp32 [.,128]
// ============================================================
#define ASTAGE 10240            // 128 rows x 80B
#define STAGEB 20480            // A + B per stage
#define NSTG 4
#define GEMM_SMEM (NSTG * STAGEB)  // 81920

template<int EPI>
__global__ __launch_bounds__(256, 2) void mma_gemm_kernel(
    const __nv_bfloat16* __restrict__ A,
    const __nv_bfloat16* __restrict__ B,
    const float* __restrict__ bias,
    float* __restrict__ Cf,
    __nv_bfloat16* __restrict__ Cbf,
    float mulscale,
    int N, int K)
{
    extern __shared__ __align__(16) char dynsm[];
    const uint32_t sBase = smem_u32(dynsm);

    const int tid = threadIdx.x;
    const int lane = tid & 31;
    const int wid = tid >> 5;
    const int warp_m = (wid & 3) * 32;
    const int warp_n = (wid >> 2) * 64;
    const int bm0 = blockIdx.y * 128;
    const int bn0 = blockIdx.x * 128;
    const int NC = K >> 5;

    const size_t rowb = (size_t)K * 2;
    const char* Ag = (const char*)A + (size_t)bm0 * rowb;
    const char* Bg = (const char*)B + (size_t)bn0 * rowb;

    const int r0 = tid >> 2, g0 = tid & 3;
    const int r1 = (tid + 256) >> 2, g1 = (tid + 256) & 3;

    auto load_stage = [&](int kc, int s) {
        const size_t koff = (size_t)kc * 64;
        const uint32_t ab = sBase + (uint32_t)(s * STAGEB);
        const uint32_t bb = ab + ASTAGE;
        uint32_t sa0 = ab + (uint32_t)(r0 * 80 + g0 * 16);
        uint32_t sa1 = ab + (uint32_t)(r1 * 80 + g1 * 16);
        uint32_t sb0 = bb + (uint32_t)(r0 * 80 + g0 * 16);
        uint32_t sb1 = bb + (uint32_t)(r1 * 80 + g1 * 16);
        const void* ga0 = Ag + (size_t)r0 * rowb + koff + g0 * 16;
        const void* ga1 = Ag + (size_t)r1 * rowb + koff + g1 * 16;
        const void* gb0 = Bg + (size_t)r0 * rowb + koff + g0 * 16;
        const void* gb1 = Bg + (size_t)r1 * rowb + koff + g1 * 16;
        asm volatile("cp.async.cg.shared.global [%0], [%1], 16;" :: "r"(sa0), "l"(ga0));
        asm volatile("cp.async.cg.shared.global [%0], [%1], 16;" :: "r"(sa1), "l"(ga1));
        asm volatile("cp.async.cg.shared.global [%0], [%1], 16;" :: "r"(sb0), "l"(gb0));
        asm volatile("cp.async.cg.shared.global [%0], [%1], 16;" :: "r"(sb1), "l"(gb1));
        asm volatile("cp.async.commit_group;");
    };

    float acc[2][8][4];
#pragma unroll
    for (int mt = 0; mt < 2; mt++)
#pragma unroll
        for (int nt = 0; nt < 8; nt++)
#pragma unroll
            for (int j = 0; j < 4; j++) acc[mt][nt][j] = 0.f;

    load_stage(0, 0);
    load_stage(1, 1);
    load_stage(2, 2);

    const int lm = lane & 15;
    const int lk = lane >> 4;
    const uint32_t aOff = (uint32_t)((warp_m + lm) * 80 + lk * 16);
    const uint32_t bOff = (uint32_t)(ASTAGE + (warp_n + lm) * 80 + lk * 16);

    for (int kc = 0; kc < NC; kc++) {
        const int s = kc & (NSTG - 1);
        if (kc + 3 <= NC)      asm volatile("cp.async.wait_group 2;");
        else if (kc + 2 == NC) asm volatile("cp.async.wait_group 1;");
        else                   asm volatile("cp.async.wait_group 0;");
        __syncthreads();
        if (kc + 3 < NC) load_stage(kc + 3, (kc + 3) & (NSTG - 1));

        const uint32_t aSt = sBase + (uint32_t)(s * STAGEB) + aOff;
        const uint32_t bSt = sBase + (uint32_t)(s * STAGEB) + bOff;

#pragma unroll
        for (int ks = 0; ks < 2; ks++) {
            uint32_t a[2][4], bf[4][4];
#pragma unroll
            for (int mt = 0; mt < 2; mt++) {
                uint32_t ad = aSt + (uint32_t)(mt * 16 * 80 + ks * 32);
                asm volatile("ldmatrix.sync.aligned.m8n8.x4.shared.b16 {%0,%1,%2,%3}, [%4];"
                             : "=r"(a[mt][0]), "=r"(a[mt][1]), "=r"(a[mt][2]), "=r"(a[mt][3])
                             : "r"(ad));
            }
#pragma unroll
            for (int ng = 0; ng < 4; ng++) {
                uint32_t bd = bSt + (uint32_t)(ng * 16 * 80 + ks * 32);
                asm volatile("ldmatrix.sync.aligned.m8n8.x4.shared.b16 {%0,%1,%2,%3}, [%4];"
                             : "=r"(bf[ng][0]), "=r"(bf[ng][1]), "=r"(bf[ng][2]), "=r"(bf[ng][3])
                             : "r"(bd));
            }
#pragma unroll
            for (int mt = 0; mt < 2; mt++)
#pragma unroll
                for (int nt = 0; nt < 8; nt++) {
                    const int g = nt >> 1, sel = nt & 1;
                    asm volatile(
                        "mma.sync.aligned.m16n8k16.row.col.f32.bf16.bf16.f32 "
                        "{%0,%1,%2,%3}, {%4,%5,%6,%7}, {%8,%9}, {%0,%1,%2,%3};"
                        : "+f"(acc[mt][nt][0]), "+f"(acc[mt][nt][1]),
                          "+f"(acc[mt][nt][2]), "+f"(acc[mt][nt][3])
                        : "r"(a[mt][0]), "r"(a[mt][1]), "r"(a[mt][2]), "r"(a[mt][3]),
                          "r"(bf[g][sel]), "r"(bf[g][sel + 2]));
                }
        }
    }

    // ---- epilogue ----
    const int erow = bm0 + warp_m + (lane >> 2);
    const int ecol0 = bn0 + warp_n + (lane & 3) * 2;
#pragma unroll
    for (int nt = 0; nt < 8; nt++) {
        const int col = ecol0 + nt * 8;
        float bx = 0.f, by = 0.f;
        if (bias) { bx = bias[col]; by = bias[col + 1]; }
#pragma unroll
        for (int mt = 0; mt < 2; mt++) {
#pragma unroll
            for (int half = 0; half < 2; half++) {
                const int row = erow + mt * 16 + half * 8;
                float vx = acc[mt][nt][half * 2 + 0] + bx;
                float vy = acc[mt][nt][half * 2 + 1] + by;
                if (EPI == 0) {
                    *(float2*)(Cf + (size_t)row * N + col) = make_float2(vx, vy);
                } else if (EPI == 3) {
                    // even/odd cols are (branch1, branch2) of output col j
                    Cf[(size_t)row * 128 + (col >> 1)] = vx * vy * mulscale;
                } else {
                    const int rr = row * 8 + (col >> 7);
                    const int cc = col & 127;
                    __nv_bfloat16 h0 = __float2bfloat16(vx);
                    __nv_bfloat16 h1 = __float2bfloat16(vy);
                    __nv_bfloat16 l0 = __float2bfloat16(vx - __bfloat162float(h0));
                    __nv_bfloat16 l1 = __float2bfloat16(vy - __bfloat162float(h1));
                    __nv_bfloat162 hv; hv.x = h0; hv.y = h1;
                    __nv_bfloat162 lv; lv.x = l0; lv.y = l1;
                    __nv_bfloat16* p = Cbf + (size_t)rr * 384 + cc;
                    *(__nv_bfloat162*)(p)       = hv;
                    *(__nv_bfloat162*)(p + 128) = hv;
                    *(__nv_bfloat162*)(p + 256) = lv;
                }
            }
        }
    }
}

// ============================================================
// Per-chunk kv = k_c^T @ v_c : [128,128] per (b,n,h)
// ============================================================
__global__ __launch_bounds__(256) void chunk_kv_kernel(
    const float* __restrict__ k, const float* __restrict__ v,
    float* __restrict__ kv)
{
    extern __shared__ float sm[];
    float* ks = sm;
    float* vs = sm + 64 * 128;

    const int bid = blockIdx.x;
    const int h = bid % HH;
    const int n = (bid / HH) % NCH;
    const int b = bid / (HH * NCH);
    const size_t base = (((size_t)b * TT + (size_t)n * CHUNK) * HH + h) * DKV;

    const int tid = threadIdx.x;
    for (int off = tid * 4; off < 64 * 128; off += 256 * 4) {
        int c = off >> 7, d = off & 127;
        *(float4*)&ks[off] = *(const float4*)&k[base + (size_t)c * (HH * DKV) + d];
        *(float4*)&vs[off] = *(const float4*)&v[base + (size_t)c * (HH * DKV) + d];
    }
    __syncthreads();

    const int tx = tid & 15, ty = tid >> 4;
    float acc[8][8];
#pragma unroll
    for (int i = 0; i < 8; i++)
#pragma unroll
        for (int j = 0; j < 8; j++) acc[i][j] = 0.f;

    for (int c = 0; c < 64; c++) {
        float a[8], bb[8];
        *(float4*)(a)      = *(const float4*)&ks[c * 128 + ty * 8];
        *(float4*)(a + 4)  = *(const float4*)&ks[c * 128 + ty * 8 + 4];
        *(float4*)(bb)     = *(const float4*)&vs[c * 128 + tx * 8];
        *(float4*)(bb + 4) = *(const float4*)&vs[c * 128 + tx * 8 + 4];
#pragma unroll
        for (int i = 0; i < 8; i++)
#pragma unroll
            for (int j = 0; j < 8; j++)
                acc[i][j] += a[i] * bb[j];
    }

    float* outp = kv + (size_t)bid * (DKV * DKV);
#pragma unroll
    for (int i = 0; i < 8; i++) {
        float* cp = outp + (ty * 8 + i) * 128 + tx * 8;
        *(float4*)(cp)     = make_float4(acc[i][0], acc[i][1], acc[i][2], acc[i][3]);
        *(float4*)(cp + 4) = make_float4(acc[i][4], acc[i][5], acc[i][6], acc[i][7]);
    }
}

// ============================================================
// Exclusive prefix over chunks (in-place)
// ============================================================
__global__ void scan_kv_kernel(float* __restrict__ kv)
{
    int gid = blockIdx.x * blockDim.x + threadIdx.x;
    int e = gid & 16383;
    int h = (gid >> 14) % HH;
    int b = gid / (16384 * HH);
    size_t idx = (((size_t)b * NCH) * HH + h) * 16384 + e;
    const size_t stride = (size_t)HH * 16384;
    float acc = 0.f;
#pragma unroll 4
    for (int n = 0; n < NCH; n++) {
        float x = kv[idx];
        kv[idx] = acc;
        acc += x;
        idx += stride;
    }
}

// ============================================================
// Per-chunk output: o = tril(q k^T) v + q @ S, fused RMSNorm,
// epilogue writes split-bf16 os rows [hi(1024)|hi|lo]
// ============================================================
__global__ __launch_bounds__(256) void chunk_out_kernel(
    const float* __restrict__ q, const float* __restrict__ k,
    const float* __restrict__ v, const float* __restrict__ kvS,
    const float* __restrict__ rms_w, __nv_bfloat16* __restrict__ os)
{
    extern __shared__ float sm[];
    float* qT = sm;
    float* kT = qT + 128 * 65;
    float* vs = kT + 128 * 65;
    float* Ss = vs + 64 * 128;
    float* AT = Ss + 128 * 128;
    float* rw = AT + 64 * 65;

    const int bid = blockIdx.x;
    const int h = bid % HH;
    const int n = (bid / HH) % NCH;
    const int b = bid / (HH * NCH);
    const size_t base = (((size_t)b * TT + (size_t)n * CHUNK) * HH + h) * DKV;

    const int tid = threadIdx.x;

    for (int off = tid; off < 64 * 128; off += 256) {
        int c = off >> 7, d = off & 127;
        qT[d * 65 + c] = q[base + (size_t)c * (HH * DKV) + d];
        kT[d * 65 + c] = k[base + (size_t)c * (HH * DKV) + d];
    }
    for (int off = tid * 4; off < 64 * 128; off += 256 * 4) {
        int c = off >> 7, d = off & 127;
        *(float4*)&vs[off] = *(const float4*)&v[base + (size_t)c * (HH * DKV) + d];
    }
    {
        const float* Sg = kvS + (size_t)bid * (DKV * DKV);
        for (int off = tid * 4; off < 128 * 128; off += 256 * 4)
            *(float4*)&Ss[off] = *(const float4*)&Sg[off];
    }
    if (tid < 128) rw[tid] = rms_w[tid];
    __syncthreads();

    const int tx = tid & 15, ty = tid >> 4;

    {
        float accA[4][4];
#pragma unroll
        for (int i = 0; i < 4; i++)
#pragma unroll
            for (int j = 0; j < 4; j++) accA[i][j] = 0.f;
        for (int d = 0; d < 128; d++) {
            float a[4], bb[4];
#pragma unroll
            for (int i = 0; i < 4; i++) a[i] = qT[d * 65 + ty * 4 + i];
#pragma unroll
            for (int j = 0; j < 4; j++) bb[j] = kT[d * 65 + tx * 4 + j];
#pragma unroll
            for (int i = 0; i < 4; i++)
#pragma unroll
                for (int j = 0; j < 4; j++)
                    accA[i][j] += a[i] * bb[j];
        }
#pragma unroll
        for (int i = 0; i < 4; i++) {
            int r = ty * 4 + i;
#pragma unroll
            for (int j = 0; j < 4; j++) {
                int c = tx * 4 + j;
                AT[c * 65 + r] = (c <= r) ? accA[i][j] : 0.f;
            }
        }
    }
    __syncthreads();

    float acc[4][8];
#pragma unroll
    for (int i = 0; i < 4; i++)
#pragma unroll
        for (int j = 0; j < 8; j++) acc[i][j] = 0.f;

    for (int kk = 0; kk < 128; kk++) {
        float a[4], bb[8];
#pragma unroll
        for (int i = 0; i < 4; i++) a[i] = qT[kk * 65 + ty * 4 + i];
        *(float4*)(bb)     = *(const float4*)&Ss[kk * 128 + tx * 8];
        *(float4*)(bb + 4) = *(const float4*)&Ss[kk * 128 + tx * 8 + 4];
#pragma unroll
        for (int i = 0; i < 4; i++)
#pragma unroll
            for (int j = 0; j < 8; j++)
                acc[i][j] += a[i] * bb[j];
    }
    for (int c = 0; c < 64; c++) {
        float a[4], bb[8];
#pragma unroll
        for (int i = 0; i < 4; i++) a[i] = AT[c * 65 + ty * 4 + i];
        *(float4*)(bb)     = *(const float4*)&vs[c * 128 + tx * 8];
        *(float4*)(bb + 4) = *(const float4*)&vs[c * 128 + tx * 8 + 4];
#pragma unroll
        for (int i = 0; i < 4; i++)
#pragma unroll
            for (int j = 0; j < 8; j++)
                acc[i][j] += a[i] * bb[j];
    }

#pragma unroll
    for (int i = 0; i < 4; i++) {
        float s = 0.f;
#pragma unroll
        for (int j = 0; j < 8; j++) s += acc[i][j] * acc[i][j];
        s += __shfl_xor_sync(0xffffffffu, s, 1);
        s += __shfl_xor_sync(0xffffffffu, s, 2);
        s += __shfl_xor_sync(0xffffffffu, s, 4);
        s += __shfl_xor_sync(0xffffffffu, s, 8);
        float scale = rsqrtf(s * (1.0f / 128.0f) + EPS);
#pragma unroll
        for (int j = 0; j < 8; j++)
            acc[i][j] *= scale * rw[tx * 8 + j];
    }

#pragma unroll
    for (int i = 0; i < 4; i++) {
        int r = ty * 4 + i;
        size_t R = (size_t)b * TT + (size_t)n * CHUNK + r;
        __nv_bfloat16* p = os + R * 3072 + h * 128 + tx * 8;
#pragma unroll
        for (int j = 0; j < 8; j += 2) {
            float vx = acc[i][j], vy = acc[i][j + 1];
            __nv_bfloat16 h0 = __float2bfloat16(vx);
            __nv_bfloat16 h1 = __float2bfloat16(vy);
            __nv_bfloat16 l0 = __float2bfloat16(vx - __bfloat162float(h0));
            __nv_bfloat16 l1 = __float2bfloat16(vy - __bfloat162float(h1));
            __nv_bfloat162 hv; hv.x = h0; hv.y = h1;
            __nv_bfloat162 lv; lv.x = l0; lv.y = l1;
            *(__nv_bfloat162*)(p + j)        = hv;
            *(__nv_bfloat162*)(p + 1024 + j) = hv;
            *(__nv_bfloat162*)(p + 2048 + j) = lv;
        }
    }
}

// ============================================================
// Launch
// ============================================================
extern "C" void kernel_launch(void* const* d_in, const int* in_sizes, int n_in,
                              void* d_out, int out_size)
{
    const float* x      = (const float*)d_in[0];
    const float* Wq     = (const float*)d_in[1];
    const float* Wk     = (const float*)d_in[2];
    const float* Wv     = (const float*)d_in[3];
    const float* fmq_w1 = (const float*)d_in[4];
    const float* fmq_b1 = (const float*)d_in[5];
    const float* fmq_w2 = (const float*)d_in[6];
    const float* fmq_b2 = (const float*)d_in[7];
    const float* fmk_w1 = (const float*)d_in[8];
    const float* fmk_b1 = (const float*)d_in[9];
    const float* fmk_w2 = (const float*)d_in[10];
    const float* fmk_b2 = (const float*)d_in[11];
    const float* rms_w  = (const float*)d_in[12];
    const float* Wo     = (const float*)d_in[13];
    float* out = (float*)d_out;

    float *bQ, *bK, *bV, *bKV;
    cudaGetSymbolAddress((void**)&bQ, g_bufQ);
    cudaGetSymbolAddress((void**)&bK, g_bufK);
    cudaGetSymbolAddress((void**)&bV, g_bufV);
    cudaGetSymbolAddress((void**)&bKV, g_kv);

    __nv_bfloat16 *xs, *ws, *q1s, *k1s, *os, *fmwI;
    float* fmbI;
    cudaGetSymbolAddress((void**)&xs,  g_xs);
    cudaGetSymbolAddress((void**)&ws,  g_ws);
    cudaGetSymbolAddress((void**)&q1s, g_q1s);
    cudaGetSymbolAddress((void**)&k1s, g_k1s);
    cudaGetSymbolAddress((void**)&os,  g_os);
    cudaGetSymbolAddress((void**)&fmwI, g_fmwI);
    cudaGetSymbolAddress((void**)&fmbI, g_fmbI);

    const int smem_kv  = 2 * 64 * 128 * 4;
    const int smem_out = (2 * 128 * 65 + 64 * 128 + 128 * 128 + 64 * 65 + 128) * 4;
    cudaFuncSetAttribute(chunk_kv_kernel,  cudaFuncAttributeMaxDynamicSharedMemorySize, smem_kv);
    cudaFuncSetAttribute(chunk_out_kernel, cudaFuncAttributeMaxDynamicSharedMemorySize, smem_out);
    cudaFuncSetAttribute(mma_gemm_kernel<0>, cudaFuncAttributeMaxDynamicSharedMemorySize, GEMM_SMEM);
    cudaFuncSetAttribute(mma_gemm_kernel<2>, cudaFuncAttributeMaxDynamicSharedMemorySize, GEMM_SMEM);
    cudaFuncSetAttribute(mma_gemm_kernel<3>, cudaFuncAttributeMaxDynamicSharedMemorySize, GEMM_SMEM);

    const size_t wsz = (size_t)HID * K3BIG;

    // ---- splits: launch idx 0..4 (so idx 5 = big GEMM for ncu -s 5) ----
    split3_kernel<<<(MROWS * HID) / 512, 256>>>(x, xs, 10, (size_t)MROWS * HID, 0);
    split3_kernel<<<(HID * HID) / 512, 256>>>(Wq, ws + 0 * wsz, 10, (size_t)HID * HID, 1);
    split3_kernel<<<(HID * HID) / 512, 256>>>(Wk, ws + 1 * wsz, 10, (size_t)HID * HID, 1);
    split3_kernel<<<(HID * HID) / 512, 256>>>(Wv, ws + 2 * wsz, 10, (size_t)HID * HID, 1);
    split3_kernel<<<(HID * HID) / 512, 256>>>(Wo, ws + 3 * wsz, 10, (size_t)HID * HID, 1);

    // ---- projections (launch idx 5,6,7) ----
    dim3 gBig(HID / 128, MROWS / 128);   // (8, 128)
    mma_gemm_kernel<2><<<gBig, 256, GEMM_SMEM>>>(xs, ws + 0 * wsz, nullptr, nullptr, q1s, 0.f, HID, K3BIG);
    mma_gemm_kernel<2><<<gBig, 256, GEMM_SMEM>>>(xs, ws + 1 * wsz, nullptr, nullptr, k1s, 0.f, HID, K3BIG);
    mma_gemm_kernel<0><<<gBig, 256, GEMM_SMEM>>>(xs, ws + 2 * wsz, nullptr, bV, nullptr, 0.f, HID, K3BIG);

    // ---- fm weight interleave + fused fm GEMMs ----
    fm_interleave_kernel<<<128, 256>>>(fmq_w1, fmq_w2, fmq_b1, fmq_b2, fmwI, fmbI);
    fm_interleave_kernel<<<128, 256>>>(fmk_w1, fmk_w2, fmk_b1, fmk_b2,
                                       fmwI + (size_t)256 * K3FM, fmbI + 256);

    dim3 gFm(2, FMROWS / 128);           // N=256 -> (2, 1024)
    const float scale = 0.08838834764831845f; // 128^-0.5
    mma_gemm_kernel<3><<<gFm, 256, GEMM_SMEM>>>(q1s, fmwI, fmbI, bQ, nullptr, scale, 256, K3FM);
    mma_gemm_kernel<3><<<gFm, 256, GEMM_SMEM>>>(k1s, fmwI + (size_t)256 * K3FM, fmbI + 256,
                                                bK, nullptr, 1.0f, 256, K3FM);

    // ---- chunked linear attention (fp32, split-bf16 epilogue) ----
    const int nBlk = BB * NCH * HH;
    chunk_kv_kernel<<<nBlk, 256, smem_kv>>>(bK, bV, bKV);
    scan_kv_kernel<<<(BB * HH * 16384) / 256, 256>>>(bKV);
    chunk_out_kernel<<<nBlk, 256, smem_out>>>(bQ, bK, bV, bKV, rms_w, os);

    // ---- output projection ----
    mma_gemm_kernel<0><<<gBig, 256, GEMM_SMEM>>>(os, ws + 3 * wsz, nullptr, out, nullptr, 0.f, HID, K3BIG);
}

// round 11
// speedup vs baseline: 2.2548x; 1.2630x over previous
#include <cuda_runtime.h>
#include <cuda_fp16.h>
#include <cstddef>
#include <cstdint>

// Problem constants
#define BB 2
#define TT 8192
#define HH 8
#define DKV 128
#define HID 1024
#define CHUNK 64
#define NCH 128           // TT / CHUNK
#define MROWS (BB*TT)     // 16384
#define FMROWS (BB*TT*HH) // 131072
#define EPS 1e-5f
#define K2BIG (2*HID)     // 2048
#define K2FM  (2*DKV)     // 256

// -------- fp32 scratch --------
__device__ float g_bufQ[MROWS * HID];   // q after feature map
__device__ float g_bufK[MROWS * HID];   // k after feature map
__device__ float g_bufV[MROWS * HID];   // v projection
__device__ float g_kv[(size_t)BB * NCH * HH * DKV * DKV];

// -------- fp16 split scratch --------
__device__ __half g_xs [(size_t)MROWS * K2BIG];       // x split [hi|lo]
__device__ __half g_ws [(size_t)4 * HID * K2BIG];     // Wq,Wk,Wv,Wo [hi|hi]
__device__ __half g_q1s[(size_t)FMROWS * K2FM];       // q proj split [hi|lo] per head
__device__ __half g_k1s[(size_t)FMROWS * K2FM];
__device__ __half g_os [(size_t)MROWS * K2BIG];       // attention out split [hi|lo]
__device__ __half g_fmwI[2][256 * K2FM];              // interleaved fm weights [hi|hi]
__device__ float g_fmbI[2][256];                      // interleaved fm biases

__device__ __forceinline__ uint32_t smem_u32(const void* p) {
    uint32_t a;
    asm("{ .reg .u64 t; cvta.to.shared.u64 t, %1; cvt.u32.u64 %0, t; }"
        : "=r"(a) : "l"(p));
    return a;
}

// ============================================================
// split2: fp32 [R,K] -> fp16 [R,2K]
//   mode 0 (activations): [hi | lo]   (lo = x - hi, exact residual)
//   mode 1 (weights):     [hi | hi]
// A[hi|lo] . W[hi|hi] = (Ah+Al).Wh = A.Wh ; err = A.(W-Wh) ~ 7e-5
// ============================================================
__global__ void split2_kernel(const float* __restrict__ in,
                              __half* __restrict__ out,
                              int log2K, size_t total, int mode)
{
    size_t i = ((size_t)blockIdx.x * blockDim.x + threadIdx.x) * 2;
    if (i >= total) return;
    const int K = 1 << log2K;
    size_t r = i >> log2K;
    int c = (int)(i & (size_t)(K - 1));
    float2 x = *(const float2*)(in + i);
    __half h0 = __float2half(x.x);
    __half h1 = __float2half(x.y);
    __half2 hv; hv.x = h0; hv.y = h1;
    __half* o = out + r * (size_t)(2 * K) + c;
    *(__half2*)(o) = hv;
    if (mode == 0) {
        __half2 lv;
        lv.x = __float2half(x.x - __half2float(h0));
        lv.y = __float2half(x.y - __half2float(h1));
        *(__half2*)(o + K) = lv;
    } else {
        *(__half2*)(o + K) = hv;
    }
}

// ============================================================
// fm weight interleave: rows alternate w1/w2, weight mode [hi|hi]
// ============================================================
__global__ void fm_interleave_kernel(const float* __restrict__ w1,
                                     const float* __restrict__ w2,
                                     const float* __restrict__ b1,
                                     const float* __restrict__ b2,
                                     __half* __restrict__ outW,
                                     float* __restrict__ outB)
{
    int idx = blockIdx.x * 256 + threadIdx.x;   // 0..32767
    int rp = idx >> 7;                          // 0..255
    int c  = idx & 127;
    const float* w = (rp & 1) ? w2 : w1;
    int sr = rp >> 1;
    float v = w[sr * 128 + c];
    __half h = __float2half(v);
    __half* o = outW + (size_t)rp * K2FM + c;
    o[0] = h; o[128] = h;
    if (c == 0) outB[rp] = ((rp & 1) ? b2 : b1)[sr];
}

// ============================================================
// Tensor-core GEMM: C[M,N] = A[M,K] @ B[N,K]^T (+bias), fp16 in, fp32 acc
// 128x128 CTA tile, BK=32, 4-stage cp.async ring, 8 warps (32x64),
// ldmatrix + m16n8k16 f16 mma.
// Epilogues:
//   EPI==0: C fp32 (+bias)
//   EPI==2: fp16 split2 act out, N=1024 -> 8 heads x 256 cols [hi|lo]
//   EPI==3: fm fused: even/odd col pairs multiplied -> fp32 [.,128]
// ============================================================
#define ASTAGE 10240            // 128 rows x 80B
#define STAGEB 20480            // A + B per stage
#define NSTG 4
#define GEMM_SMEM (NSTG * STAGEB)  // 81920

template<int EPI>
__global__ __launch_bounds__(256, 2) void mma_gemm_kernel(
    const __half* __restrict__ A,
    const __half* __restrict__ B,
    const float* __restrict__ bias,
    float* __restrict__ Cf,
    __half* __restrict__ Chf,
    float mulscale,
    int N, int K)
{
    extern __shared__ __align__(16) char dynsm[];
    const uint32_t sBase = smem_u32(dynsm);

    const int tid = threadIdx.x;
    const int lane = tid & 31;
    const int wid = tid >> 5;
    const int warp_m = (wid & 3) * 32;
    const int warp_n = (wid >> 2) * 64;
    const int bm0 = blockIdx.y * 128;
    const int bn0 = blockIdx.x * 128;
    const int NC = K >> 5;

    const size_t rowb = (size_t)K * 2;
    const char* Ag = (const char*)A + (size_t)bm0 * rowb;
    const char* Bg = (const char*)B + (size_t)bn0 * rowb;

    const int r0 = tid >> 2, g0 = tid & 3;
    const int r1 = (tid + 256) >> 2, g1 = (tid + 256) & 3;

    auto load_stage = [&](int kc, int s) {
        const size_t koff = (size_t)kc * 64;
        const uint32_t ab = sBase + (uint32_t)(s * STAGEB);
        const uint32_t bb = ab + ASTAGE;
        uint32_t sa0 = ab + (uint32_t)(r0 * 80 + g0 * 16);
        uint32_t sa1 = ab + (uint32_t)(r1 * 80 + g1 * 16);
        uint32_t sb0 = bb + (uint32_t)(r0 * 80 + g0 * 16);
        uint32_t sb1 = bb + (uint32_t)(r1 * 80 + g1 * 16);
        const void* ga0 = Ag + (size_t)r0 * rowb + koff + g0 * 16;
        const void* ga1 = Ag + (size_t)r1 * rowb + koff + g1 * 16;
        const void* gb0 = Bg + (size_t)r0 * rowb + koff + g0 * 16;
        const void* gb1 = Bg + (size_t)r1 * rowb + koff + g1 * 16;
        asm volatile("cp.async.cg.shared.global [%0], [%1], 16;" :: "r"(sa0), "l"(ga0));
        asm volatile("cp.async.cg.shared.global [%0], [%1], 16;" :: "r"(sa1), "l"(ga1));
        asm volatile("cp.async.cg.shared.global [%0], [%1], 16;" :: "r"(sb0), "l"(gb0));
        asm volatile("cp.async.cg.shared.global [%0], [%1], 16;" :: "r"(sb1), "l"(gb1));
        asm volatile("cp.async.commit_group;");
    };

    float acc[2][8][4];
#pragma unroll
    for (int mt = 0; mt < 2; mt++)
#pragma unroll
        for (int nt = 0; nt < 8; nt++)
#pragma unroll
            for (int j = 0; j < 4; j++) acc[mt][nt][j] = 0.f;

    load_stage(0, 0);
    load_stage(1, 1);
    load_stage(2, 2);

    const int lm = lane & 15;
    const int lk = lane >> 4;
    const uint32_t aOff = (uint32_t)((warp_m + lm) * 80 + lk * 16);
    const uint32_t bOff = (uint32_t)(ASTAGE + (warp_n + lm) * 80 + lk * 16);

    for (int kc = 0; kc < NC; kc++) {
        const int s = kc & (NSTG - 1);
        if (kc + 3 <= NC)      asm volatile("cp.async.wait_group 2;");
        else if (kc + 2 == NC) asm volatile("cp.async.wait_group 1;");
        else                   asm volatile("cp.async.wait_group 0;");
        __syncthreads();
        if (kc + 3 < NC) load_stage(kc + 3, (kc + 3) & (NSTG - 1));

        const uint32_t aSt = sBase + (uint32_t)(s * STAGEB) + aOff;
        const uint32_t bSt = sBase + (uint32_t)(s * STAGEB) + bOff;

#pragma unroll
        for (int ks = 0; ks < 2; ks++) {
            uint32_t a[2][4], bf[4][4];
#pragma unroll
            for (int mt = 0; mt < 2; mt++) {
                uint32_t ad = aSt + (uint32_t)(mt * 16 * 80 + ks * 32);
                asm volatile("ldmatrix.sync.aligned.m8n8.x4.shared.b16 {%0,%1,%2,%3}, [%4];"
                             : "=r"(a[mt][0]), "=r"(a[mt][1]), "=r"(a[mt][2]), "=r"(a[mt][3])
                             : "r"(ad));
            }
#pragma unroll
            for (int ng = 0; ng < 4; ng++) {
                uint32_t bd = bSt + (uint32_t)(ng * 16 * 80 + ks * 32);
                asm volatile("ldmatrix.sync.aligned.m8n8.x4.shared.b16 {%0,%1,%2,%3}, [%4];"
                             : "=r"(bf[ng][0]), "=r"(bf[ng][1]), "=r"(bf[ng][2]), "=r"(bf[ng][3])
                             : "r"(bd));
            }
#pragma unroll
            for (int mt = 0; mt < 2; mt++)
#pragma unroll
                for (int nt = 0; nt < 8; nt++) {
                    const int g = nt >> 1, sel = nt & 1;
                    asm volatile(
                        "mma.sync.aligned.m16n8k16.row.col.f32.f16.f16.f32 "
                        "{%0,%1,%2,%3}, {%4,%5,%6,%7}, {%8,%9}, {%0,%1,%2,%3};"
                        : "+f"(acc[mt][nt][0]), "+f"(acc[mt][nt][1]),
                          "+f"(acc[mt][nt][2]), "+f"(acc[mt][nt][3])
                        : "r"(a[mt][0]), "r"(a[mt][1]), "r"(a[mt][2]), "r"(a[mt][3]),
                          "r"(bf[g][sel]), "r"(bf[g][sel + 2]));
                }
        }
    }

    // ---- epilogue ----
    const int erow = bm0 + warp_m + (lane >> 2);
    const int ecol0 = bn0 + warp_n + (lane & 3) * 2;
#pragma unroll
    for (int nt = 0; nt < 8; nt++) {
        const int col = ecol0 + nt * 8;
        float bx = 0.f, by = 0.f;
        if (bias) { bx = bias[col]; by = bias[col + 1]; }
#pragma unroll
        for (int mt = 0; mt < 2; mt++) {
#pragma unroll
            for (int half = 0; half < 2; half++) {
                const int row = erow + mt * 16 + half * 8;
                float vx = acc[mt][nt][half * 2 + 0] + bx;
                float vy = acc[mt][nt][half * 2 + 1] + by;
                if (EPI == 0) {
                    *(float2*)(Cf + (size_t)row * N + col) = make_float2(vx, vy);
                } else if (EPI == 3) {
                    // even/odd cols are (branch1, branch2) of output col j
                    Cf[(size_t)row * 128 + (col >> 1)] = vx * vy * mulscale;
                } else {
                    // N=1024 -> 8 heads x 256 cols [hi|lo]
                    const int rr = row * 8 + (col >> 7);
                    const int cc = col & 127;
                    __half h0 = __float2half(vx);
                    __half h1 = __float2half(vy);
                    __half2 hv; hv.x = h0; hv.y = h1;
                    __half2 lv;
                    lv.x = __float2half(vx - __half2float(h0));
                    lv.y = __float2half(vy - __half2float(h1));
                    __half* p = Chf + (size_t)rr * 256 + cc;
                    *(__half2*)(p)       = hv;
                    *(__half2*)(p + 128) = lv;
                }
            }
        }
    }
}

// ============================================================
// Per-chunk kv = k_c^T @ v_c : [128,128] per (b,n,h)
// ============================================================
__global__ __launch_bounds__(256) void chunk_kv_kernel(
    const float* __restrict__ k, const float* __restrict__ v,
    float* __restrict__ kv)
{
    extern __shared__ float sm[];
    float* ks = sm;
    float* vs = sm + 64 * 128;

    const int bid = blockIdx.x;
    const int h = bid % HH;
    const int n = (bid / HH) % NCH;
    const int b = bid / (HH * NCH);
    const size_t base = (((size_t)b * TT + (size_t)n * CHUNK) * HH + h) * DKV;

    const int tid = threadIdx.x;
    for (int off = tid * 4; off < 64 * 128; off += 256 * 4) {
        int c = off >> 7, d = off & 127;
        *(float4*)&ks[off] = *(const float4*)&k[base + (size_t)c * (HH * DKV) + d];
        *(float4*)&vs[off] = *(const float4*)&v[base + (size_t)c * (HH * DKV) + d];
    }
    __syncthreads();

    const int tx = tid & 15, ty = tid >> 4;
    float acc[8][8];
#pragma unroll
    for (int i = 0; i < 8; i++)
#pragma unroll
        for (int j = 0; j < 8; j++) acc[i][j] = 0.f;

    for (int c = 0; c < 64; c++) {
        float a[8], bb[8];
        *(float4*)(a)      = *(const float4*)&ks[c * 128 + ty * 8];
        *(float4*)(a + 4)  = *(const float4*)&ks[c * 128 + ty * 8 + 4];
        *(float4*)(bb)     = *(const float4*)&vs[c * 128 + tx * 8];
        *(float4*)(bb + 4) = *(const float4*)&vs[c * 128 + tx * 8 + 4];
#pragma unroll
        for (int i = 0; i < 8; i++)
#pragma unroll
            for (int j = 0; j < 8; j++)
                acc[i][j] += a[i] * bb[j];
    }

    float* outp = kv + (size_t)bid * (DKV * DKV);
#pragma unroll
    for (int i = 0; i < 8; i++) {
        float* cp = outp + (ty * 8 + i) * 128 + tx * 8;
        *(float4*)(cp)     = make_float4(acc[i][0], acc[i][1], acc[i][2], acc[i][3]);
        *(float4*)(cp + 4) = make_float4(acc[i][4], acc[i][5], acc[i][6], acc[i][7]);
    }
}

// ============================================================
// Exclusive prefix over chunks (in-place)
// ============================================================
__global__ void scan_kv_kernel(float* __restrict__ kv)
{
    int gid = blockIdx.x * blockDim.x + threadIdx.x;
    int e = gid & 16383;
    int h = (gid >> 14) % HH;
    int b = gid / (16384 * HH);
    size_t idx = (((size_t)b * NCH) * HH + h) * 16384 + e;
    const size_t stride = (size_t)HH * 16384;
    float acc = 0.f;
#pragma unroll 4
    for (int n = 0; n < NCH; n++) {
        float x = kv[idx];
        kv[idx] = acc;
        acc += x;
        idx += stride;
    }
}

// ============================================================
// Per-chunk output: o = tril(q k^T) v + q @ S, fused RMSNorm,
// epilogue writes fp16 split2 os rows [hi(1024)|lo(1024)]
// ============================================================
__global__ __launch_bounds__(256) void chunk_out_kernel(
    const float* __restrict__ q, const float* __restrict__ k,
    const float* __restrict__ v, const float* __restrict__ kvS,
    const float* __restrict__ rms_w, __half* __restrict__ os)
{
    extern __shared__ float sm[];
    float* qT = sm;
    float* kT = qT + 128 * 65;
    float* vs = kT + 128 * 65;
    float* Ss = vs + 64 * 128;
    float* AT = Ss + 128 * 128;
    float* rw = AT + 64 * 65;

    const int bid = blockIdx.x;
    const int h = bid % HH;
    const int n = (bid / HH) % NCH;
    const int b = bid / (HH * NCH);
    const size_t base = (((size_t)b * TT + (size_t)n * CHUNK) * HH + h) * DKV;

    const int tid = threadIdx.x;

    for (int off = tid; off < 64 * 128; off += 256) {
        int c = off >> 7, d = off & 127;
        qT[d * 65 + c] = q[base + (size_t)c * (HH * DKV) + d];
        kT[d * 65 + c] = k[base + (size_t)c * (HH * DKV) + d];
    }
    for (int off = tid * 4; off < 64 * 128; off += 256 * 4) {
        int c = off >> 7, d = off & 127;
        *(float4*)&vs[off] = *(const float4*)&v[base + (size_t)c * (HH * DKV) + d];
    }
    {
        const float* Sg = kvS + (size_t)bid * (DKV * DKV);
        for (int off = tid * 4; off < 128 * 128; off += 256 * 4)
            *(float4*)&Ss[off] = *(const float4*)&Sg[off];
    }
    if (tid < 128) rw[tid] = rms_w[tid];
    __syncthreads();

    const int tx = tid & 15, ty = tid >> 4;

    {
        float accA[4][4];
#pragma unroll
        for (int i = 0; i < 4; i++)
#pragma unroll
            for (int j = 0; j < 4; j++) accA[i][j] = 0.f;
        for (int d = 0; d < 128; d++) {
            float a[4], bb[4];
#pragma unroll
            for (int i = 0; i < 4; i++) a[i] = qT[d * 65 + ty * 4 + i];
#pragma unroll
            for (int j = 0; j < 4; j++) bb[j] = kT[d * 65 + tx * 4 + j];
#pragma unroll
            for (int i = 0; i < 4; i++)
#pragma unroll
                for (int j = 0; j < 4; j++)
                    accA[i][j] += a[i] * bb[j];
        }
#pragma unroll
        for (int i = 0; i < 4; i++) {
            int r = ty * 4 + i;
#pragma unroll
            for (int j = 0; j < 4; j++) {
                int c = tx * 4 + j;
                AT[c * 65 + r] = (c <= r) ? accA[i][j] : 0.f;
            }
        }
    }
    __syncthreads();

    float acc[4][8];
#pragma unroll
    for (int i = 0; i < 4; i++)
#pragma unroll
        for (int j = 0; j < 8; j++) acc[i][j] = 0.f;

    for (int kk = 0; kk < 128; kk++) {
        float a[4], bb[8];
#pragma unroll
        for (int i = 0; i < 4; i++) a[i] = qT[kk * 65 + ty * 4 + i];
        *(float4*)(bb)     = *(const float4*)&Ss[kk * 128 + tx * 8];
        *(float4*)(bb + 4) = *(const float4*)&Ss[kk * 128 + tx * 8 + 4];
#pragma unroll
        for (int i = 0; i < 4; i++)
#pragma unroll
            for (int j = 0; j < 8; j++)
                acc[i][j] += a[i] * bb[j];
    }
    for (int c = 0; c < 64; c++) {
        float a[4], bb[8];
#pragma unroll
        for (int i = 0; i < 4; i++) a[i] = AT[c * 65 + ty * 4 + i];
        *(float4*)(bb)     = *(const float4*)&vs[c * 128 + tx * 8];
        *(float4*)(bb + 4) = *(const float4*)&vs[c * 128 + tx * 8 + 4];
#pragma unroll
        for (int i = 0; i < 4; i++)
#pragma unroll
            for (int j = 0; j < 8; j++)
                acc[i][j] += a[i] * bb[j];
    }

#pragma unroll
    for (int i = 0; i < 4; i++) {
        float s = 0.f;
#pragma unroll
        for (int j = 0; j < 8; j++) s += acc[i][j] * acc[i][j];
        s += __shfl_xor_sync(0xffffffffu, s, 1);
        s += __shfl_xor_sync(0xffffffffu, s, 2);
        s += __shfl_xor_sync(0xffffffffu, s, 4);
        s += __shfl_xor_sync(0xffffffffu, s, 8);
        float scale = rsqrtf(s * (1.0f / 128.0f) + EPS);
#pragma unroll
        for (int j = 0; j < 8; j++)
            acc[i][j] *= scale * rw[tx * 8 + j];
    }

#pragma unroll
    for (int i = 0; i < 4; i++) {
        int r = ty * 4 + i;
        size_t R = (size_t)b * TT + (size_t)n * CHUNK + r;
        __half* p = os + R * 2048 + h * 128 + tx * 8;
#pragma unroll
        for (int j = 0; j < 8; j += 2) {
            float vx = acc[i][j], vy = acc[i][j + 1];
            __half h0 = __float2half(vx);
            __half h1 = __float2half(vy);
            __half2 hv; hv.x = h0; hv.y = h1;
            __half2 lv;
            lv.x = __float2half(vx - __half2float(h0));
            lv.y = __float2half(vy - __half2float(h1));
            *(__half2*)(p + j)        = hv;
            *(__half2*)(p + 1024 + j) = lv;
        }
    }
}

// ============================================================
// Launch
// ============================================================
extern "C" void kernel_launch(void* const* d_in, const int* in_sizes, int n_in,
                              void* d_out, int out_size)
{
    const float* x      = (const float*)d_in[0];
    const float* Wq     = (const float*)d_in[1];
    const float* Wk     = (const float*)d_in[2];
    const float* Wv     = (const float*)d_in[3];
    const float* fmq_w1 = (const float*)d_in[4];
    const float* fmq_b1 = (const float*)d_in[5];
    const float* fmq_w2 = (const float*)d_in[6];
    const float* fmq_b2 = (const float*)d_in[7];
    const float* fmk_w1 = (const float*)d_in[8];
    const float* fmk_b1 = (const float*)d_in[9];
    const float* fmk_w2 = (const float*)d_in[10];
    const float* fmk_b2 = (const float*)d_in[11];
    const float* rms_w  = (const float*)d_in[12];
    const float* Wo     = (const float*)d_in[13];
    float* out = (float*)d_out;

    float *bQ, *bK, *bV, *bKV;
    cudaGetSymbolAddress((void**)&bQ, g_bufQ);
    cudaGetSymbolAddress((void**)&bK, g_bufK);
    cudaGetSymbolAddress((void**)&bV, g_bufV);
    cudaGetSymbolAddress((void**)&bKV, g_kv);

    __half *xs, *ws, *q1s, *k1s, *os, *fmwI;
    float* fmbI;
    cudaGetSymbolAddress((void**)&xs,  g_xs);
    cudaGetSymbolAddress((void**)&ws,  g_ws);
    cudaGetSymbolAddress((void**)&q1s, g_q1s);
    cudaGetSymbolAddress((void**)&k1s, g_k1s);
    cudaGetSymbolAddress((void**)&os,  g_os);
    cudaGetSymbolAddress((void**)&fmwI, g_fmwI);
    cudaGetSymbolAddress((void**)&fmbI, g_fmbI);

    const int smem_kv  = 2 * 64 * 128 * 4;
    const int smem_out = (2 * 128 * 65 + 64 * 128 + 128 * 128 + 64 * 65 + 128) * 4;
    cudaFuncSetAttribute(chunk_kv_kernel,  cudaFuncAttributeMaxDynamicSharedMemorySize, smem_kv);
    cudaFuncSetAttribute(chunk_out_kernel, cudaFuncAttributeMaxDynamicSharedMemorySize, smem_out);
    cudaFuncSetAttribute(mma_gemm_kernel<0>, cudaFuncAttributeMaxDynamicSharedMemorySize, GEMM_SMEM);
    cudaFuncSetAttribute(mma_gemm_kernel<2>, cudaFuncAttributeMaxDynamicSharedMemorySize, GEMM_SMEM);
    cudaFuncSetAttribute(mma_gemm_kernel<3>, cudaFuncAttributeMaxDynamicSharedMemorySize, GEMM_SMEM);

    const size_t wsz = (size_t)HID * K2BIG;

    // ---- splits ----
    split2_kernel<<<(MROWS * HID) / 512, 256>>>(x, xs, 10, (size_t)MROWS * HID, 0);
    split2_kernel<<<(HID * HID) / 512, 256>>>(Wq, ws + 0 * wsz, 10, (size_t)HID * HID, 1);
    split2_kernel<<<(HID * HID) / 512, 256>>>(Wk, ws + 1 * wsz, 10, (size_t)HID * HID, 1);
    split2_kernel<<<(HID * HID) / 512, 256>>>(Wv, ws + 2 * wsz, 10, (size_t)HID * HID, 1);
    split2_kernel<<<(HID * HID) / 512, 256>>>(Wo, ws + 3 * wsz, 10, (size_t)HID * HID, 1);

    // ---- projections ----
    dim3 gBig(HID / 128, MROWS / 128);   // (8, 128)
    mma_gemm_kernel<2><<<gBig, 256, GEMM_SMEM>>>(xs, ws + 0 * wsz, nullptr, nullptr, q1s, 0.f, HID, K2BIG);
    mma_gemm_kernel<2><<<gBig, 256, GEMM_SMEM>>>(xs, ws + 1 * wsz, nullptr, nullptr, k1s, 0.f, HID, K2BIG);
    mma_gemm_kernel<0><<<gBig, 256, GEMM_SMEM>>>(xs, ws + 2 * wsz, nullptr, bV, nullptr, 0.f, HID, K2BIG);

    // ---- fm weight interleave + fused fm GEMMs ----
    fm_interleave_kernel<<<128, 256>>>(fmq_w1, fmq_w2, fmq_b1, fmq_b2, fmwI, fmbI);
    fm_interleave_kernel<<<128, 256>>>(fmk_w1, fmk_w2, fmk_b1, fmk_b2,
                                       fmwI + (size_t)256 * K2FM, fmbI + 256);

    dim3 gFm(2, FMROWS / 128);           // N=256 -> (2, 1024)
    const float scale = 0.08838834764831845f; // 128^-0.5
    mma_gemm_kernel<3><<<gFm, 256, GEMM_SMEM>>>(q1s, fmwI, fmbI, bQ, nullptr, scale, 256, K2FM);
    mma_gemm_kernel<3><<<gFm, 256, GEMM_SMEM>>>(k1s, fmwI + (size_t)256 * K2FM, fmbI + 256,
                                                bK, nullptr, 1.0f, 256, K2FM);

    // ---- chunked linear attention (fp32, fp16-split epilogue) ----
    const int nBlk = BB * NCH * HH;
    chunk_kv_kernel<<<nBlk, 256, smem_kv>>>(bK, bV, bKV);
    scan_kv_kernel<<<(BB * HH * 16384) / 256, 256>>>(bKV);
    chunk_out_kernel<<<nBlk, 256, smem_out>>>(bQ, bK, bV, bKV, rms_w, os);

    // ---- output projection ----
    mma_gemm_kernel<0><<<gBig, 256, GEMM_SMEM>>>(os, ws + 3 * wsz, nullptr, out, nullptr, 0.f, HID, K2BIG);
}

// round 12
// speedup vs baseline: 2.4335x; 1.0793x over previous
#include <cuda_runtime.h>
#include <cuda_fp16.h>
#include <cstddef>
#include <cstdint>

// Problem constants
#define BB 2
#define TT 8192
#define HH 8
#define DKV 128
#define HID 1024
#define CHUNK 64
#define NCH 128           // TT / CHUNK
#define MROWS (BB*TT)     // 16384
#define FMROWS (BB*TT*HH) // 131072
#define EPS 1e-5f
#define K2BIG (2*HID)     // 2048
#define K2FM  (2*DKV)     // 256

// -------- fp32 scratch --------
__device__ float g_bufQ[MROWS * HID];   // q after feature map
__device__ float g_bufK[MROWS * HID];   // k after feature map
__device__ float g_bufV[MROWS * HID];   // v projection
__device__ float g_kv[(size_t)BB * NCH * HH * DKV * DKV];

// -------- fp16 split scratch --------
__device__ __half g_xs [(size_t)MROWS * K2BIG];       // x split [hi|lo]
__device__ __half g_ws [(size_t)4 * HID * K2BIG];     // Wq,Wk,Wv,Wo [hi|hi]
__device__ __half g_q1s[(size_t)FMROWS * K2FM];       // q proj split [hi|lo] per head
__device__ __half g_k1s[(size_t)FMROWS * K2FM];
__device__ __half g_os [(size_t)MROWS * K2BIG];       // attention out split [hi|lo]
__device__ __half g_fmwI[2][256 * K2FM];              // interleaved fm weights [hi|hi]
__device__ float g_fmbI[2][256];                      // interleaved fm biases

__device__ __forceinline__ uint32_t smem_u32(const void* p) {
    uint32_t a;
    asm("{ .reg .u64 t; cvta.to.shared.u64 t, %1; cvt.u32.u64 %0, t; }"
        : "=r"(a) : "l"(p));
    return a;
}

#define LDSM(r0,r1,r2,r3,addr) \
    asm volatile("ldmatrix.sync.aligned.m8n8.x4.shared.b16 {%0,%1,%2,%3}, [%4];" \
                 : "=r"(r0),"=r"(r1),"=r"(r2),"=r"(r3) : "r"(addr))
#define LDSM_T(r0,r1,r2,r3,addr) \
    asm volatile("ldmatrix.sync.aligned.m8n8.x4.trans.shared.b16 {%0,%1,%2,%3}, [%4];" \
                 : "=r"(r0),"=r"(r1),"=r"(r2),"=r"(r3) : "r"(addr))
#define MMA16816(acc,a0,a1,a2,a3,b0,b1) \
    asm volatile("mma.sync.aligned.m16n8k16.row.col.f32.f16.f16.f32 " \
                 "{%0,%1,%2,%3}, {%4,%5,%6,%7}, {%8,%9}, {%0,%1,%2,%3};" \
                 : "+f"((acc)[0]), "+f"((acc)[1]), "+f"((acc)[2]), "+f"((acc)[3]) \
                 : "r"(a0), "r"(a1), "r"(a2), "r"(a3), "r"(b0), "r"(b1))

// ============================================================
// split2: fp32 [R,K] -> fp16 [R,2K]
//   mode 0 (activations): [hi | lo]
//   mode 1 (weights):     [hi | hi]
// ============================================================
__global__ void split2_kernel(const float* __restrict__ in,
                              __half* __restrict__ out,
                              int log2K, size_t total, int mode)
{
    size_t i = ((size_t)blockIdx.x * blockDim.x + threadIdx.x) * 2;
    if (i >= total) return;
    const int K = 1 << log2K;
    size_t r = i >> log2K;
    int c = (int)(i & (size_t)(K - 1));
    float2 x = *(const float2*)(in + i);
    __half h0 = __float2half(x.x);
    __half h1 = __float2half(x.y);
    __half2 hv; hv.x = h0; hv.y = h1;
    __half* o = out + r * (size_t)(2 * K) + c;
    *(__half2*)(o) = hv;
    if (mode == 0) {
        __half2 lv;
        lv.x = __float2half(x.x - __half2float(h0));
        lv.y = __float2half(x.y - __half2float(h1));
        *(__half2*)(o + K) = lv;
    } else {
        *(__half2*)(o + K) = hv;
    }
}

// ============================================================
// fm weight interleave: rows alternate w1/w2, weight mode [hi|hi]
// ============================================================
__global__ void fm_interleave_kernel(const float* __restrict__ w1,
                                     const float* __restrict__ w2,
                                     const float* __restrict__ b1,
                                     const float* __restrict__ b2,
                                     __half* __restrict__ outW,
                                     float* __restrict__ outB)
{
    int idx = blockIdx.x * 256 + threadIdx.x;
    int rp = idx >> 7;
    int c  = idx & 127;
    const float* w = (rp & 1) ? w2 : w1;
    int sr = rp >> 1;
    float v = w[sr * 128 + c];
    __half h = __float2half(v);
    __half* o = outW + (size_t)rp * K2FM + c;
    o[0] = h; o[128] = h;
    if (c == 0) outB[rp] = ((rp & 1) ? b2 : b1)[sr];
}

// ============================================================
// Tensor-core GEMM (unchanged from R11)
// ============================================================
#define ASTAGE 10240
#define STAGEB 20480
#define NSTG 4
#define GEMM_SMEM (NSTG * STAGEB)

template<int EPI>
__global__ __launch_bounds__(256, 2) void mma_gemm_kernel(
    const __half* __restrict__ A,
    const __half* __restrict__ B,
    const float* __restrict__ bias,
    float* __restrict__ Cf,
    __half* __restrict__ Chf,
    float mulscale,
    int N, int K)
{
    extern __shared__ __align__(16) char dynsm[];
    const uint32_t sBase = smem_u32(dynsm);

    const int tid = threadIdx.x;
    const int lane = tid & 31;
    const int wid = tid >> 5;
    const int warp_m = (wid & 3) * 32;
    const int warp_n = (wid >> 2) * 64;
    const int bm0 = blockIdx.y * 128;
    const int bn0 = blockIdx.x * 128;
    const int NC = K >> 5;

    const size_t rowb = (size_t)K * 2;
    const char* Ag = (const char*)A + (size_t)bm0 * rowb;
    const char* Bg = (const char*)B + (size_t)bn0 * rowb;

    const int r0 = tid >> 2, g0 = tid & 3;
    const int r1 = (tid + 256) >> 2, g1 = (tid + 256) & 3;

    auto load_stage = [&](int kc, int s) {
        const size_t koff = (size_t)kc * 64;
        const uint32_t ab = sBase + (uint32_t)(s * STAGEB);
        const uint32_t bb = ab + ASTAGE;
        uint32_t sa0 = ab + (uint32_t)(r0 * 80 + g0 * 16);
        uint32_t sa1 = ab + (uint32_t)(r1 * 80 + g1 * 16);
        uint32_t sb0 = bb + (uint32_t)(r0 * 80 + g0 * 16);
        uint32_t sb1 = bb + (uint32_t)(r1 * 80 + g1 * 16);
        const void* ga0 = Ag + (size_t)r0 * rowb + koff + g0 * 16;
        const void* ga1 = Ag + (size_t)r1 * rowb + koff + g1 * 16;
        const void* gb0 = Bg + (size_t)r0 * rowb + koff + g0 * 16;
        const void* gb1 = Bg + (size_t)r1 * rowb + koff + g1 * 16;
        asm volatile("cp.async.cg.shared.global [%0], [%1], 16;" :: "r"(sa0), "l"(ga0));
        asm volatile("cp.async.cg.shared.global [%0], [%1], 16;" :: "r"(sa1), "l"(ga1));
        asm volatile("cp.async.cg.shared.global [%0], [%1], 16;" :: "r"(sb0), "l"(gb0));
        asm volatile("cp.async.cg.shared.global [%0], [%1], 16;" :: "r"(sb1), "l"(gb1));
        asm volatile("cp.async.commit_group;");
    };

    float acc[2][8][4];
#pragma unroll
    for (int mt = 0; mt < 2; mt++)
#pragma unroll
        for (int nt = 0; nt < 8; nt++)
#pragma unroll
            for (int j = 0; j < 4; j++) acc[mt][nt][j] = 0.f;

    load_stage(0, 0);
    load_stage(1, 1);
    load_stage(2, 2);

    const int lm = lane & 15;
    const int lk = lane >> 4;
    const uint32_t aOff = (uint32_t)((warp_m + lm) * 80 + lk * 16);
    const uint32_t bOff = (uint32_t)(ASTAGE + (warp_n + lm) * 80 + lk * 16);

    for (int kc = 0; kc < NC; kc++) {
        const int s = kc & (NSTG - 1);
        if (kc + 3 <= NC)      asm volatile("cp.async.wait_group 2;");
        else if (kc + 2 == NC) asm volatile("cp.async.wait_group 1;");
        else                   asm volatile("cp.async.wait_group 0;");
        __syncthreads();
        if (kc + 3 < NC) load_stage(kc + 3, (kc + 3) & (NSTG - 1));

        const uint32_t aSt = sBase + (uint32_t)(s * STAGEB) + aOff;
        const uint32_t bSt = sBase + (uint32_t)(s * STAGEB) + bOff;

#pragma unroll
        for (int ks = 0; ks < 2; ks++) {
            uint32_t a[2][4], bf[4][4];
#pragma unroll
            for (int mt = 0; mt < 2; mt++) {
                uint32_t ad = aSt + (uint32_t)(mt * 16 * 80 + ks * 32);
                LDSM(a[mt][0], a[mt][1], a[mt][2], a[mt][3], ad);
            }
#pragma unroll
            for (int ng = 0; ng < 4; ng++) {
                uint32_t bd = bSt + (uint32_t)(ng * 16 * 80 + ks * 32);
                LDSM(bf[ng][0], bf[ng][1], bf[ng][2], bf[ng][3], bd);
            }
#pragma unroll
            for (int mt = 0; mt < 2; mt++)
#pragma unroll
                for (int nt = 0; nt < 8; nt++) {
                    const int g = nt >> 1, sel = nt & 1;
                    MMA16816(acc[mt][nt], a[mt][0], a[mt][1], a[mt][2], a[mt][3],
                             bf[g][sel], bf[g][sel + 2]);
                }
        }
    }

    const int erow = bm0 + warp_m + (lane >> 2);
    const int ecol0 = bn0 + warp_n + (lane & 3) * 2;
#pragma unroll
    for (int nt = 0; nt < 8; nt++) {
        const int col = ecol0 + nt * 8;
        float bx = 0.f, by = 0.f;
        if (bias) { bx = bias[col]; by = bias[col + 1]; }
#pragma unroll
        for (int mt = 0; mt < 2; mt++) {
#pragma unroll
            for (int half = 0; half < 2; half++) {
                const int row = erow + mt * 16 + half * 8;
                float vx = acc[mt][nt][half * 2 + 0] + bx;
                float vy = acc[mt][nt][half * 2 + 1] + by;
                if (EPI == 0) {
                    *(float2*)(Cf + (size_t)row * N + col) = make_float2(vx, vy);
                } else if (EPI == 3) {
                    Cf[(size_t)row * 128 + (col >> 1)] = vx * vy * mulscale;
                } else {
                    const int rr = row * 8 + (col >> 7);
                    const int cc = col & 127;
                    __half h0 = __float2half(vx);
                    __half h1 = __float2half(vy);
                    __half2 hv; hv.x = h0; hv.y = h1;
                    __half2 lv;
                    lv.x = __float2half(vx - __half2float(h0));
                    lv.y = __float2half(vy - __half2float(h1));
                    __half* p = Chf + (size_t)rr * 256 + cc;
                    *(__half2*)(p)       = hv;
                    *(__half2*)(p + 128) = lv;
                }
            }
        }
    }
}

// ============================================================
// chunk_kv_mma: kv = k_c^T @ v_c via fp16 HMMA, 3-product exact split.
// smem: kS [128 rows c' x 136] fp16 ([kh(64);kl(64)]), vS same ([vh;vl]).
// Virtual K = 192: kh.vh + kl.vh + kh.vl. trans-ldmatrix both operands.
// ============================================================
#define KV_SMEM (2 * 128 * 136 * 2)   // 69632

__global__ __launch_bounds__(256) void chunk_kv_mma(
    const float* __restrict__ k, const float* __restrict__ v,
    float* __restrict__ kv)
{
    extern __shared__ __align__(16) char sm[];
    __half* kS = (__half*)sm;                 // [128][136]
    __half* vS = (__half*)(sm + 128*136*2);
    const uint32_t kB = smem_u32(kS);
    const uint32_t vB = smem_u32(vS);

    const int bid = blockIdx.x;
    const int h = bid % HH, n = (bid / HH) % NCH, b = bid / (HH * NCH);
    const size_t base = (((size_t)b * TT + (size_t)n * CHUNK) * HH + h) * DKV;
    const int tid = threadIdx.x;
    const int lane = tid & 31;
    const int wid = tid >> 5;

    for (int off = tid * 4; off < 64 * 128; off += 1024) {
        int c = off >> 7, d = off & 127;
        float4 kk = *(const float4*)&k[base + (size_t)c * (HH * DKV) + d];
        float4 vv = *(const float4*)&v[base + (size_t)c * (HH * DKV) + d];
        __half2 kh0 = __floats2half2_rn(kk.x, kk.y);
        __half2 kh1 = __floats2half2_rn(kk.z, kk.w);
        __half2 kl0 = __floats2half2_rn(kk.x - __low2float(kh0),  kk.y - __high2float(kh0));
        __half2 kl1 = __floats2half2_rn(kk.z - __low2float(kh1),  kk.w - __high2float(kh1));
        __half2 vh0 = __floats2half2_rn(vv.x, vv.y);
        __half2 vh1 = __floats2half2_rn(vv.z, vv.w);
        __half2 vl0 = __floats2half2_rn(vv.x - __low2float(vh0),  vv.y - __high2float(vh0));
        __half2 vl1 = __floats2half2_rn(vv.z - __low2float(vh1),  vv.w - __high2float(vh1));
        *(__half2*)(kS + c * 136 + d)            = kh0;
        *(__half2*)(kS + c * 136 + d + 2)        = kh1;
        *(__half2*)(kS + (c + 64) * 136 + d)     = kl0;
        *(__half2*)(kS + (c + 64) * 136 + d + 2) = kl1;
        *(__half2*)(vS + c * 136 + d)            = vh0;
        *(__half2*)(vS + c * 136 + d + 2)        = vh1;
        *(__half2*)(vS + (c + 64) * 136 + d)     = vl0;
        *(__half2*)(vS + (c + 64) * 136 + d + 2) = vl1;
    }
    __syncthreads();

    const int warp_m = (wid & 3) * 32;
    const int warp_n = (wid >> 2) * 64;
    const int krl = ((lane >> 4) << 3) + (lane & 7);   // trans row offset
    const int mco = ((lane >> 3) & 1) << 3;            // trans col offset

    float acc[2][8][4];
#pragma unroll
    for (int mt = 0; mt < 2; mt++)
#pragma unroll
        for (int nt = 0; nt < 8; nt++)
#pragma unroll
            for (int j = 0; j < 4; j++) acc[mt][nt][j] = 0.f;

#pragma unroll
    for (int kc = 0; kc < 12; kc++) {
        const int t = kc >> 2;
        const int cb = (kc & 3) << 4;
        const int ar = ((t == 1) ? 64 : 0) + cb;   // kh,kl,kh
        const int br = ((t == 2) ? 64 : 0) + cb;   // vh,vh,vl
        uint32_t a[2][4], bf[4][4];
#pragma unroll
        for (int mt = 0; mt < 2; mt++) {
            uint32_t ad = kB + (uint32_t)(((ar + krl) * 136 + warp_m + mt * 16 + mco) * 2);
            LDSM_T(a[mt][0], a[mt][1], a[mt][2], a[mt][3], ad);
        }
#pragma unroll
        for (int ng = 0; ng < 4; ng++) {
            uint32_t bd = vB + (uint32_t)(((br + krl) * 136 + warp_n + ng * 16 + mco) * 2);
            LDSM_T(bf[ng][0], bf[ng][1], bf[ng][2], bf[ng][3], bd);
        }
#pragma unroll
        for (int mt = 0; mt < 2; mt++)
#pragma unroll
            for (int nt = 0; nt < 8; nt++) {
                const int g = nt >> 1, sel = nt & 1;
                MMA16816(acc[mt][nt], a[mt][0], a[mt][1], a[mt][2], a[mt][3],
                         bf[g][sel], bf[g][sel + 2]);
            }
    }

    float* outp = kv + (size_t)bid * (DKV * DKV);
    const int er = warp_m + (lane >> 2);
    const int ec = warp_n + (lane & 3) * 2;
#pragma unroll
    for (int nt = 0; nt < 8; nt++)
#pragma unroll
        for (int mt = 0; mt < 2; mt++)
#pragma unroll
            for (int half = 0; half < 2; half++) {
                int row = er + mt * 16 + half * 8;
                *(float2*)(outp + row * 128 + ec + nt * 8) =
                    make_float2(acc[mt][nt][half * 2], acc[mt][nt][half * 2 + 1]);
            }
}

// ============================================================
// Exclusive prefix over chunks (in-place)
// ============================================================
__global__ void scan_kv_kernel(float* __restrict__ kv)
{
    int gid = blockIdx.x * blockDim.x + threadIdx.x;
    int e = gid & 16383;
    int h = (gid >> 14) % HH;
    int b = gid / (16384 * HH);
    size_t idx = (((size_t)b * NCH) * HH + h) * 16384 + e;
    const size_t stride = (size_t)HH * 16384;
    float acc = 0.f;
#pragma unroll 4
    for (int n = 0; n < NCH; n++) {
        float x = kv[idx];
        kv[idx] = acc;
        acc += x;
        idx += stride;
    }
}

// ============================================================
// chunk_out_mma: A = tril(q k^T); o = A.v + q.S; RMSNorm; os split.
// All matmuls fp16 HMMA with 3-product exact splits.
// smem layout (bytes):
//   qS  @ 0      : [64][264] fp16  ([qh(128)|ql(128)])
//   A'  @ 33792  : [64][136] fp16  ([Ah(64)|Al(64)])
//   v'  @ 51200  : [128][136] fp16 ([vh(64);vl(64)])
//   S'  @ 86016  : [256][136] fp16 ([Sh(128);Sl(128)]); also kSm / oS reuse
// ============================================================
#define CO_QS   0
#define CO_AP   33792
#define CO_VP   51200
#define CO_SP   86016
#define CO_SMEM (86016 + 256*136*2)   // 155648

__global__ __launch_bounds__(256) void chunk_out_mma(
    const float* __restrict__ q, const float* __restrict__ k,
    const float* __restrict__ v, const float* __restrict__ kvS,
    const float* __restrict__ rms_w, __half* __restrict__ os)
{
    extern __shared__ __align__(16) char sm[];
    __half* qS = (__half*)(sm + CO_QS);
    __half* Ap = (__half*)(sm + CO_AP);
    __half* vP = (__half*)(sm + CO_VP);
    __half* sP = (__half*)(sm + CO_SP);
    __half* kSm = (__half*)(sm + CO_SP);     // A-phase reuse
    float* oS = (float*)(sm + CO_SP);        // post-mma reuse [64][132]
    const uint32_t qB = smem_u32(qS);
    const uint32_t aB = smem_u32(Ap);
    const uint32_t vB = smem_u32(vP);
    const uint32_t sB = smem_u32(sP);
    const uint32_t kB2 = sB;

    const int bid = blockIdx.x;
    const int h = bid % HH, n = (bid / HH) % NCH, b = bid / (HH * NCH);
    const size_t base = (((size_t)b * TT + (size_t)n * CHUNK) * HH + h) * DKV;
    const int tid = threadIdx.x;
    const int lane = tid & 31;
    const int wid = tid >> 5;

    // ---- phase 1: load q, k -> fp16 splits ----
    for (int off = tid * 4; off < 64 * 128; off += 1024) {
        int c = off >> 7, d = off & 127;
        float4 qq = *(const float4*)&q[base + (size_t)c * (HH * DKV) + d];
        float4 kk = *(const float4*)&k[base + (size_t)c * (HH * DKV) + d];
        __half2 qh0 = __floats2half2_rn(qq.x, qq.y);
        __half2 qh1 = __floats2half2_rn(qq.z, qq.w);
        __half2 ql0 = __floats2half2_rn(qq.x - __low2float(qh0), qq.y - __high2float(qh0));
        __half2 ql1 = __floats2half2_rn(qq.z - __low2float(qh1), qq.w - __high2float(qh1));
        __half2 kh0 = __floats2half2_rn(kk.x, kk.y);
        __half2 kh1 = __floats2half2_rn(kk.z, kk.w);
        __half2 kl0 = __floats2half2_rn(kk.x - __low2float(kh0), kk.y - __high2float(kh0));
        __half2 kl1 = __floats2half2_rn(kk.z - __low2float(kh1), kk.w - __high2float(kh1));
        *(__half2*)(qS + c * 264 + d)           = qh0;
        *(__half2*)(qS + c * 264 + d + 2)       = qh1;
        *(__half2*)(qS + c * 264 + 128 + d)     = ql0;
        *(__half2*)(qS + c * 264 + 128 + d + 2) = ql1;
        *(__half2*)(kSm + c * 264 + d)           = kh0;
        *(__half2*)(kSm + c * 264 + d + 2)       = kh1;
        *(__half2*)(kSm + c * 264 + 128 + d)     = kl0;
        *(__half2*)(kSm + c * 264 + 128 + d + 2) = kl1;
    }
    __syncthreads();

    const int krl = ((lane >> 4) << 3) + (lane & 7);
    const int mco = ((lane >> 3) & 1) << 3;

    // ---- phase 2: A = q.k^T (M=64, N=64, virtual K=384) ----
    {
        const int wmA = (wid & 1) * 32;
        const int wnA = (wid >> 1) * 16;
        float accA[2][2][4];
#pragma unroll
        for (int mt = 0; mt < 2; mt++)
#pragma unroll
            for (int nt = 0; nt < 2; nt++)
#pragma unroll
                for (int j = 0; j < 4; j++) accA[mt][nt][j] = 0.f;

#pragma unroll
        for (int kc = 0; kc < 24; kc++) {
            const int t = kc >> 3;
            const int cb = (kc & 7) << 4;
            const int qc = ((t == 1) ? 128 : 0) + cb;   // qh,ql,qh
            const int kc2 = ((t == 2) ? 128 : 0) + cb;  // kh,kh,kl
            uint32_t a[2][4], bf[4];
#pragma unroll
            for (int mt = 0; mt < 2; mt++) {
                uint32_t ad = qB + (uint32_t)(((wmA + mt * 16 + (lane & 15)) * 264
                                               + qc + ((lane >> 4) << 3)) * 2);
                LDSM(a[mt][0], a[mt][1], a[mt][2], a[mt][3], ad);
            }
            uint32_t bd = kB2 + (uint32_t)(((wnA + (lane & 15)) * 264
                                            + kc2 + ((lane >> 4) << 3)) * 2);
            LDSM(bf[0], bf[1], bf[2], bf[3], bd);
#pragma unroll
            for (int mt = 0; mt < 2; mt++)
#pragma unroll
                for (int nt = 0; nt < 2; nt++)
                    MMA16816(accA[mt][nt], a[mt][0], a[mt][1], a[mt][2], a[mt][3],
                             bf[nt], bf[nt + 2]);
        }

        // masked write to A' smem [Ah|Al]
        const int er = wmA + (lane >> 2);
        const int ec = wnA + (lane & 3) * 2;
#pragma unroll
        for (int mt = 0; mt < 2; mt++)
#pragma unroll
            for (int nt = 0; nt < 2; nt++)
#pragma unroll
                for (int half = 0; half < 2; half++) {
                    int r = er + mt * 16 + half * 8;
                    int c = ec + nt * 8;
                    float v0 = (c     <= r) ? accA[mt][nt][half * 2 + 0] : 0.f;
                    float v1 = (c + 1 <= r) ? accA[mt][nt][half * 2 + 1] : 0.f;
                    __half h0 = __float2half(v0);
                    __half h1 = __float2half(v1);
                    __half2 hv; hv.x = h0; hv.y = h1;
                    __half2 lv;
                    lv.x = __float2half(v0 - __half2float(h0));
                    lv.y = __float2half(v1 - __half2float(h1));
                    *(__half2*)(Ap + r * 136 + c)      = hv;
                    *(__half2*)(Ap + r * 136 + 64 + c) = lv;
                }
    }
    __syncthreads();   // A' complete; kSm region free

    // ---- phase 3: load v, S -> fp16 splits (overwrites kSm region with S') ----
    for (int off = tid * 4; off < 64 * 128; off += 1024) {
        int c = off >> 7, d = off & 127;
        float4 vv = *(const float4*)&v[base + (size_t)c * (HH * DKV) + d];
        __half2 vh0 = __floats2half2_rn(vv.x, vv.y);
        __half2 vh1 = __floats2half2_rn(vv.z, vv.w);
        __half2 vl0 = __floats2half2_rn(vv.x - __low2float(vh0), vv.y - __high2float(vh0));
        __half2 vl1 = __floats2half2_rn(vv.z - __low2float(vh1), vv.w - __high2float(vh1));
        *(__half2*)(vP + c * 136 + d)            = vh0;
        *(__half2*)(vP + c * 136 + d + 2)        = vh1;
        *(__half2*)(vP + (c + 64) * 136 + d)     = vl0;
        *(__half2*)(vP + (c + 64) * 136 + d + 2) = vl1;
    }
    {
        const float* Sg = kvS + (size_t)bid * (DKV * DKV);
        for (int off = tid * 4; off < 128 * 128; off += 1024) {
            int dr = off >> 7, dv = off & 127;
            float4 ss = *(const float4*)&Sg[dr * 128 + dv];
            __half2 sh0 = __floats2half2_rn(ss.x, ss.y);
            __half2 sh1 = __floats2half2_rn(ss.z, ss.w);
            __half2 sl0 = __floats2half2_rn(ss.x - __low2float(sh0), ss.y - __high2float(sh0));
            __half2 sl1 = __floats2half2_rn(ss.z - __low2float(sh1), ss.w - __high2float(sh1));
            *(__half2*)(sP + dr * 136 + dv)             = sh0;
            *(__half2*)(sP + dr * 136 + dv + 2)         = sh1;
            *(__half2*)(sP + (dr + 128) * 136 + dv)     = sl0;
            *(__half2*)(sP + (dr + 128) * 136 + dv + 2) = sl1;
        }
    }
    __syncthreads();

    // ---- phase 4: o = A'.v' + q.S' (M=64, N=128) ----
    const int warp_m = (wid & 1) * 32;
    const int warp_n = (wid >> 1) * 32;
    float acc[2][4][4];
#pragma unroll
    for (int mt = 0; mt < 2; mt++)
#pragma unroll
        for (int nt = 0; nt < 4; nt++)
#pragma unroll
            for (int j = 0; j < 4; j++) acc[mt][nt][j] = 0.f;

#pragma unroll
    for (int kc = 0; kc < 12; kc++) {       // A'.v' : Ah.vh + Al.vh + Ah.vl
        const int t = kc >> 2;
        const int cb = (kc & 3) << 4;
        const int ac = ((t == 1) ? 64 : 0) + cb;
        const int br = ((t == 2) ? 64 : 0) + cb;
        uint32_t a[2][4], bf[2][4];
#pragma unroll
        for (int mt = 0; mt < 2; mt++) {
            uint32_t ad = aB + (uint32_t)(((warp_m + mt * 16 + (lane & 15)) * 136
                                           + ac + ((lane >> 4) << 3)) * 2);
            LDSM(a[mt][0], a[mt][1], a[mt][2], a[mt][3], ad);
        }
#pragma unroll
        for (int ng = 0; ng < 2; ng++) {
            uint32_t bd = vB + (uint32_t)(((br + krl) * 136 + warp_n + ng * 16 + mco) * 2);
            LDSM_T(bf[ng][0], bf[ng][1], bf[ng][2], bf[ng][3], bd);
        }
#pragma unroll
        for (int mt = 0; mt < 2; mt++)
#pragma unroll
            for (int nt = 0; nt < 4; nt++) {
                const int g = nt >> 1, sel = nt & 1;
                MMA16816(acc[mt][nt], a[mt][0], a[mt][1], a[mt][2], a[mt][3],
                         bf[g][sel], bf[g][sel + 2]);
            }
    }
#pragma unroll
    for (int kc = 0; kc < 24; kc++) {       // q.S' : qh.Sh + ql.Sh + qh.Sl
        const int t = kc >> 3;
        const int cb = (kc & 7) << 4;
        const int qc = ((t == 1) ? 128 : 0) + cb;
        const int sr = ((t == 2) ? 128 : 0) + cb;
        uint32_t a[2][4], bf[2][4];
#pragma unroll
        for (int mt = 0; mt < 2; mt++) {
            uint32_t ad = qB + (uint32_t)(((warp_m + mt * 16 + (lane & 15)) * 264
                                           + qc + ((lane >> 4) << 3)) * 2);
            LDSM(a[mt][0], a[mt][1], a[mt][2], a[mt][3], ad);
        }
#pragma unroll
        for (int ng = 0; ng < 2; ng++) {
            uint32_t bd = sB + (uint32_t)(((sr + krl) * 136 + warp_n + ng * 16 + mco) * 2);
            LDSM_T(bf[ng][0], bf[ng][1], bf[ng][2], bf[ng][3], bd);
        }
#pragma unroll
        for (int mt = 0; mt < 2; mt++)
#pragma unroll
            for (int nt = 0; nt < 4; nt++) {
                const int g = nt >> 1, sel = nt & 1;
                MMA16816(acc[mt][nt], a[mt][0], a[mt][1], a[mt][2], a[mt][3],
                         bf[g][sel], bf[g][sel + 2]);
            }
    }

    // ---- phase 5: stage o to smem fp32 (reuses S' region) ----
    __syncthreads();
    {
        const int er = warp_m + (lane >> 2);
        const int ec = warp_n + (lane & 3) * 2;
#pragma unroll
        for (int mt = 0; mt < 2; mt++)
#pragma unroll
            for (int nt = 0; nt < 4; nt++)
#pragma unroll
                for (int half = 0; half < 2; half++) {
                    int r = er + mt * 16 + half * 8;
                    *(float2*)(oS + r * 132 + ec + nt * 8) =
                        make_float2(acc[mt][nt][half * 2], acc[mt][nt][half * 2 + 1]);
                }
    }
    __syncthreads();

    // ---- phase 6: RMSNorm + fp16-split write to os ----
    {
        const int r = tid >> 2;
        const int part = tid & 3;
        float vals[32];
        float s = 0.f;
#pragma unroll
        for (int j = 0; j < 32; j += 4) {
            float4 x = *(const float4*)(oS + r * 132 + part * 32 + j);
            vals[j] = x.x; vals[j+1] = x.y; vals[j+2] = x.z; vals[j+3] = x.w;
            s += x.x*x.x + x.y*x.y + x.z*x.z + x.w*x.w;
        }
        s += __shfl_xor_sync(0xffffffffu, s, 1);
        s += __shfl_xor_sync(0xffffffffu, s, 2);
        float scale = rsqrtf(s * (1.0f / 128.0f) + EPS);
        size_t R = (size_t)b * TT + (size_t)n * CHUNK + r;
        __half* p = os + R * 2048 + h * 128 + part * 32;
#pragma unroll
        for (int j = 0; j < 32; j += 2) {
            float vx = vals[j]   * scale * rms_w[part * 32 + j];
            float vy = vals[j+1] * scale * rms_w[part * 32 + j + 1];
            __half h0 = __float2half(vx);
            __half h1 = __float2half(vy);
            __half2 hv; hv.x = h0; hv.y = h1;
            __half2 lv;
            lv.x = __float2half(vx - __half2float(h0));
            lv.y = __float2half(vy - __half2float(h1));
            *(__half2*)(p + j)        = hv;
            *(__half2*)(p + 1024 + j) = lv;
        }
    }
}

// ============================================================
// Launch
// ============================================================
extern "C" void kernel_launch(void* const* d_in, const int* in_sizes, int n_in,
                              void* d_out, int out_size)
{
    const float* x      = (const float*)d_in[0];
    const float* Wq     = (const float*)d_in[1];
    const float* Wk     = (const float*)d_in[2];
    const float* Wv     = (const float*)d_in[3];
    const float* fmq_w1 = (const float*)d_in[4];
    const float* fmq_b1 = (const float*)d_in[5];
    const float* fmq_w2 = (const float*)d_in[6];
    const float* fmq_b2 = (const float*)d_in[7];
    const float* fmk_w1 = (const float*)d_in[8];
    const float* fmk_b1 = (const float*)d_in[9];
    const float* fmk_w2 = (const float*)d_in[10];
    const float* fmk_b2 = (const float*)d_in[11];
    const float* rms_w  = (const float*)d_in[12];
    const float* Wo     = (const float*)d_in[13];
    float* out = (float*)d_out;

    float *bQ, *bK, *bV, *bKV;
    cudaGetSymbolAddress((void**)&bQ, g_bufQ);
    cudaGetSymbolAddress((void**)&bK, g_bufK);
    cudaGetSymbolAddress((void**)&bV, g_bufV);
    cudaGetSymbolAddress((void**)&bKV, g_kv);

    __half *xs, *ws, *q1s, *k1s, *os, *fmwI;
    float* fmbI;
    cudaGetSymbolAddress((void**)&xs,  g_xs);
    cudaGetSymbolAddress((void**)&ws,  g_ws);
    cudaGetSymbolAddress((void**)&q1s, g_q1s);
    cudaGetSymbolAddress((void**)&k1s, g_k1s);
    cudaGetSymbolAddress((void**)&os,  g_os);
    cudaGetSymbolAddress((void**)&fmwI, g_fmwI);
    cudaGetSymbolAddress((void**)&fmbI, g_fmbI);

    cudaFuncSetAttribute(chunk_kv_mma,  cudaFuncAttributeMaxDynamicSharedMemorySize, KV_SMEM);
    cudaFuncSetAttribute(chunk_out_mma, cudaFuncAttributeMaxDynamicSharedMemorySize, CO_SMEM);
    cudaFuncSetAttribute(mma_gemm_kernel<0>, cudaFuncAttributeMaxDynamicSharedMemorySize, GEMM_SMEM);
    cudaFuncSetAttribute(mma_gemm_kernel<2>, cudaFuncAttributeMaxDynamicSharedMemorySize, GEMM_SMEM);
    cudaFuncSetAttribute(mma_gemm_kernel<3>, cudaFuncAttributeMaxDynamicSharedMemorySize, GEMM_SMEM);

    const size_t wsz = (size_t)HID * K2BIG;

    // ---- splits ----
    split2_kernel<<<(MROWS * HID) / 512, 256>>>(x, xs, 10, (size_t)MROWS * HID, 0);
    split2_kernel<<<(HID * HID) / 512, 256>>>(Wq, ws + 0 * wsz, 10, (size_t)HID * HID, 1);
    split2_kernel<<<(HID * HID) / 512, 256>>>(Wk, ws + 1 * wsz, 10, (size_t)HID * HID, 1);
    split2_kernel<<<(HID * HID) / 512, 256>>>(Wv, ws + 2 * wsz, 10, (size_t)HID * HID, 1);
    split2_kernel<<<(HID * HID) / 512, 256>>>(Wo, ws + 3 * wsz, 10, (size_t)HID * HID, 1);

    // ---- projections ----
    dim3 gBig(HID / 128, MROWS / 128);
    mma_gemm_kernel<2><<<gBig, 256, GEMM_SMEM>>>(xs, ws + 0 * wsz, nullptr, nullptr, q1s, 0.f, HID, K2BIG);
    mma_gemm_kernel<2><<<gBig, 256, GEMM_SMEM>>>(xs, ws + 1 * wsz, nullptr, nullptr, k1s, 0.f, HID, K2BIG);
    mma_gemm_kernel<0><<<gBig, 256, GEMM_SMEM>>>(xs, ws + 2 * wsz, nullptr, bV, nullptr, 0.f, HID, K2BIG);

    // ---- fm weight interleave + fused fm GEMMs ----
    fm_interleave_kernel<<<128, 256>>>(fmq_w1, fmq_w2, fmq_b1, fmq_b2, fmwI, fmbI);
    fm_interleave_kernel<<<128, 256>>>(fmk_w1, fmk_w2, fmk_b1, fmk_b2,
                                       fmwI + (size_t)256 * K2FM, fmbI + 256);

    dim3 gFm(2, FMROWS / 128);
    const float scale = 0.08838834764831845f;
    mma_gemm_kernel<3><<<gFm, 256, GEMM_SMEM>>>(q1s, fmwI, fmbI, bQ, nullptr, scale, 256, K2FM);
    mma_gemm_kernel<3><<<gFm, 256, GEMM_SMEM>>>(k1s, fmwI + (size_t)256 * K2FM, fmbI + 256,
                                                bK, nullptr, 1.0f, 256, K2FM);

    // ---- chunked linear attention (HMMA) ----
    const int nBlk = BB * NCH * HH;
    chunk_kv_mma<<<nBlk, 256, KV_SMEM>>>(bK, bV, bKV);
    scan_kv_kernel<<<(BB * HH * 16384) / 256, 256>>>(bKV);
    chunk_out_mma<<<nBlk, 256, CO_SMEM>>>(bQ, bK, bV, bKV, rms_w, os);

    // ---- output projection ----
    mma_gemm_kernel<0><<<gBig, 256, GEMM_SMEM>>>(os, ws + 3 * wsz, nullptr, out, nullptr, 0.f, HID, K2BIG);
}

// round 13
// speedup vs baseline: 2.8046x; 1.1525x over previous
#include <cuda_runtime.h>
#include <cuda_fp16.h>
#include <cstddef>
#include <cstdint>

// Problem constants
#define BB 2
#define TT 8192
#define HH 8
#define DKV 128
#define HID 1024
#define CHUNK 64
#define NCH 128           // TT / CHUNK
#define MROWS (BB*TT)     // 16384
#define FMROWS (BB*TT*HH) // 131072
#define EPS 1e-5f
#define K2BIG (2*HID)     // 2048
#define K2FM  (2*DKV)     // 256

// -------- fp32 scratch --------
__device__ float g_bufQ[MROWS * HID];   // q after feature map
__device__ float g_bufK[MROWS * HID];   // k after feature map
__device__ float g_bufV[MROWS * HID];   // v projection
__device__ float g_kv[(size_t)BB * NCH * HH * DKV * DKV];

// -------- fp16 split scratch --------
__device__ __half g_xs [(size_t)MROWS * K2BIG];       // x split [hi|lo]
__device__ __half g_ws [(size_t)2 * HID * K2BIG];     // Wq,Wk [hi|hi]
__device__ __half g_wv16[(size_t)HID * HID];          // Wv hi only
__device__ __half g_wo16[(size_t)HID * HID];          // Wo hi only
__device__ __half g_q1s[(size_t)FMROWS * K2FM];       // q proj split [hi|lo] per head
__device__ __half g_k1s[(size_t)FMROWS * K2FM];
__device__ __half g_os [(size_t)MROWS * K2BIG];       // attention out (hi half used)
__device__ __half g_fmwI[2][256 * K2FM];              // interleaved fm weights [hi|hi]
__device__ float g_fmbI[2][256];                      // interleaved fm biases

__device__ __forceinline__ uint32_t smem_u32(const void* p) {
    uint32_t a;
    asm("{ .reg .u64 t; cvta.to.shared.u64 t, %1; cvt.u32.u64 %0, t; }"
        : "=r"(a) : "l"(p));
    return a;
}

#define LDSM(r0,r1,r2,r3,addr) \
    asm volatile("ldmatrix.sync.aligned.m8n8.x4.shared.b16 {%0,%1,%2,%3}, [%4];" \
                 : "=r"(r0),"=r"(r1),"=r"(r2),"=r"(r3) : "r"(addr))
#define LDSM_T(r0,r1,r2,r3,addr) \
    asm volatile("ldmatrix.sync.aligned.m8n8.x4.trans.shared.b16 {%0,%1,%2,%3}, [%4];" \
                 : "=r"(r0),"=r"(r1),"=r"(r2),"=r"(r3) : "r"(addr))
#define MMA16816(acc,a0,a1,a2,a3,b0,b1) \
    asm volatile("mma.sync.aligned.m16n8k16.row.col.f32.f16.f16.f32 " \
                 "{%0,%1,%2,%3}, {%4,%5,%6,%7}, {%8,%9}, {%0,%1,%2,%3};" \
                 : "+f"((acc)[0]), "+f"((acc)[1]), "+f"((acc)[2]), "+f"((acc)[3]) \
                 : "r"(a0), "r"(a1), "r"(a2), "r"(a3), "r"(b0), "r"(b1))

// ============================================================
// split2: fp32 [R,K] -> fp16 [R,2K]
//   mode 0 (activations): [hi | lo]
//   mode 1 (weights):     [hi | hi]
// ============================================================
__global__ void split2_kernel(const float* __restrict__ in,
                              __half* __restrict__ out,
                              int log2K, size_t total, int mode)
{
    size_t i = ((size_t)blockIdx.x * blockDim.x + threadIdx.x) * 2;
    if (i >= total) return;
    const int K = 1 << log2K;
    size_t r = i >> log2K;
    int c = (int)(i & (size_t)(K - 1));
    float2 x = *(const float2*)(in + i);
    __half h0 = __float2half(x.x);
    __half h1 = __float2half(x.y);
    __half2 hv; hv.x = h0; hv.y = h1;
    __half* o = out + r * (size_t)(2 * K) + c;
    *(__half2*)(o) = hv;
    if (mode == 0) {
        __half2 lv;
        lv.x = __float2half(x.x - __half2float(h0));
        lv.y = __float2half(x.y - __half2float(h1));
        *(__half2*)(o + K) = lv;
    } else {
        *(__half2*)(o + K) = hv;
    }
}

// ============================================================
// tof16: plain fp32 -> fp16 convert (packed)
// ============================================================
__global__ void tof16_kernel(const float* __restrict__ in,
                             __half* __restrict__ out, size_t total)
{
    size_t i = ((size_t)blockIdx.x * blockDim.x + threadIdx.x) * 2;
    if (i >= total) return;
    float2 x = *(const float2*)(in + i);
    __half2 hv;
    hv.x = __float2half(x.x);
    hv.y = __float2half(x.y);
    *(__half2*)(out + i) = hv;
}

// ============================================================
// fm weight interleave: rows alternate w1/w2, weight mode [hi|hi]
// ============================================================
__global__ void fm_interleave_kernel(const float* __restrict__ w1,
                                     const float* __restrict__ w2,
                                     const float* __restrict__ b1,
                                     const float* __restrict__ b2,
                                     __half* __restrict__ outW,
                                     float* __restrict__ outB)
{
    int idx = blockIdx.x * 256 + threadIdx.x;
    int rp = idx >> 7;
    int c  = idx & 127;
    const float* w = (rp & 1) ? w2 : w1;
    int sr = rp >> 1;
    float v = w[sr * 128 + c];
    __half h = __float2half(v);
    __half* o = outW + (size_t)rp * K2FM + c;
    o[0] = h; o[128] = h;
    if (c == 0) outB[rp] = ((rp & 1) ? b2 : b1)[sr];
}

// ============================================================
// Tensor-core GEMM: C[M,N] = A[M,0:K] @ B[N,K]^T (+bias)
// A row stride = ldA elements (>= K); B packed rows of K.
// ============================================================
#define ASTAGE 10240
#define STAGEB 20480
#define NSTG 4
#define GEMM_SMEM (NSTG * STAGEB)

template<int EPI>
__global__ __launch_bounds__(256, 2) void mma_gemm_kernel(
    const __half* __restrict__ A,
    const __half* __restrict__ B,
    const float* __restrict__ bias,
    float* __restrict__ Cf,
    __half* __restrict__ Chf,
    float mulscale,
    int N, int K, int ldA)
{
    extern __shared__ __align__(16) char dynsm[];
    const uint32_t sBase = smem_u32(dynsm);

    const int tid = threadIdx.x;
    const int lane = tid & 31;
    const int wid = tid >> 5;
    const int warp_m = (wid & 3) * 32;
    const int warp_n = (wid >> 2) * 64;
    const int bm0 = blockIdx.y * 128;
    const int bn0 = blockIdx.x * 128;
    const int NC = K >> 5;

    const size_t rowbA = (size_t)ldA * 2;
    const size_t rowbB = (size_t)K * 2;
    const char* Ag = (const char*)A + (size_t)bm0 * rowbA;
    const char* Bg = (const char*)B + (size_t)bn0 * rowbB;

    const int r0 = tid >> 2, g0 = tid & 3;
    const int r1 = (tid + 256) >> 2, g1 = (tid + 256) & 3;

    auto load_stage = [&](int kc, int s) {
        const size_t koff = (size_t)kc * 64;
        const uint32_t ab = sBase + (uint32_t)(s * STAGEB);
        const uint32_t bb = ab + ASTAGE;
        uint32_t sa0 = ab + (uint32_t)(r0 * 80 + g0 * 16);
        uint32_t sa1 = ab + (uint32_t)(r1 * 80 + g1 * 16);
        uint32_t sb0 = bb + (uint32_t)(r0 * 80 + g0 * 16);
        uint32_t sb1 = bb + (uint32_t)(r1 * 80 + g1 * 16);
        const void* ga0 = Ag + (size_t)r0 * rowbA + koff + g0 * 16;
        const void* ga1 = Ag + (size_t)r1 * rowbA + koff + g1 * 16;
        const void* gb0 = Bg + (size_t)r0 * rowbB + koff + g0 * 16;
        const void* gb1 = Bg + (size_t)r1 * rowbB + koff + g1 * 16;
        asm volatile("cp.async.cg.shared.global [%0], [%1], 16;" :: "r"(sa0), "l"(ga0));
        asm volatile("cp.async.cg.shared.global [%0], [%1], 16;" :: "r"(sa1), "l"(ga1));
        asm volatile("cp.async.cg.shared.global [%0], [%1], 16;" :: "r"(sb0), "l"(gb0));
        asm volatile("cp.async.cg.shared.global [%0], [%1], 16;" :: "r"(sb1), "l"(gb1));
        asm volatile("cp.async.commit_group;");
    };

    float acc[2][8][4];
#pragma unroll
    for (int mt = 0; mt < 2; mt++)
#pragma unroll
        for (int nt = 0; nt < 8; nt++)
#pragma unroll
            for (int j = 0; j < 4; j++) acc[mt][nt][j] = 0.f;

    load_stage(0, 0);
    load_stage(1, 1);
    load_stage(2, 2);

    const int lm = lane & 15;
    const int lk = lane >> 4;
    const uint32_t aOff = (uint32_t)((warp_m + lm) * 80 + lk * 16);
    const uint32_t bOff = (uint32_t)(ASTAGE + (warp_n + lm) * 80 + lk * 16);

    for (int kc = 0; kc < NC; kc++) {
        const int s = kc & (NSTG - 1);
        if (kc + 3 <= NC)      asm volatile("cp.async.wait_group 2;");
        else if (kc + 2 == NC) asm volatile("cp.async.wait_group 1;");
        else                   asm volatile("cp.async.wait_group 0;");
        __syncthreads();
        if (kc + 3 < NC) load_stage(kc + 3, (kc + 3) & (NSTG - 1));

        const uint32_t aSt = sBase + (uint32_t)(s * STAGEB) + aOff;
        const uint32_t bSt = sBase + (uint32_t)(s * STAGEB) + bOff;

#pragma unroll
        for (int ks = 0; ks < 2; ks++) {
            uint32_t a[2][4], bf[4][4];
#pragma unroll
            for (int mt = 0; mt < 2; mt++) {
                uint32_t ad = aSt + (uint32_t)(mt * 16 * 80 + ks * 32);
                LDSM(a[mt][0], a[mt][1], a[mt][2], a[mt][3], ad);
            }
#pragma unroll
            for (int ng = 0; ng < 4; ng++) {
                uint32_t bd = bSt + (uint32_t)(ng * 16 * 80 + ks * 32);
                LDSM(bf[ng][0], bf[ng][1], bf[ng][2], bf[ng][3], bd);
            }
#pragma unroll
            for (int mt = 0; mt < 2; mt++)
#pragma unroll
                for (int nt = 0; nt < 8; nt++) {
                    const int g = nt >> 1, sel = nt & 1;
                    MMA16816(acc[mt][nt], a[mt][0], a[mt][1], a[mt][2], a[mt][3],
                             bf[g][sel], bf[g][sel + 2]);
                }
        }
    }

    const int erow = bm0 + warp_m + (lane >> 2);
    const int ecol0 = bn0 + warp_n + (lane & 3) * 2;
#pragma unroll
    for (int nt = 0; nt < 8; nt++) {
        const int col = ecol0 + nt * 8;
        float bx = 0.f, by = 0.f;
        if (bias) { bx = bias[col]; by = bias[col + 1]; }
#pragma unroll
        for (int mt = 0; mt < 2; mt++) {
#pragma unroll
            for (int half = 0; half < 2; half++) {
                const int row = erow + mt * 16 + half * 8;
                float vx = acc[mt][nt][half * 2 + 0] + bx;
                float vy = acc[mt][nt][half * 2 + 1] + by;
                if (EPI == 0) {
                    *(float2*)(Cf + (size_t)row * N + col) = make_float2(vx, vy);
                } else if (EPI == 3) {
                    Cf[(size_t)row * 128 + (col >> 1)] = vx * vy * mulscale;
                } else {
                    const int rr = row * 8 + (col >> 7);
                    const int cc = col & 127;
                    __half h0 = __float2half(vx);
                    __half h1 = __float2half(vy);
                    __half2 hv; hv.x = h0; hv.y = h1;
                    __half2 lv;
                    lv.x = __float2half(vx - __half2float(h0));
                    lv.y = __float2half(vy - __half2float(h1));
                    __half* p = Chf + (size_t)rr * 256 + cc;
                    *(__half2*)(p)       = hv;
                    *(__half2*)(p + 128) = lv;
                }
            }
        }
    }
}

// ============================================================
// chunk_kv_mma: kv = k_c^T @ v_c via fp16 HMMA, 3-product split.
// ============================================================
#define KV_SMEM (2 * 128 * 136 * 2)   // 69632

__global__ __launch_bounds__(256) void chunk_kv_mma(
    const float* __restrict__ k, const float* __restrict__ v,
    float* __restrict__ kv)
{
    extern __shared__ __align__(16) char sm[];
    __half* kS = (__half*)sm;                 // [128][136]
    __half* vS = (__half*)(sm + 128*136*2);
    const uint32_t kB = smem_u32(kS);
    const uint32_t vB = smem_u32(vS);

    const int bid = blockIdx.x;
    const int h = bid % HH, n = (bid / HH) % NCH, b = bid / (HH * NCH);
    const size_t base = (((size_t)b * TT + (size_t)n * CHUNK) * HH + h) * DKV;
    const int tid = threadIdx.x;
    const int lane = tid & 31;
    const int wid = tid >> 5;

    for (int off = tid * 4; off < 64 * 128; off += 1024) {
        int c = off >> 7, d = off & 127;
        float4 kk = *(const float4*)&k[base + (size_t)c * (HH * DKV) + d];
        float4 vv = *(const float4*)&v[base + (size_t)c * (HH * DKV) + d];
        __half2 kh0 = __floats2half2_rn(kk.x, kk.y);
        __half2 kh1 = __floats2half2_rn(kk.z, kk.w);
        __half2 kl0 = __floats2half2_rn(kk.x - __low2float(kh0),  kk.y - __high2float(kh0));
        __half2 kl1 = __floats2half2_rn(kk.z - __low2float(kh1),  kk.w - __high2float(kh1));
        __half2 vh0 = __floats2half2_rn(vv.x, vv.y);
        __half2 vh1 = __floats2half2_rn(vv.z, vv.w);
        __half2 vl0 = __floats2half2_rn(vv.x - __low2float(vh0),  vv.y - __high2float(vh0));
        __half2 vl1 = __floats2half2_rn(vv.z - __low2float(vh1),  vv.w - __high2float(vh1));
        *(__half2*)(kS + c * 136 + d)            = kh0;
        *(__half2*)(kS + c * 136 + d + 2)        = kh1;
        *(__half2*)(kS + (c + 64) * 136 + d)     = kl0;
        *(__half2*)(kS + (c + 64) * 136 + d + 2) = kl1;
        *(__half2*)(vS + c * 136 + d)            = vh0;
        *(__half2*)(vS + c * 136 + d + 2)        = vh1;
        *(__half2*)(vS + (c + 64) * 136 + d)     = vl0;
        *(__half2*)(vS + (c + 64) * 136 + d + 2) = vl1;
    }
    __syncthreads();

    const int warp_m = (wid & 3) * 32;
    const int warp_n = (wid >> 2) * 64;
    const int krl = ((lane >> 4) << 3) + (lane & 7);
    const int mco = ((lane >> 3) & 1) << 3;

    float acc[2][8][4];
#pragma unroll
    for (int mt = 0; mt < 2; mt++)
#pragma unroll
        for (int nt = 0; nt < 8; nt++)
#pragma unroll
            for (int j = 0; j < 4; j++) acc[mt][nt][j] = 0.f;

#pragma unroll
    for (int kc = 0; kc < 12; kc++) {
        const int t = kc >> 2;
        const int cb = (kc & 3) << 4;
        const int ar = ((t == 1) ? 64 : 0) + cb;
        const int br = ((t == 2) ? 64 : 0) + cb;
        uint32_t a[2][4], bf[4][4];
#pragma unroll
        for (int mt = 0; mt < 2; mt++) {
            uint32_t ad = kB + (uint32_t)(((ar + krl) * 136 + warp_m + mt * 16 + mco) * 2);
            LDSM_T(a[mt][0], a[mt][1], a[mt][2], a[mt][3], ad);
        }
#pragma unroll
        for (int ng = 0; ng < 4; ng++) {
            uint32_t bd = vB + (uint32_t)(((br + krl) * 136 + warp_n + ng * 16 + mco) * 2);
            LDSM_T(bf[ng][0], bf[ng][1], bf[ng][2], bf[ng][3], bd);
        }
#pragma unroll
        for (int mt = 0; mt < 2; mt++)
#pragma unroll
            for (int nt = 0; nt < 8; nt++) {
                const int g = nt >> 1, sel = nt & 1;
                MMA16816(acc[mt][nt], a[mt][0], a[mt][1], a[mt][2], a[mt][3],
                         bf[g][sel], bf[g][sel + 2]);
            }
    }

    float* outp = kv + (size_t)bid * (DKV * DKV);
    const int er = warp_m + (lane >> 2);
    const int ec = warp_n + (lane & 3) * 2;
#pragma unroll
    for (int nt = 0; nt < 8; nt++)
#pragma unroll
        for (int mt = 0; mt < 2; mt++)
#pragma unroll
            for (int half = 0; half < 2; half++) {
                int row = er + mt * 16 + half * 8;
                *(float2*)(outp + row * 128 + ec + nt * 8) =
                    make_float2(acc[mt][nt][half * 2], acc[mt][nt][half * 2 + 1]);
            }
}

// ============================================================
// Exclusive prefix over chunks (in-place)
// ============================================================
__global__ void scan_kv_kernel(float* __restrict__ kv)
{
    int gid = blockIdx.x * blockDim.x + threadIdx.x;
    int e = gid & 16383;
    int h = (gid >> 14) % HH;
    int b = gid / (16384 * HH);
    size_t idx = (((size_t)b * NCH) * HH + h) * 16384 + e;
    const size_t stride = (size_t)HH * 16384;
    float acc = 0.f;
#pragma unroll 4
    for (int n = 0; n < NCH; n++) {
        float x = kv[idx];
        kv[idx] = acc;
        acc += x;
        idx += stride;
    }
}

// ============================================================
// chunk_out_mma: A = tril(q k^T); o = A.v + q.S; RMSNorm; os hi out.
// ============================================================
#define CO_QS   0
#define CO_AP   33792
#define CO_VP   51200
#define CO_SP   86016
#define CO_SMEM (86016 + 256*136*2)   // 155648

__global__ __launch_bounds__(256) void chunk_out_mma(
    const float* __restrict__ q, const float* __restrict__ k,
    const float* __restrict__ v, const float* __restrict__ kvS,
    const float* __restrict__ rms_w, __half* __restrict__ os)
{
    extern __shared__ __align__(16) char sm[];
    __half* qS = (__half*)(sm + CO_QS);
    __half* Ap = (__half*)(sm + CO_AP);
    __half* vP = (__half*)(sm + CO_VP);
    __half* sP = (__half*)(sm + CO_SP);
    __half* kSm = (__half*)(sm + CO_SP);
    float* oS = (float*)(sm + CO_SP);
    const uint32_t qB = smem_u32(qS);
    const uint32_t aB = smem_u32(Ap);
    const uint32_t vB = smem_u32(vP);
    const uint32_t sB = smem_u32(sP);
    const uint32_t kB2 = sB;

    const int bid = blockIdx.x;
    const int h = bid % HH, n = (bid / HH) % NCH, b = bid / (HH * NCH);
    const size_t base = (((size_t)b * TT + (size_t)n * CHUNK) * HH + h) * DKV;
    const int tid = threadIdx.x;
    const int lane = tid & 31;
    const int wid = tid >> 5;

    // ---- phase 1: load q, k -> fp16 splits ----
    for (int off = tid * 4; off < 64 * 128; off += 1024) {
        int c = off >> 7, d = off & 127;
        float4 qq = *(const float4*)&q[base + (size_t)c * (HH * DKV) + d];
        float4 kk = *(const float4*)&k[base + (size_t)c * (HH * DKV) + d];
        __half2 qh0 = __floats2half2_rn(qq.x, qq.y);
        __half2 qh1 = __floats2half2_rn(qq.z, qq.w);
        __half2 ql0 = __floats2half2_rn(qq.x - __low2float(qh0), qq.y - __high2float(qh0));
        __half2 ql1 = __floats2half2_rn(qq.z - __low2float(qh1), qq.w - __high2float(qh1));
        __half2 kh0 = __floats2half2_rn(kk.x, kk.y);
        __half2 kh1 = __floats2half2_rn(kk.z, kk.w);
        __half2 kl0 = __floats2half2_rn(kk.x - __low2float(kh0), kk.y - __high2float(kh0));
        __half2 kl1 = __floats2half2_rn(kk.z - __low2float(kh1), kk.w - __high2float(kh1));
        *(__half2*)(qS + c * 264 + d)           = qh0;
        *(__half2*)(qS + c * 264 + d + 2)       = qh1;
        *(__half2*)(qS + c * 264 + 128 + d)     = ql0;
        *(__half2*)(qS + c * 264 + 128 + d + 2) = ql1;
        *(__half2*)(kSm + c * 264 + d)           = kh0;
        *(__half2*)(kSm + c * 264 + d + 2)       = kh1;
        *(__half2*)(kSm + c * 264 + 128 + d)     = kl0;
        *(__half2*)(kSm + c * 264 + 128 + d + 2) = kl1;
    }
    __syncthreads();

    const int krl = ((lane >> 4) << 3) + (lane & 7);
    const int mco = ((lane >> 3) & 1) << 3;

    // ---- phase 2: A = q.k^T ----
    {
        const int wmA = (wid & 1) * 32;
        const int wnA = (wid >> 1) * 16;
        float accA[2][2][4];
#pragma unroll
        for (int mt = 0; mt < 2; mt++)
#pragma unroll
            for (int nt = 0; nt < 2; nt++)
#pragma unroll
                for (int j = 0; j < 4; j++) accA[mt][nt][j] = 0.f;

#pragma unroll
        for (int kc = 0; kc < 24; kc++) {
            const int t = kc >> 3;
            const int cb = (kc & 7) << 4;
            const int qc = ((t == 1) ? 128 : 0) + cb;
            const int kc2 = ((t == 2) ? 128 : 0) + cb;
            uint32_t a[2][4], bf[4];
#pragma unroll
            for (int mt = 0; mt < 2; mt++) {
                uint32_t ad = qB + (uint32_t)(((wmA + mt * 16 + (lane & 15)) * 264
                                               + qc + ((lane >> 4) << 3)) * 2);
                LDSM(a[mt][0], a[mt][1], a[mt][2], a[mt][3], ad);
            }
            uint32_t bd = kB2 + (uint32_t)(((wnA + (lane & 15)) * 264
                                            + kc2 + ((lane >> 4) << 3)) * 2);
            LDSM(bf[0], bf[1], bf[2], bf[3], bd);
#pragma unroll
            for (int mt = 0; mt < 2; mt++)
#pragma unroll
                for (int nt = 0; nt < 2; nt++)
                    MMA16816(accA[mt][nt], a[mt][0], a[mt][1], a[mt][2], a[mt][3],
                             bf[nt], bf[nt + 2]);
        }

        const int er = wmA + (lane >> 2);
        const int ec = wnA + (lane & 3) * 2;
#pragma unroll
        for (int mt = 0; mt < 2; mt++)
#pragma unroll
            for (int nt = 0; nt < 2; nt++)
#pragma unroll
                for (int half = 0; half < 2; half++) {
                    int r = er + mt * 16 + half * 8;
                    int c = ec + nt * 8;
                    float v0 = (c     <= r) ? accA[mt][nt][half * 2 + 0] : 0.f;
                    float v1 = (c + 1 <= r) ? accA[mt][nt][half * 2 + 1] : 0.f;
                    __half h0 = __float2half(v0);
                    __half h1 = __float2half(v1);
                    __half2 hv; hv.x = h0; hv.y = h1;
                    __half2 lv;
                    lv.x = __float2half(v0 - __half2float(h0));
                    lv.y = __float2half(v1 - __half2float(h1));
                    *(__half2*)(Ap + r * 136 + c)      = hv;
                    *(__half2*)(Ap + r * 136 + 64 + c) = lv;
                }
    }
    __syncthreads();

    // ---- phase 3: load v, S -> fp16 splits ----
    for (int off = tid * 4; off < 64 * 128; off += 1024) {
        int c = off >> 7, d = off & 127;
        float4 vv = *(const float4*)&v[base + (size_t)c * (HH * DKV) + d];
        __half2 vh0 = __floats2half2_rn(vv.x, vv.y);
        __half2 vh1 = __floats2half2_rn(vv.z, vv.w);
        __half2 vl0 = __floats2half2_rn(vv.x - __low2float(vh0), vv.y - __high2float(vh0));
        __half2 vl1 = __floats2half2_rn(vv.z - __low2float(vh1), vv.w - __high2float(vh1));
        *(__half2*)(vP + c * 136 + d)            = vh0;
        *(__half2*)(vP + c * 136 + d + 2)        = vh1;
        *(__half2*)(vP + (c + 64) * 136 + d)     = vl0;
        *(__half2*)(vP + (c + 64) * 136 + d + 2) = vl1;
    }
    {
        const float* Sg = kvS + (size_t)bid * (DKV * DKV);
        for (int off = tid * 4; off < 128 * 128; off += 1024) {
            int dr = off >> 7, dv = off & 127;
            float4 ss = *(const float4*)&Sg[dr * 128 + dv];
            __half2 sh0 = __floats2half2_rn(ss.x, ss.y);
            __half2 sh1 = __floats2half2_rn(ss.z, ss.w);
            __half2 sl0 = __floats2half2_rn(ss.x - __low2float(sh0), ss.y - __high2float(sh0));
            __half2 sl1 = __floats2half2_rn(ss.z - __low2float(sh1), ss.w - __high2float(sh1));
            *(__half2*)(sP + dr * 136 + dv)             = sh0;
            *(__half2*)(sP + dr * 136 + dv + 2)         = sh1;
            *(__half2*)(sP + (dr + 128) * 136 + dv)     = sl0;
            *(__half2*)(sP + (dr + 128) * 136 + dv + 2) = sl1;
        }
    }
    __syncthreads();

    // ---- phase 4: o = A'.v' + q.S' ----
    const int warp_m = (wid & 1) * 32;
    const int warp_n = (wid >> 1) * 32;
    float acc[2][4][4];
#pragma unroll
    for (int mt = 0; mt < 2; mt++)
#pragma unroll
        for (int nt = 0; nt < 4; nt++)
#pragma unroll
            for (int j = 0; j < 4; j++) acc[mt][nt][j] = 0.f;

#pragma unroll
    for (int kc = 0; kc < 12; kc++) {
        const int t = kc >> 2;
        const int cb = (kc & 3) << 4;
        const int ac = ((t == 1) ? 64 : 0) + cb;
        const int br = ((t == 2) ? 64 : 0) + cb;
        uint32_t a[2][4], bf[2][4];
#pragma unroll
        for (int mt = 0; mt < 2; mt++) {
            uint32_t ad = aB + (uint32_t)(((warp_m + mt * 16 + (lane & 15)) * 136
                                           + ac + ((lane >> 4) << 3)) * 2);
            LDSM(a[mt][0], a[mt][1], a[mt][2], a[mt][3], ad);
        }
#pragma unroll
        for (int ng = 0; ng < 2; ng++) {
            uint32_t bd = vB + (uint32_t)(((br + krl) * 136 + warp_n + ng * 16 + mco) * 2);
            LDSM_T(bf[ng][0], bf[ng][1], bf[ng][2], bf[ng][3], bd);
        }
#pragma unroll
        for (int mt = 0; mt < 2; mt++)
#pragma unroll
            for (int nt = 0; nt < 4; nt++) {
                const int g = nt >> 1, sel = nt & 1;
                MMA16816(acc[mt][nt], a[mt][0], a[mt][1], a[mt][2], a[mt][3],
                         bf[g][sel], bf[g][sel + 2]);
            }
    }
#pragma unroll
    for (int kc = 0; kc < 24; kc++) {
        const int t = kc >> 3;
        const int cb = (kc & 7) << 4;
        const int qc = ((t == 1) ? 128 : 0) + cb;
        const int sr = ((t == 2) ? 128 : 0) + cb;
        uint32_t a[2][4], bf[2][4];
#pragma unroll
        for (int mt = 0; mt < 2; mt++) {
            uint32_t ad = qB + (uint32_t)(((warp_m + mt * 16 + (lane & 15)) * 264
                                           + qc + ((lane >> 4) << 3)) * 2);
            LDSM(a[mt][0], a[mt][1], a[mt][2], a[mt][3], ad);
        }
#pragma unroll
        for (int ng = 0; ng < 2; ng++) {
            uint32_t bd = sB + (uint32_t)(((sr + krl) * 136 + warp_n + ng * 16 + mco) * 2);
            LDSM_T(bf[ng][0], bf[ng][1], bf[ng][2], bf[ng][3], bd);
        }
#pragma unroll
        for (int mt = 0; mt < 2; mt++)
#pragma unroll
            for (int nt = 0; nt < 4; nt++) {
                const int g = nt >> 1, sel = nt & 1;
                MMA16816(acc[mt][nt], a[mt][0], a[mt][1], a[mt][2], a[mt][3],
                         bf[g][sel], bf[g][sel + 2]);
            }
    }

    // ---- phase 5: stage o to smem fp32 ----
    __syncthreads();
    {
        const int er = warp_m + (lane >> 2);
        const int ec = warp_n + (lane & 3) * 2;
#pragma unroll
        for (int mt = 0; mt < 2; mt++)
#pragma unroll
            for (int nt = 0; nt < 4; nt++)
#pragma unroll
                for (int half = 0; half < 2; half++) {
                    int r = er + mt * 16 + half * 8;
                    *(float2*)(oS + r * 132 + ec + nt * 8) =
                        make_float2(acc[mt][nt][half * 2], acc[mt][nt][half * 2 + 1]);
                }
    }
    __syncthreads();

    // ---- phase 6: RMSNorm + fp16 hi write to os ----
    {
        const int r = tid >> 2;
        const int part = tid & 3;
        float vals[32];
        float s = 0.f;
#pragma unroll
        for (int j = 0; j < 32; j += 4) {
            float4 x = *(const float4*)(oS + r * 132 + part * 32 + j);
            vals[j] = x.x; vals[j+1] = x.y; vals[j+2] = x.z; vals[j+3] = x.w;
            s += x.x*x.x + x.y*x.y + x.z*x.z + x.w*x.w;
        }
        s += __shfl_xor_sync(0xffffffffu, s, 1);
        s += __shfl_xor_sync(0xffffffffu, s, 2);
        float scale = rsqrtf(s * (1.0f / 128.0f) + EPS);
        size_t R = (size_t)b * TT + (size_t)n * CHUNK + r;
        __half* p = os + R * 2048 + h * 128 + part * 32;
#pragma unroll
        for (int j = 0; j < 32; j += 2) {
            float vx = vals[j]   * scale * rms_w[part * 32 + j];
            float vy = vals[j+1] * scale * rms_w[part * 32 + j + 1];
            __half2 hv;
            hv.x = __float2half(vx);
            hv.y = __float2half(vy);
            *(__half2*)(p + j) = hv;
        }
    }
}

// ============================================================
// Launch
// ============================================================
extern "C" void kernel_launch(void* const* d_in, const int* in_sizes, int n_in,
                              void* d_out, int out_size)
{
    const float* x      = (const float*)d_in[0];
    const float* Wq     = (const float*)d_in[1];
    const float* Wk     = (const float*)d_in[2];
    const float* Wv     = (const float*)d_in[3];
    const float* fmq_w1 = (const float*)d_in[4];
    const float* fmq_b1 = (const float*)d_in[5];
    const float* fmq_w2 = (const float*)d_in[6];
    const float* fmq_b2 = (const float*)d_in[7];
    const float* fmk_w1 = (const float*)d_in[8];
    const float* fmk_b1 = (const float*)d_in[9];
    const float* fmk_w2 = (const float*)d_in[10];
    const float* fmk_b2 = (const float*)d_in[11];
    const float* rms_w  = (const float*)d_in[12];
    const float* Wo     = (const float*)d_in[13];
    float* out = (float*)d_out;

    float *bQ, *bK, *bV, *bKV;
    cudaGetSymbolAddress((void**)&bQ, g_bufQ);
    cudaGetSymbolAddress((void**)&bK, g_bufK);
    cudaGetSymbolAddress((void**)&bV, g_bufV);
    cudaGetSymbolAddress((void**)&bKV, g_kv);

    __half *xs, *ws, *wv16, *wo16, *q1s, *k1s, *os, *fmwI;
    float* fmbI;
    cudaGetSymbolAddress((void**)&xs,  g_xs);
    cudaGetSymbolAddress((void**)&ws,  g_ws);
    cudaGetSymbolAddress((void**)&wv16, g_wv16);
    cudaGetSymbolAddress((void**)&wo16, g_wo16);
    cudaGetSymbolAddress((void**)&q1s, g_q1s);
    cudaGetSymbolAddress((void**)&k1s, g_k1s);
    cudaGetSymbolAddress((void**)&os,  g_os);
    cudaGetSymbolAddress((void**)&fmwI, g_fmwI);
    cudaGetSymbolAddress((void**)&fmbI, g_fmbI);

    cudaFuncSetAttribute(chunk_kv_mma,  cudaFuncAttributeMaxDynamicSharedMemorySize, KV_SMEM);
    cudaFuncSetAttribute(chunk_out_mma, cudaFuncAttributeMaxDynamicSharedMemorySize, CO_SMEM);
    cudaFuncSetAttribute(mma_gemm_kernel<0>, cudaFuncAttributeMaxDynamicSharedMemorySize, GEMM_SMEM);
    cudaFuncSetAttribute(mma_gemm_kernel<2>, cudaFuncAttributeMaxDynamicSharedMemorySize, GEMM_SMEM);
    cudaFuncSetAttribute(mma_gemm_kernel<3>, cudaFuncAttributeMaxDynamicSharedMemorySize, GEMM_SMEM);

    const size_t wsz = (size_t)HID * K2BIG;

    // ---- splits / converts ----
    split2_kernel<<<(MROWS * HID) / 512, 256>>>(x, xs, 10, (size_t)MROWS * HID, 0);
    split2_kernel<<<(HID * HID) / 512, 256>>>(Wq, ws + 0 * wsz, 10, (size_t)HID * HID, 1);
    split2_kernel<<<(HID * HID) / 512, 256>>>(Wk, ws + 1 * wsz, 10, (size_t)HID * HID, 1);
    tof16_kernel<<<(HID * HID) / 512, 256>>>(Wv, wv16, (size_t)HID * HID);
    tof16_kernel<<<(HID * HID) / 512, 256>>>(Wo, wo16, (size_t)HID * HID);

    // ---- projections ----
    dim3 gBig(HID / 128, MROWS / 128);
    mma_gemm_kernel<2><<<gBig, 256, GEMM_SMEM>>>(xs, ws + 0 * wsz, nullptr, nullptr, q1s, 0.f, HID, K2BIG, K2BIG);
    mma_gemm_kernel<2><<<gBig, 256, GEMM_SMEM>>>(xs, ws + 1 * wsz, nullptr, nullptr, k1s, 0.f, HID, K2BIG, K2BIG);
    mma_gemm_kernel<0><<<gBig, 256, GEMM_SMEM>>>(xs, wv16, nullptr, bV, nullptr, 0.f, HID, HID, K2BIG);

    // ---- fm weight interleave + fused fm GEMMs ----
    fm_interleave_kernel<<<128, 256>>>(fmq_w1, fmq_w2, fmq_b1, fmq_b2, fmwI, fmbI);
    fm_interleave_kernel<<<128, 256>>>(fmk_w1, fmk_w2, fmk_b1, fmk_b2,
                                       fmwI + (size_t)256 * K2FM, fmbI + 256);

    dim3 gFm(2, FMROWS / 128);
    const float scale = 0.08838834764831845f;
    mma_gemm_kernel<3><<<gFm, 256, GEMM_SMEM>>>(q1s, fmwI, fmbI, bQ, nullptr, scale, 256, K2FM, K2FM);
    mma_gemm_kernel<3><<<gFm, 256, GEMM_SMEM>>>(k1s, fmwI + (size_t)256 * K2FM, fmbI + 256,
                                                bK, nullptr, 1.0f, 256, K2FM, K2FM);

    // ---- chunked linear attention (HMMA) ----
    const int nBlk = BB * NCH * HH;
    chunk_kv_mma<<<nBlk, 256, KV_SMEM>>>(bK, bV, bKV);
    scan_kv_kernel<<<(BB * HH * 16384) / 256, 256>>>(bKV);
    chunk_out_mma<<<nBlk, 256, CO_SMEM>>>(bQ, bK, bV, bKV, rms_w, os);

    // ---- output projection (hi-only, K=1024) ----
    mma_gemm_kernel<0><<<gBig, 256, GEMM_SMEM>>>(os, wo16, nullptr, out, nullptr, 0.f, HID, HID, K2BIG);
}

// round 14
// speedup vs baseline: 2.8805x; 1.0270x over previous
#include <cuda_runtime.h>
#include <cuda_fp16.h>
#include <cstddef>
#include <cstdint>

// Problem constants
#define BB 2
#define TT 8192
#define HH 8
#define DKV 128
#define HID 1024
#define CHUNK 64
#define NCH 128           // TT / CHUNK
#define MROWS (BB*TT)     // 16384
#define FMROWS (BB*TT*HH) // 131072
#define EPS 1e-5f
#define K2BIG (2*HID)     // 2048

// -------- fp32 scratch --------
__device__ float g_bufQ[MROWS * HID];   // q after feature map
__device__ float g_bufK[MROWS * HID];   // k after feature map
__device__ float g_bufV[MROWS * HID];   // v projection
__device__ float g_kv[(size_t)BB * NCH * HH * DKV * DKV];

// -------- fp16 scratch --------
__device__ __half g_x16 [(size_t)MROWS * HID];        // x fp16
__device__ __half g_wv16[(size_t)HID * HID];          // Wv hi
__device__ __half g_wo16[(size_t)HID * HID];          // Wo hi
__device__ __half g_os [(size_t)MROWS * K2BIG];       // attention out (hi half used)
__device__ __half g_wcq[(size_t)2 * HID * HID];       // composite q weights [2048,1024]
__device__ __half g_wck[(size_t)2 * HID * HID];       // composite k weights
__device__ float  g_bcq[2 * HID];                     // composite q bias [2048]
__device__ float  g_bck[2 * HID];

__device__ __forceinline__ uint32_t smem_u32(const void* p) {
    uint32_t a;
    asm("{ .reg .u64 t; cvta.to.shared.u64 t, %1; cvt.u32.u64 %0, t; }"
        : "=r"(a) : "l"(p));
    return a;
}

#define LDSM(r0,r1,r2,r3,addr) \
    asm volatile("ldmatrix.sync.aligned.m8n8.x4.shared.b16 {%0,%1,%2,%3}, [%4];" \
                 : "=r"(r0),"=r"(r1),"=r"(r2),"=r"(r3) : "r"(addr))
#define LDSM_T(r0,r1,r2,r3,addr) \
    asm volatile("ldmatrix.sync.aligned.m8n8.x4.trans.shared.b16 {%0,%1,%2,%3}, [%4];" \
                 : "=r"(r0),"=r"(r1),"=r"(r2),"=r"(r3) : "r"(addr))
#define MMA16816(acc,a0,a1,a2,a3,b0,b1) \
    asm volatile("mma.sync.aligned.m16n8k16.row.col.f32.f16.f16.f32 " \
                 "{%0,%1,%2,%3}, {%4,%5,%6,%7}, {%8,%9}, {%0,%1,%2,%3};" \
                 : "+f"((acc)[0]), "+f"((acc)[1]), "+f"((acc)[2]), "+f"((acc)[3]) \
                 : "r"(a0), "r"(a1), "r"(a2), "r"(a3), "r"(b0), "r"(b1))

// ============================================================
// tof16: plain fp32 -> fp16 convert (packed)
// ============================================================
__global__ void tof16_kernel(const float* __restrict__ in,
                             __half* __restrict__ out, size_t total)
{
    size_t i = ((size_t)blockIdx.x * blockDim.x + threadIdx.x) * 2;
    if (i >= total) return;
    float2 x = *(const float2*)(in + i);
    __half2 hv;
    hv.x = __float2half(x.x);
    hv.y = __float2half(x.y);
    *(__half2*)(out + i) = hv;
}

// ============================================================
// composite_kernel: Wc[2*(h*128+j)+br, n] = sum_d w{br}[j,d]*Wp[h*128+d, n]
// grid (8 ntile, 4 rpg, 8 head), 256 threads. smem: Wqs[128][129] fp32.
// Also bc[rp] = b{br}[j].
// ============================================================
__global__ __launch_bounds__(256) void composite_kernel(
    const float* __restrict__ w1, const float* __restrict__ w2,
    const float* __restrict__ b1, const float* __restrict__ b2,
    const float* __restrict__ Wp,
    __half* __restrict__ Wc, float* __restrict__ bc)
{
    extern __shared__ float Wqs[];   // [128][129]
    const int nt = blockIdx.x;       // 0..7
    const int rpg = blockIdx.y;      // 0..3
    const int h = blockIdx.z;        // 0..7
    const int tid = threadIdx.x;

    for (int i = tid; i < 128 * 128; i += 256) {
        int d = i >> 7, c = i & 127;
        Wqs[d * 129 + c] = Wp[(size_t)(h * 128 + d) * 1024 + nt * 128 + c];
    }
    __syncthreads();

    const int rpl = rpg * 64 + (tid >> 2);  // 0..255 within head
    const int colg = tid & 3;
    const int j = rpl >> 1, br = rpl & 1;
    const float* w = br ? w2 : w1;

    float acc[32];
#pragma unroll
    for (int c = 0; c < 32; c++) acc[c] = 0.f;
    for (int d = 0; d < 128; d++) {
        float wv = w[j * 128 + d];
#pragma unroll
        for (int c = 0; c < 32; c++)
            acc[c] += wv * Wqs[d * 129 + colg + 4 * c];
    }

    const int rp = h * 256 + rpl;
    __half* o = Wc + (size_t)rp * 1024 + nt * 128 + colg;
#pragma unroll
    for (int c = 0; c < 32; c++)
        o[4 * c] = __float2half(acc[c]);
    if (nt == 0 && colg == 0)
        bc[rp] = (br ? b2 : b1)[j];
}

// ============================================================
// Tensor-core GEMM: C[M,N] = A[M,0:K] @ B[N,K]^T (+bias)
// EPI==0: C fp32 (+bias). EPI==3: hadamard pairs -> fp32 [., N/2].
// ============================================================
#define ASTAGE 10240
#define STAGEB 20480
#define NSTG 4
#define GEMM_SMEM (NSTG * STAGEB)

template<int EPI>
__global__ __launch_bounds__(256, 2) void mma_gemm_kernel(
    const __half* __restrict__ A,
    const __half* __restrict__ B,
    const float* __restrict__ bias,
    float* __restrict__ Cf,
    float mulscale,
    int N, int K, int ldA)
{
    extern __shared__ __align__(16) char dynsm[];
    const uint32_t sBase = smem_u32(dynsm);

    const int tid = threadIdx.x;
    const int lane = tid & 31;
    const int wid = tid >> 5;
    const int warp_m = (wid & 3) * 32;
    const int warp_n = (wid >> 2) * 64;
    const int bm0 = blockIdx.y * 128;
    const int bn0 = blockIdx.x * 128;
    const int NC = K >> 5;

    const size_t rowbA = (size_t)ldA * 2;
    const size_t rowbB = (size_t)K * 2;
    const char* Ag = (const char*)A + (size_t)bm0 * rowbA;
    const char* Bg = (const char*)B + (size_t)bn0 * rowbB;

    const int r0 = tid >> 2, g0 = tid & 3;
    const int r1 = (tid + 256) >> 2, g1 = (tid + 256) & 3;

    auto load_stage = [&](int kc, int s) {
        const size_t koff = (size_t)kc * 64;
        const uint32_t ab = sBase + (uint32_t)(s * STAGEB);
        const uint32_t bb = ab + ASTAGE;
        uint32_t sa0 = ab + (uint32_t)(r0 * 80 + g0 * 16);
        uint32_t sa1 = ab + (uint32_t)(r1 * 80 + g1 * 16);
        uint32_t sb0 = bb + (uint32_t)(r0 * 80 + g0 * 16);
        uint32_t sb1 = bb + (uint32_t)(r1 * 80 + g1 * 16);
        const void* ga0 = Ag + (size_t)r0 * rowbA + koff + g0 * 16;
        const void* ga1 = Ag + (size_t)r1 * rowbA + koff + g1 * 16;
        const void* gb0 = Bg + (size_t)r0 * rowbB + koff + g0 * 16;
        const void* gb1 = Bg + (size_t)r1 * rowbB + koff + g1 * 16;
        asm volatile("cp.async.cg.shared.global [%0], [%1], 16;" :: "r"(sa0), "l"(ga0));
        asm volatile("cp.async.cg.shared.global [%0], [%1], 16;" :: "r"(sa1), "l"(ga1));
        asm volatile("cp.async.cg.shared.global [%0], [%1], 16;" :: "r"(sb0), "l"(gb0));
        asm volatile("cp.async.cg.shared.global [%0], [%1], 16;" :: "r"(sb1), "l"(gb1));
        asm volatile("cp.async.commit_group;");
    };

    float acc[2][8][4];
#pragma unroll
    for (int mt = 0; mt < 2; mt++)
#pragma unroll
        for (int nt = 0; nt < 8; nt++)
#pragma unroll
            for (int j = 0; j < 4; j++) acc[mt][nt][j] = 0.f;

    load_stage(0, 0);
    load_stage(1, 1);
    load_stage(2, 2);

    const int lm = lane & 15;
    const int lk = lane >> 4;
    const uint32_t aOff = (uint32_t)((warp_m + lm) * 80 + lk * 16);
    const uint32_t bOff = (uint32_t)(ASTAGE + (warp_n + lm) * 80 + lk * 16);

    for (int kc = 0; kc < NC; kc++) {
        const int s = kc & (NSTG - 1);
        if (kc + 3 <= NC)      asm volatile("cp.async.wait_group 2;");
        else if (kc + 2 == NC) asm volatile("cp.async.wait_group 1;");
        else                   asm volatile("cp.async.wait_group 0;");
        __syncthreads();
        if (kc + 3 < NC) load_stage(kc + 3, (kc + 3) & (NSTG - 1));

        const uint32_t aSt = sBase + (uint32_t)(s * STAGEB) + aOff;
        const uint32_t bSt = sBase + (uint32_t)(s * STAGEB) + bOff;

#pragma unroll
        for (int ks = 0; ks < 2; ks++) {
            uint32_t a[2][4], bf[4][4];
#pragma unroll
            for (int mt = 0; mt < 2; mt++) {
                uint32_t ad = aSt + (uint32_t)(mt * 16 * 80 + ks * 32);
                LDSM(a[mt][0], a[mt][1], a[mt][2], a[mt][3], ad);
            }
#pragma unroll
            for (int ng = 0; ng < 4; ng++) {
                uint32_t bd = bSt + (uint32_t)(ng * 16 * 80 + ks * 32);
                LDSM(bf[ng][0], bf[ng][1], bf[ng][2], bf[ng][3], bd);
            }
#pragma unroll
            for (int mt = 0; mt < 2; mt++)
#pragma unroll
                for (int nt = 0; nt < 8; nt++) {
                    const int g = nt >> 1, sel = nt & 1;
                    MMA16816(acc[mt][nt], a[mt][0], a[mt][1], a[mt][2], a[mt][3],
                             bf[g][sel], bf[g][sel + 2]);
                }
        }
    }

    const int erow = bm0 + warp_m + (lane >> 2);
    const int ecol0 = bn0 + warp_n + (lane & 3) * 2;
#pragma unroll
    for (int nt = 0; nt < 8; nt++) {
        const int col = ecol0 + nt * 8;
        float bx = 0.f, by = 0.f;
        if (bias) { bx = bias[col]; by = bias[col + 1]; }
#pragma unroll
        for (int mt = 0; mt < 2; mt++) {
#pragma unroll
            for (int half = 0; half < 2; half++) {
                const int row = erow + mt * 16 + half * 8;
                float vx = acc[mt][nt][half * 2 + 0] + bx;
                float vy = acc[mt][nt][half * 2 + 1] + by;
                if (EPI == 0) {
                    *(float2*)(Cf + (size_t)row * N + col) = make_float2(vx, vy);
                } else {
                    // hadamard pairs: out col = col/2, out stride = N/2
                    Cf[(size_t)row * (N >> 1) + (col >> 1)] = vx * vy * mulscale;
                }
            }
        }
    }
}

// ============================================================
// chunk_kv_mma: kv = k_c^T @ v_c via fp16 HMMA, 3-product split.
// ============================================================
#define KV_SMEM (2 * 128 * 136 * 2)   // 69632

__global__ __launch_bounds__(256) void chunk_kv_mma(
    const float* __restrict__ k, const float* __restrict__ v,
    float* __restrict__ kv)
{
    extern __shared__ __align__(16) char sm[];
    __half* kS = (__half*)sm;
    __half* vS = (__half*)(sm + 128*136*2);
    const uint32_t kB = smem_u32(kS);
    const uint32_t vB = smem_u32(vS);

    const int bid = blockIdx.x;
    const int h = bid % HH, n = (bid / HH) % NCH, b = bid / (HH * NCH);
    const size_t base = (((size_t)b * TT + (size_t)n * CHUNK) * HH + h) * DKV;
    const int tid = threadIdx.x;
    const int lane = tid & 31;
    const int wid = tid >> 5;

    for (int off = tid * 4; off < 64 * 128; off += 1024) {
        int c = off >> 7, d = off & 127;
        float4 kk = *(const float4*)&k[base + (size_t)c * (HH * DKV) + d];
        float4 vv = *(const float4*)&v[base + (size_t)c * (HH * DKV) + d];
        __half2 kh0 = __floats2half2_rn(kk.x, kk.y);
        __half2 kh1 = __floats2half2_rn(kk.z, kk.w);
        __half2 kl0 = __floats2half2_rn(kk.x - __low2float(kh0),  kk.y - __high2float(kh0));
        __half2 kl1 = __floats2half2_rn(kk.z - __low2float(kh1),  kk.w - __high2float(kh1));
        __half2 vh0 = __floats2half2_rn(vv.x, vv.y);
        __half2 vh1 = __floats2half2_rn(vv.z, vv.w);
        __half2 vl0 = __floats2half2_rn(vv.x - __low2float(vh0),  vv.y - __high2float(vh0));
        __half2 vl1 = __floats2half2_rn(vv.z - __low2float(vh1),  vv.w - __high2float(vh1));
        *(__half2*)(kS + c * 136 + d)            = kh0;
        *(__half2*)(kS + c * 136 + d + 2)        = kh1;
        *(__half2*)(kS + (c + 64) * 136 + d)     = kl0;
        *(__half2*)(kS + (c + 64) * 136 + d + 2) = kl1;
        *(__half2*)(vS + c * 136 + d)            = vh0;
        *(__half2*)(vS + c * 136 + d + 2)        = vh1;
        *(__half2*)(vS + (c + 64) * 136 + d)     = vl0;
        *(__half2*)(vS + (c + 64) * 136 + d + 2) = vl1;
    }
    __syncthreads();

    const int warp_m = (wid & 3) * 32;
    const int warp_n = (wid >> 2) * 64;
    const int krl = ((lane >> 4) << 3) + (lane & 7);
    const int mco = ((lane >> 3) & 1) << 3;

    float acc[2][8][4];
#pragma unroll
    for (int mt = 0; mt < 2; mt++)
#pragma unroll
        for (int nt = 0; nt < 8; nt++)
#pragma unroll
            for (int j = 0; j < 4; j++) acc[mt][nt][j] = 0.f;

#pragma unroll
    for (int kc = 0; kc < 12; kc++) {
        const int t = kc >> 2;
        const int cb = (kc & 3) << 4;
        const int ar = ((t == 1) ? 64 : 0) + cb;
        const int br = ((t == 2) ? 64 : 0) + cb;
        uint32_t a[2][4], bf[4][4];
#pragma unroll
        for (int mt = 0; mt < 2; mt++) {
            uint32_t ad = kB + (uint32_t)(((ar + krl) * 136 + warp_m + mt * 16 + mco) * 2);
            LDSM_T(a[mt][0], a[mt][1], a[mt][2], a[mt][3], ad);
        }
#pragma unroll
        for (int ng = 0; ng < 4; ng++) {
            uint32_t bd = vB + (uint32_t)(((br + krl) * 136 + warp_n + ng * 16 + mco) * 2);
            LDSM_T(bf[ng][0], bf[ng][1], bf[ng][2], bf[ng][3], bd);
        }
#pragma unroll
        for (int mt = 0; mt < 2; mt++)
#pragma unroll
            for (int nt = 0; nt < 8; nt++) {
                const int g = nt >> 1, sel = nt & 1;
                MMA16816(acc[mt][nt], a[mt][0], a[mt][1], a[mt][2], a[mt][3],
                         bf[g][sel], bf[g][sel + 2]);
            }
    }

    float* outp = kv + (size_t)bid * (DKV * DKV);
    const int er = warp_m + (lane >> 2);
    const int ec = warp_n + (lane & 3) * 2;
#pragma unroll
    for (int nt = 0; nt < 8; nt++)
#pragma unroll
        for (int mt = 0; mt < 2; mt++)
#pragma unroll
            for (int half = 0; half < 2; half++) {
                int row = er + mt * 16 + half * 8;
                *(float2*)(outp + row * 128 + ec + nt * 8) =
                    make_float2(acc[mt][nt][half * 2], acc[mt][nt][half * 2 + 1]);
            }
}

// ============================================================
// Exclusive prefix over chunks (in-place)
// ============================================================
__global__ void scan_kv_kernel(float* __restrict__ kv)
{
    int gid = blockIdx.x * blockDim.x + threadIdx.x;
    int e = gid & 16383;
    int h = (gid >> 14) % HH;
    int b = gid / (16384 * HH);
    size_t idx = (((size_t)b * NCH) * HH + h) * 16384 + e;
    const size_t stride = (size_t)HH * 16384;
    float acc = 0.f;
#pragma unroll 4
    for (int n = 0; n < NCH; n++) {
        float x = kv[idx];
        kv[idx] = acc;
        acc += x;
        idx += stride;
    }
}

// ============================================================
// chunk_out_mma: A = tril(q k^T); o = A.v + q.S; RMSNorm; os hi out.
// ============================================================
#define CO_QS   0
#define CO_AP   33792
#define CO_VP   51200
#define CO_SP   86016
#define CO_SMEM (86016 + 256*136*2)   // 155648

__global__ __launch_bounds__(256) void chunk_out_mma(
    const float* __restrict__ q, const float* __restrict__ k,
    const float* __restrict__ v, const float* __restrict__ kvS,
    const float* __restrict__ rms_w, __half* __restrict__ os)
{
    extern __shared__ __align__(16) char sm[];
    __half* qS = (__half*)(sm + CO_QS);
    __half* Ap = (__half*)(sm + CO_AP);
    __half* vP = (__half*)(sm + CO_VP);
    __half* sP = (__half*)(sm + CO_SP);
    __half* kSm = (__half*)(sm + CO_SP);
    float* oS = (float*)(sm + CO_SP);
    const uint32_t qB = smem_u32(qS);
    const uint32_t aB = smem_u32(Ap);
    const uint32_t vB = smem_u32(vP);
    const uint32_t sB = smem_u32(sP);
    const uint32_t kB2 = sB;

    const int bid = blockIdx.x;
    const int h = bid % HH, n = (bid / HH) % NCH, b = bid / (HH * NCH);
    const size_t base = (((size_t)b * TT + (size_t)n * CHUNK) * HH + h) * DKV;
    const int tid = threadIdx.x;
    const int lane = tid & 31;
    const int wid = tid >> 5;

    // ---- phase 1: load q, k -> fp16 splits ----
    for (int off = tid * 4; off < 64 * 128; off += 1024) {
        int c = off >> 7, d = off & 127;
        float4 qq = *(const float4*)&q[base + (size_t)c * (HH * DKV) + d];
        float4 kk = *(const float4*)&k[base + (size_t)c * (HH * DKV) + d];
        __half2 qh0 = __floats2half2_rn(qq.x, qq.y);
        __half2 qh1 = __floats2half2_rn(qq.z, qq.w);
        __half2 ql0 = __floats2half2_rn(qq.x - __low2float(qh0), qq.y - __high2float(qh0));
        __half2 ql1 = __floats2half2_rn(qq.z - __low2float(qh1), qq.w - __high2float(qh1));
        __half2 kh0 = __floats2half2_rn(kk.x, kk.y);
        __half2 kh1 = __floats2half2_rn(kk.z, kk.w);
        __half2 kl0 = __floats2half2_rn(kk.x - __low2float(kh0), kk.y - __high2float(kh0));
        __half2 kl1 = __floats2half2_rn(kk.z - __low2float(kh1), kk.w - __high2float(kh1));
        *(__half2*)(qS + c * 264 + d)           = qh0;
        *(__half2*)(qS + c * 264 + d + 2)       = qh1;
        *(__half2*)(qS + c * 264 + 128 + d)     = ql0;
        *(__half2*)(qS + c * 264 + 128 + d + 2) = ql1;
        *(__half2*)(kSm + c * 264 + d)           = kh0;
        *(__half2*)(kSm + c * 264 + d + 2)       = kh1;
        *(__half2*)(kSm + c * 264 + 128 + d)     = kl0;
        *(__half2*)(kSm + c * 264 + 128 + d + 2) = kl1;
    }
    __syncthreads();

    const int krl = ((lane >> 4) << 3) + (lane & 7);
    const int mco = ((lane >> 3) & 1) << 3;

    // ---- phase 2: A = q.k^T ----
    {
        const int wmA = (wid & 1) * 32;
        const int wnA = (wid >> 1) * 16;
        float accA[2][2][4];
#pragma unroll
        for (int mt = 0; mt < 2; mt++)
#pragma unroll
            for (int nt = 0; nt < 2; nt++)
#pragma unroll
                for (int j = 0; j < 4; j++) accA[mt][nt][j] = 0.f;

#pragma unroll
        for (int kc = 0; kc < 24; kc++) {
            const int t = kc >> 3;
            const int cb = (kc & 7) << 4;
            const int qc = ((t == 1) ? 128 : 0) + cb;
            const int kc2 = ((t == 2) ? 128 : 0) + cb;
            uint32_t a[2][4], bf[4];
#pragma unroll
            for (int mt = 0; mt < 2; mt++) {
                uint32_t ad = qB + (uint32_t)(((wmA + mt * 16 + (lane & 15)) * 264
                                               + qc + ((lane >> 4) << 3)) * 2);
                LDSM(a[mt][0], a[mt][1], a[mt][2], a[mt][3], ad);
            }
            uint32_t bd = kB2 + (uint32_t)(((wnA + (lane & 15)) * 264
                                            + kc2 + ((lane >> 4) << 3)) * 2);
            LDSM(bf[0], bf[1], bf[2], bf[3], bd);
#pragma unroll
            for (int mt = 0; mt < 2; mt++)
#pragma unroll
                for (int nt = 0; nt < 2; nt++)
                    MMA16816(accA[mt][nt], a[mt][0], a[mt][1], a[mt][2], a[mt][3],
                             bf[nt], bf[nt + 2]);
        }

        const int er = wmA + (lane >> 2);
        const int ec = wnA + (lane & 3) * 2;
#pragma unroll
        for (int mt = 0; mt < 2; mt++)
#pragma unroll
            for (int nt = 0; nt < 2; nt++)
#pragma unroll
                for (int half = 0; half < 2; half++) {
                    int r = er + mt * 16 + half * 8;
                    int c = ec + nt * 8;
                    float v0 = (c     <= r) ? accA[mt][nt][half * 2 + 0] : 0.f;
                    float v1 = (c + 1 <= r) ? accA[mt][nt][half * 2 + 1] : 0.f;
                    __half h0 = __float2half(v0);
                    __half h1 = __float2half(v1);
                    __half2 hv; hv.x = h0; hv.y = h1;
                    __half2 lv;
                    lv.x = __float2half(v0 - __half2float(h0));
                    lv.y = __float2half(v1 - __half2float(h1));
                    *(__half2*)(Ap + r * 136 + c)      = hv;
                    *(__half2*)(Ap + r * 136 + 64 + c) = lv;
                }
    }
    __syncthreads();

    // ---- phase 3: load v, S -> fp16 splits ----
    for (int off = tid * 4; off < 64 * 128; off += 1024) {
        int c = off >> 7, d = off & 127;
        float4 vv = *(const float4*)&v[base + (size_t)c * (HH * DKV) + d];
        __half2 vh0 = __floats2half2_rn(vv.x, vv.y);
        __half2 vh1 = __floats2half2_rn(vv.z, vv.w);
        __half2 vl0 = __floats2half2_rn(vv.x - __low2float(vh0), vv.y - __high2float(vh0));
        __half2 vl1 = __floats2half2_rn(vv.z - __low2float(vh1), vv.w - __high2float(vh1));
        *(__half2*)(vP + c * 136 + d)            = vh0;
        *(__half2*)(vP + c * 136 + d + 2)        = vh1;
        *(__half2*)(vP + (c + 64) * 136 + d)     = vl0;
        *(__half2*)(vP + (c + 64) * 136 + d + 2) = vl1;
    }
    {
        const float* Sg = kvS + (size_t)bid * (DKV * DKV);
        for (int off = tid * 4; off < 128 * 128; off += 1024) {
            int dr = off >> 7, dv = off & 127;
            float4 ss = *(const float4*)&Sg[dr * 128 + dv];
            __half2 sh0 = __floats2half2_rn(ss.x, ss.y);
            __half2 sh1 = __floats2half2_rn(ss.z, ss.w);
            __half2 sl0 = __floats2half2_rn(ss.x - __low2float(sh0), ss.y - __high2float(sh0));
            __half2 sl1 = __floats2half2_rn(ss.z - __low2float(sh1), ss.w - __high2float(sh1));
            *(__half2*)(sP + dr * 136 + dv)             = sh0;
            *(__half2*)(sP + dr * 136 + dv + 2)         = sh1;
            *(__half2*)(sP + (dr + 128) * 136 + dv)     = sl0;
            *(__half2*)(sP + (dr + 128) * 136 + dv + 2) = sl1;
        }
    }
    __syncthreads();

    // ---- phase 4: o = A'.v' + q.S' ----
    const int warp_m = (wid & 1) * 32;
    const int warp_n = (wid >> 1) * 32;
    float acc[2][4][4];
#pragma unroll
    for (int mt = 0; mt < 2; mt++)
#pragma unroll
        for (int nt = 0; nt < 4; nt++)
#pragma unroll
            for (int j = 0; j < 4; j++) acc[mt][nt][j] = 0.f;

#pragma unroll
    for (int kc = 0; kc < 12; kc++) {
        const int t = kc >> 2;
        const int cb = (kc & 3) << 4;
        const int ac = ((t == 1) ? 64 : 0) + cb;
        const int br = ((t == 2) ? 64 : 0) + cb;
        uint32_t a[2][4], bf[2][4];
#pragma unroll
        for (int mt = 0; mt < 2; mt++) {
            uint32_t ad = aB + (uint32_t)(((warp_m + mt * 16 + (lane & 15)) * 136
                                           + ac + ((lane >> 4) << 3)) * 2);
            LDSM(a[mt][0], a[mt][1], a[mt][2], a[mt][3], ad);
        }
#pragma unroll
        for (int ng = 0; ng < 2; ng++) {
            uint32_t bd = vB + (uint32_t)(((br + krl) * 136 + warp_n + ng * 16 + mco) * 2);
            LDSM_T(bf[ng][0], bf[ng][1], bf[ng][2], bf[ng][3], bd);
        }
#pragma unroll
        for (int mt = 0; mt < 2; mt++)
#pragma unroll
            for (int nt = 0; nt < 4; nt++) {
                const int g = nt >> 1, sel = nt & 1;
                MMA16816(acc[mt][nt], a[mt][0], a[mt][1], a[mt][2], a[mt][3],
                         bf[g][sel], bf[g][sel + 2]);
            }
    }
#pragma unroll
    for (int kc = 0; kc < 24; kc++) {
        const int t = kc >> 3;
        const int cb = (kc & 7) << 4;
        const int qc = ((t == 1) ? 128 : 0) + cb;
        const int sr = ((t == 2) ? 128 : 0) + cb;
        uint32_t a[2][4], bf[2][4];
#pragma unroll
        for (int mt = 0; mt < 2; mt++) {
            uint32_t ad = qB + (uint32_t)(((warp_m + mt * 16 + (lane & 15)) * 264
                                           + qc + ((lane >> 4) << 3)) * 2);
            LDSM(a[mt][0], a[mt][1], a[mt][2], a[mt][3], ad);
        }
#pragma unroll
        for (int ng = 0; ng < 2; ng++) {
            uint32_t bd = sB + (uint32_t)(((sr + krl) * 136 + warp_n + ng * 16 + mco) * 2);
            LDSM_T(bf[ng][0], bf[ng][1], bf[ng][2], bf[ng][3], bd);
        }
#pragma unroll
        for (int mt = 0; mt < 2; mt++)
#pragma unroll
            for (int nt = 0; nt < 4; nt++) {
                const int g = nt >> 1, sel = nt & 1;
                MMA16816(acc[mt][nt], a[mt][0], a[mt][1], a[mt][2], a[mt][3],
                         bf[g][sel], bf[g][sel + 2]);
            }
    }

    // ---- phase 5: stage o to smem fp32 ----
    __syncthreads();
    {
        const int er = warp_m + (lane >> 2);
        const int ec = warp_n + (lane & 3) * 2;
#pragma unroll
        for (int mt = 0; mt < 2; mt++)
#pragma unroll
            for (int nt = 0; nt < 4; nt++)
#pragma unroll
                for (int half = 0; half < 2; half++) {
                    int r = er + mt * 16 + half * 8;
                    *(float2*)(oS + r * 132 + ec + nt * 8) =
                        make_float2(acc[mt][nt][half * 2], acc[mt][nt][half * 2 + 1]);
                }
    }
    __syncthreads();

    // ---- phase 6: RMSNorm + fp16 hi write to os ----
    {
        const int r = tid >> 2;
        const int part = tid & 3;
        float vals[32];
        float s = 0.f;
#pragma unroll
        for (int j = 0; j < 32; j += 4) {
            float4 x = *(const float4*)(oS + r * 132 + part * 32 + j);
            vals[j] = x.x; vals[j+1] = x.y; vals[j+2] = x.z; vals[j+3] = x.w;
            s += x.x*x.x + x.y*x.y + x.z*x.z + x.w*x.w;
        }
        s += __shfl_xor_sync(0xffffffffu, s, 1);
        s += __shfl_xor_sync(0xffffffffu, s, 2);
        float scale = rsqrtf(s * (1.0f / 128.0f) + EPS);
        size_t R = (size_t)b * TT + (size_t)n * CHUNK + r;
        __half* p = os + R * 2048 + h * 128 + part * 32;
#pragma unroll
        for (int j = 0; j < 32; j += 2) {
            float vx = vals[j]   * scale * rms_w[part * 32 + j];
            float vy = vals[j+1] * scale * rms_w[part * 32 + j + 1];
            __half2 hv;
            hv.x = __float2half(vx);
            hv.y = __float2half(vy);
            *(__half2*)(p + j) = hv;
        }
    }
}

// ============================================================
// Launch
// ============================================================
extern "C" void kernel_launch(void* const* d_in, const int* in_sizes, int n_in,
                              void* d_out, int out_size)
{
    const float* x      = (const float*)d_in[0];
    const float* Wq     = (const float*)d_in[1];
    const float* Wk     = (const float*)d_in[2];
    const float* Wv     = (const float*)d_in[3];
    const float* fmq_w1 = (const float*)d_in[4];
    const float* fmq_b1 = (const float*)d_in[5];
    const float* fmq_w2 = (const float*)d_in[6];
    const float* fmq_b2 = (const float*)d_in[7];
    const float* fmk_w1 = (const float*)d_in[8];
    const float* fmk_b1 = (const float*)d_in[9];
    const float* fmk_w2 = (const float*)d_in[10];
    const float* fmk_b2 = (const float*)d_in[11];
    const float* rms_w  = (const float*)d_in[12];
    const float* Wo     = (const float*)d_in[13];
    float* out = (float*)d_out;

    float *bQ, *bK, *bV, *bKV, *bcq, *bck;
    cudaGetSymbolAddress((void**)&bQ, g_bufQ);
    cudaGetSymbolAddress((void**)&bK, g_bufK);
    cudaGetSymbolAddress((void**)&bV, g_bufV);
    cudaGetSymbolAddress((void**)&bKV, g_kv);
    cudaGetSymbolAddress((void**)&bcq, g_bcq);
    cudaGetSymbolAddress((void**)&bck, g_bck);

    __half *x16, *wv16, *wo16, *os, *wcq, *wck;
    cudaGetSymbolAddress((void**)&x16,  g_x16);
    cudaGetSymbolAddress((void**)&wv16, g_wv16);
    cudaGetSymbolAddress((void**)&wo16, g_wo16);
    cudaGetSymbolAddress((void**)&os,   g_os);
    cudaGetSymbolAddress((void**)&wcq,  g_wcq);
    cudaGetSymbolAddress((void**)&wck,  g_wck);

    const int comp_smem = 128 * 129 * 4;  // 66048
    cudaFuncSetAttribute(composite_kernel, cudaFuncAttributeMaxDynamicSharedMemorySize, comp_smem);
    cudaFuncSetAttribute(chunk_kv_mma,  cudaFuncAttributeMaxDynamicSharedMemorySize, KV_SMEM);
    cudaFuncSetAttribute(chunk_out_mma, cudaFuncAttributeMaxDynamicSharedMemorySize, CO_SMEM);
    cudaFuncSetAttribute(mma_gemm_kernel<0>, cudaFuncAttributeMaxDynamicSharedMemorySize, GEMM_SMEM);
    cudaFuncSetAttribute(mma_gemm_kernel<3>, cudaFuncAttributeMaxDynamicSharedMemorySize, GEMM_SMEM);

    // ---- converts ----
    tof16_kernel<<<(MROWS * HID) / 512, 256>>>(x, x16, (size_t)MROWS * HID);
    tof16_kernel<<<(HID * HID) / 512, 256>>>(Wv, wv16, (size_t)HID * HID);
    tof16_kernel<<<(HID * HID) / 512, 256>>>(Wo, wo16, (size_t)HID * HID);

    // ---- composite fm∘proj weights ----
    dim3 gComp(8, 4, 8);
    composite_kernel<<<gComp, 256, comp_smem>>>(fmq_w1, fmq_w2, fmq_b1, fmq_b2, Wq, wcq, bcq);
    composite_kernel<<<gComp, 256, comp_smem>>>(fmk_w1, fmk_w2, fmk_b1, fmk_b2, Wk, wck, bck);

    // ---- composed projections (hadamard epilogue -> bQ/bK fp32) ----
    dim3 gQK(2 * HID / 128, MROWS / 128);   // (16, 128)
    dim3 gBig(HID / 128, MROWS / 128);      // (8, 128)
    const float scale = 0.08838834764831845f; // 128^-0.5
    mma_gemm_kernel<3><<<gQK, 256, GEMM_SMEM>>>(x16, wcq, bcq, bQ, scale, 2 * HID, HID, HID);
    mma_gemm_kernel<3><<<gQK, 256, GEMM_SMEM>>>(x16, wck, bck, bK, 1.0f, 2 * HID, HID, HID);
    mma_gemm_kernel<0><<<gBig, 256, GEMM_SMEM>>>(x16, wv16, nullptr, bV, 0.f, HID, HID, HID);

    // ---- chunked linear attention (HMMA) ----
    const int nBlk = BB * NCH * HH;
    chunk_kv_mma<<<nBlk, 256, KV_SMEM>>>(bK, bV, bKV);
    scan_kv_kernel<<<(BB * HH * 16384) / 256, 256>>>(bKV);
    chunk_out_mma<<<nBlk, 256, CO_SMEM>>>(bQ, bK, bV, bKV, rms_w, os);

    // ---- output projection (hi-only, K=1024) ----
    mma_gemm_kernel<0><<<gBig, 256, GEMM_SMEM>>>(os, wo16, nullptr, out, 0.f, HID, HID, K2BIG);
}

// round 15
// speedup vs baseline: 3.0031x; 1.0426x over previous
#include <cuda_runtime.h>
#include <cuda_fp16.h>
#include <cstddef>
#include <cstdint>

// Problem constants
#define BB 2
#define TT 8192
#define HH 8
#define DKV 128
#define HID 1024
#define CHUNK 64
#define NCH 128           // TT / CHUNK
#define MROWS (BB*TT)     // 16384
#define FMROWS (BB*TT*HH) // 131072
#define EPS 1e-5f
#define K2BIG (2*HID)     // 2048

// -------- fp32 scratch --------
__device__ float g_bufQ[MROWS * HID];   // q after feature map
__device__ float g_bufK[MROWS * HID];   // k after feature map
__device__ float g_bufV[MROWS * HID];   // v projection
__device__ float g_kv[(size_t)BB * NCH * HH * DKV * DKV];

// -------- fp16 scratch --------
__device__ __half g_x16 [(size_t)MROWS * HID];        // x fp16
__device__ __half g_wv16[(size_t)HID * HID];          // Wv hi
__device__ __half g_wo16[(size_t)HID * HID];          // Wo hi
__device__ __half g_os [(size_t)MROWS * HID];         // attention out fp16
__device__ __half g_wcq[(size_t)2 * HID * HID];       // composite q weights [2048,1024]
__device__ __half g_wck[(size_t)2 * HID * HID];       // composite k weights
__device__ float  g_bcq[2 * HID];                     // composite q bias [2048]
__device__ float  g_bck[2 * HID];

__device__ __forceinline__ uint32_t smem_u32(const void* p) {
    uint32_t a;
    asm("{ .reg .u64 t; cvta.to.shared.u64 t, %1; cvt.u32.u64 %0, t; }"
        : "=r"(a) : "l"(p));
    return a;
}

#define LDSM(r0,r1,r2,r3,addr) \
    asm volatile("ldmatrix.sync.aligned.m8n8.x4.shared.b16 {%0,%1,%2,%3}, [%4];" \
                 : "=r"(r0),"=r"(r1),"=r"(r2),"=r"(r3) : "r"(addr))
#define LDSM_T(r0,r1,r2,r3,addr) \
    asm volatile("ldmatrix.sync.aligned.m8n8.x4.trans.shared.b16 {%0,%1,%2,%3}, [%4];" \
                 : "=r"(r0),"=r"(r1),"=r"(r2),"=r"(r3) : "r"(addr))
#define MMA16816(acc,a0,a1,a2,a3,b0,b1) \
    asm volatile("mma.sync.aligned.m16n8k16.row.col.f32.f16.f16.f32 " \
                 "{%0,%1,%2,%3}, {%4,%5,%6,%7}, {%8,%9}, {%0,%1,%2,%3};" \
                 : "+f"((acc)[0]), "+f"((acc)[1]), "+f"((acc)[2]), "+f"((acc)[3]) \
                 : "r"(a0), "r"(a1), "r"(a2), "r"(a3), "r"(b0), "r"(b1))

// ============================================================
// tof16: plain fp32 -> fp16 convert (packed)
// ============================================================
__global__ void tof16_kernel(const float* __restrict__ in,
                             __half* __restrict__ out, size_t total)
{
    size_t i = ((size_t)blockIdx.x * blockDim.x + threadIdx.x) * 2;
    if (i >= total) return;
    float2 x = *(const float2*)(in + i);
    __half2 hv;
    hv.x = __float2half(x.x);
    hv.y = __float2half(x.y);
    *(__half2*)(out + i) = hv;
}

// ============================================================
// composite_kernel v2 (register-tiled):
// Wc[2*(h*128+j)+br, n] = sum_d w{br}[j,d] * Wp[h*128+d, n]  (* s1 if br==0)
// grid (8 nt, 4 rpg, 8 head), 256 threads.
// smem: Wqs [128][132] fp32 (Wp tile) + Ws [64][132] fp32 (fm rows)
// Per thread: 4 rp x 8 cols -> 12 LDS per 32 FMA.
// ============================================================
#define COMP_SMEM ((128 * 132 + 64 * 132) * 4)   // 101376

__global__ __launch_bounds__(256) void composite_kernel(
    const float* __restrict__ w1, const float* __restrict__ w2,
    const float* __restrict__ b1, const float* __restrict__ b2,
    const float* __restrict__ Wp,
    __half* __restrict__ Wc, float* __restrict__ bc, float s1)
{
    extern __shared__ float smco[];
    float* Wqs = smco;             // [128][132]
    float* Ws  = smco + 128 * 132; // [64][132]
    const int nt = blockIdx.x;     // 0..7
    const int rpg = blockIdx.y;    // 0..3
    const int h = blockIdx.z;      // 0..7
    const int tid = threadIdx.x;

    for (int i = tid; i < 128 * 128; i += 256) {
        int d = i >> 7, c = i & 127;
        Wqs[d * 132 + c] = Wp[(size_t)(h * 128 + d) * 1024 + nt * 128 + c];
    }
    for (int i = tid; i < 64 * 128; i += 256) {
        int l = i >> 7, d = i & 127;
        int rpl = rpg * 64 + l;
        int j = rpl >> 1, br = rpl & 1;
        float wv = (br ? w2 : w1)[j * 128 + d];
        if (br == 0) wv *= s1;
        Ws[l * 132 + d] = wv;
    }
    __syncthreads();

    const int tidm = tid >> 4;     // 0..15 -> rp-local = tidm*4
    const int tidn = tid & 15;     // 0..15 -> cols = tidn*8
    float acc[4][8];
#pragma unroll
    for (int i = 0; i < 4; i++)
#pragma unroll
        for (int c = 0; c < 8; c++) acc[i][c] = 0.f;

    for (int d = 0; d < 128; d++) {
        float a[4];
#pragma unroll
        for (int i = 0; i < 4; i++) a[i] = Ws[(tidm * 4 + i) * 132 + d];
        float bb[8];
        *(float4*)(bb)     = *(const float4*)&Wqs[d * 132 + tidn * 8];
        *(float4*)(bb + 4) = *(const float4*)&Wqs[d * 132 + tidn * 8 + 4];
#pragma unroll
        for (int i = 0; i < 4; i++)
#pragma unroll
            for (int c = 0; c < 8; c++)
                acc[i][c] += a[i] * bb[c];
    }

#pragma unroll
    for (int i = 0; i < 4; i++) {
        int rp = h * 256 + rpg * 64 + tidm * 4 + i;
        __half* o = Wc + (size_t)rp * 1024 + nt * 128 + tidn * 8;
#pragma unroll
        for (int c = 0; c < 8; c++)
            o[c] = __float2half(acc[i][c]);
        if (nt == 0 && tidn == 0) {
            int rpl = rpg * 64 + tidm * 4 + i;
            int j = rpl >> 1, br = rpl & 1;
            float bv = (br ? b2 : b1)[j];
            bc[rp] = br ? bv : bv * s1;
        }
    }
}

// ============================================================
// Tensor-core GEMM: C[M,N] = A[M,0:K] @ B[N,K]^T (+bias)
// EPI==0: C fp32 (+bias). EPI==3: hadamard pairs -> fp32 [., N/2].
// ============================================================
#define ASTAGE 10240
#define STAGEB 20480
#define NSTG 4
#define GEMM_SMEM (NSTG * STAGEB)

template<int EPI>
__global__ __launch_bounds__(256, 2) void mma_gemm_kernel(
    const __half* __restrict__ A,
    const __half* __restrict__ B,
    const float* __restrict__ bias,
    float* __restrict__ Cf,
    int N, int K, int ldA)
{
    extern __shared__ __align__(16) char dynsm[];
    const uint32_t sBase = smem_u32(dynsm);

    const int tid = threadIdx.x;
    const int lane = tid & 31;
    const int wid = tid >> 5;
    const int warp_m = (wid & 3) * 32;
    const int warp_n = (wid >> 2) * 64;
    const int bm0 = blockIdx.y * 128;
    const int bn0 = blockIdx.x * 128;
    const int NC = K >> 5;

    const size_t rowbA = (size_t)ldA * 2;
    const size_t rowbB = (size_t)K * 2;
    const char* Ag = (const char*)A + (size_t)bm0 * rowbA;
    const char* Bg = (const char*)B + (size_t)bn0 * rowbB;

    const int r0 = tid >> 2, g0 = tid & 3;
    const int r1 = (tid + 256) >> 2, g1 = (tid + 256) & 3;

    auto load_stage = [&](int kc, int s) {
        const size_t koff = (size_t)kc * 64;
        const uint32_t ab = sBase + (uint32_t)(s * STAGEB);
        const uint32_t bb = ab + ASTAGE;
        uint32_t sa0 = ab + (uint32_t)(r0 * 80 + g0 * 16);
        uint32_t sa1 = ab + (uint32_t)(r1 * 80 + g1 * 16);
        uint32_t sb0 = bb + (uint32_t)(r0 * 80 + g0 * 16);
        uint32_t sb1 = bb + (uint32_t)(r1 * 80 + g1 * 16);
        const void* ga0 = Ag + (size_t)r0 * rowbA + koff + g0 * 16;
        const void* ga1 = Ag + (size_t)r1 * rowbA + koff + g1 * 16;
        const void* gb0 = Bg + (size_t)r0 * rowbB + koff + g0 * 16;
        const void* gb1 = Bg + (size_t)r1 * rowbB + koff + g1 * 16;
        asm volatile("cp.async.cg.shared.global [%0], [%1], 16;" :: "r"(sa0), "l"(ga0));
        asm volatile("cp.async.cg.shared.global [%0], [%1], 16;" :: "r"(sa1), "l"(ga1));
        asm volatile("cp.async.cg.shared.global [%0], [%1], 16;" :: "r"(sb0), "l"(gb0));
        asm volatile("cp.async.cg.shared.global [%0], [%1], 16;" :: "r"(sb1), "l"(gb1));
        asm volatile("cp.async.commit_group;");
    };

    float acc[2][8][4];
#pragma unroll
    for (int mt = 0; mt < 2; mt++)
#pragma unroll
        for (int nt = 0; nt < 8; nt++)
#pragma unroll
            for (int j = 0; j < 4; j++) acc[mt][nt][j] = 0.f;

    load_stage(0, 0);
    load_stage(1, 1);
    load_stage(2, 2);

    const int lm = lane & 15;
    const int lk = lane >> 4;
    const uint32_t aOff = (uint32_t)((warp_m + lm) * 80 + lk * 16);
    const uint32_t bOff = (uint32_t)(ASTAGE + (warp_n + lm) * 80 + lk * 16);

    for (int kc = 0; kc < NC; kc++) {
        const int s = kc & (NSTG - 1);
        if (kc + 3 <= NC)      asm volatile("cp.async.wait_group 2;");
        else if (kc + 2 == NC) asm volatile("cp.async.wait_group 1;");
        else                   asm volatile("cp.async.wait_group 0;");
        __syncthreads();
        if (kc + 3 < NC) load_stage(kc + 3, (kc + 3) & (NSTG - 1));

        const uint32_t aSt = sBase + (uint32_t)(s * STAGEB) + aOff;
        const uint32_t bSt = sBase + (uint32_t)(s * STAGEB) + bOff;

#pragma unroll
        for (int ks = 0; ks < 2; ks++) {
            uint32_t a[2][4], bf[4][4];
#pragma unroll
            for (int mt = 0; mt < 2; mt++) {
                uint32_t ad = aSt + (uint32_t)(mt * 16 * 80 + ks * 32);
                LDSM(a[mt][0], a[mt][1], a[mt][2], a[mt][3], ad);
            }
#pragma unroll
            for (int ng = 0; ng < 4; ng++) {
                uint32_t bd = bSt + (uint32_t)(ng * 16 * 80 + ks * 32);
                LDSM(bf[ng][0], bf[ng][1], bf[ng][2], bf[ng][3], bd);
            }
#pragma unroll
            for (int mt = 0; mt < 2; mt++)
#pragma unroll
                for (int nt = 0; nt < 8; nt++) {
                    const int g = nt >> 1, sel = nt & 1;
                    MMA16816(acc[mt][nt], a[mt][0], a[mt][1], a[mt][2], a[mt][3],
                             bf[g][sel], bf[g][sel + 2]);
                }
        }
    }

    const int erow = bm0 + warp_m + (lane >> 2);
    const int ecol0 = bn0 + warp_n + (lane & 3) * 2;
#pragma unroll
    for (int nt = 0; nt < 8; nt++) {
        const int col = ecol0 + nt * 8;
        float bx = 0.f, by = 0.f;
        if (bias) { bx = bias[col]; by = bias[col + 1]; }
#pragma unroll
        for (int mt = 0; mt < 2; mt++) {
#pragma unroll
            for (int half = 0; half < 2; half++) {
                const int row = erow + mt * 16 + half * 8;
                float vx = acc[mt][nt][half * 2 + 0] + bx;
                float vy = acc[mt][nt][half * 2 + 1] + by;
                if (EPI == 0) {
                    *(float2*)(Cf + (size_t)row * N + col) = make_float2(vx, vy);
                } else {
                    // hadamard pairs: out col = col/2, out stride = N/2
                    Cf[(size_t)row * (N >> 1) + (col >> 1)] = vx * vy;
                }
            }
        }
    }
}

// ============================================================
// chunk_kv_mma: kv = k_c^T @ v_c via fp16 HMMA, 3-product split.
// ============================================================
#define KV_SMEM (2 * 128 * 136 * 2)   // 69632

__global__ __launch_bounds__(256) void chunk_kv_mma(
    const float* __restrict__ k, const float* __restrict__ v,
    float* __restrict__ kv)
{
    extern __shared__ __align__(16) char sm[];
    __half* kS = (__half*)sm;
    __half* vS = (__half*)(sm + 128*136*2);
    const uint32_t kB = smem_u32(kS);
    const uint32_t vB = smem_u32(vS);

    const int bid = blockIdx.x;
    const int h = bid % HH, n = (bid / HH) % NCH, b = bid / (HH * NCH);
    const size_t base = (((size_t)b * TT + (size_t)n * CHUNK) * HH + h) * DKV;
    const int tid = threadIdx.x;
    const int lane = tid & 31;
    const int wid = tid >> 5;

    for (int off = tid * 4; off < 64 * 128; off += 1024) {
        int c = off >> 7, d = off & 127;
        float4 kk = *(const float4*)&k[base + (size_t)c * (HH * DKV) + d];
        float4 vv = *(const float4*)&v[base + (size_t)c * (HH * DKV) + d];
        __half2 kh0 = __floats2half2_rn(kk.x, kk.y);
        __half2 kh1 = __floats2half2_rn(kk.z, kk.w);
        __half2 kl0 = __floats2half2_rn(kk.x - __low2float(kh0),  kk.y - __high2float(kh0));
        __half2 kl1 = __floats2half2_rn(kk.z - __low2float(kh1),  kk.w - __high2float(kh1));
        __half2 vh0 = __floats2half2_rn(vv.x, vv.y);
        __half2 vh1 = __floats2half2_rn(vv.z, vv.w);
        __half2 vl0 = __floats2half2_rn(vv.x - __low2float(vh0),  vv.y - __high2float(vh0));
        __half2 vl1 = __floats2half2_rn(vv.z - __low2float(vh1),  vv.w - __high2float(vh1));
        *(__half2*)(kS + c * 136 + d)            = kh0;
        *(__half2*)(kS + c * 136 + d + 2)        = kh1;
        *(__half2*)(kS + (c + 64) * 136 + d)     = kl0;
        *(__half2*)(kS + (c + 64) * 136 + d + 2) = kl1;
        *(__half2*)(vS + c * 136 + d)            = vh0;
        *(__half2*)(vS + c * 136 + d + 2)        = vh1;
        *(__half2*)(vS + (c + 64) * 136 + d)     = vl0;
        *(__half2*)(vS + (c + 64) * 136 + d + 2) = vl1;
    }
    __syncthreads();

    const int warp_m = (wid & 3) * 32;
    const int warp_n = (wid >> 2) * 64;
    const int krl = ((lane >> 4) << 3) + (lane & 7);
    const int mco = ((lane >> 3) & 1) << 3;

    float acc[2][8][4];
#pragma unroll
    for (int mt = 0; mt < 2; mt++)
#pragma unroll
        for (int nt = 0; nt < 8; nt++)
#pragma unroll
            for (int j = 0; j < 4; j++) acc[mt][nt][j] = 0.f;

#pragma unroll
    for (int kc = 0; kc < 12; kc++) {
        const int t = kc >> 2;
        const int cb = (kc & 3) << 4;
        const int ar = ((t == 1) ? 64 : 0) + cb;
        const int br = ((t == 2) ? 64 : 0) + cb;
        uint32_t a[2][4], bf[4][4];
#pragma unroll
        for (int mt = 0; mt < 2; mt++) {
            uint32_t ad = kB + (uint32_t)(((ar + krl) * 136 + warp_m + mt * 16 + mco) * 2);
            LDSM_T(a[mt][0], a[mt][1], a[mt][2], a[mt][3], ad);
        }
#pragma unroll
        for (int ng = 0; ng < 4; ng++) {
            uint32_t bd = vB + (uint32_t)(((br + krl) * 136 + warp_n + ng * 16 + mco) * 2);
            LDSM_T(bf[ng][0], bf[ng][1], bf[ng][2], bf[ng][3], bd);
        }
#pragma unroll
        for (int mt = 0; mt < 2; mt++)
#pragma unroll
            for (int nt = 0; nt < 8; nt++) {
                const int g = nt >> 1, sel = nt & 1;
                MMA16816(acc[mt][nt], a[mt][0], a[mt][1], a[mt][2], a[mt][3],
                         bf[g][sel], bf[g][sel + 2]);
            }
    }

    float* outp = kv + (size_t)bid * (DKV * DKV);
    const int er = warp_m + (lane >> 2);
    const int ec = warp_n + (lane & 3) * 2;
#pragma unroll
    for (int nt = 0; nt < 8; nt++)
#pragma unroll
        for (int mt = 0; mt < 2; mt++)
#pragma unroll
            for (int half = 0; half < 2; half++) {
                int row = er + mt * 16 + half * 8;
                *(float2*)(outp + row * 128 + ec + nt * 8) =
                    make_float2(acc[mt][nt][half * 2], acc[mt][nt][half * 2 + 1]);
            }
}

// ============================================================
// Exclusive prefix over chunks (in-place)
// ============================================================
__global__ void scan_kv_kernel(float* __restrict__ kv)
{
    int gid = blockIdx.x * blockDim.x + threadIdx.x;
    int e = gid & 16383;
    int h = (gid >> 14) % HH;
    int b = gid / (16384 * HH);
    size_t idx = (((size_t)b * NCH) * HH + h) * 16384 + e;
    const size_t stride = (size_t)HH * 16384;
    float acc = 0.f;
#pragma unroll 4
    for (int n = 0; n < NCH; n++) {
        float x = kv[idx];
        kv[idx] = acc;
        acc += x;
        idx += stride;
    }
}

// ============================================================
// chunk_out_mma: A = tril(q k^T); o = A.v + q.S; RMSNorm; os fp16.
// ============================================================
#define CO_QS   0
#define CO_AP   33792
#define CO_VP   51200
#define CO_SP   86016
#define CO_SMEM (86016 + 256*136*2)   // 155648

__global__ __launch_bounds__(256) void chunk_out_mma(
    const float* __restrict__ q, const float* __restrict__ k,
    const float* __restrict__ v, const float* __restrict__ kvS,
    const float* __restrict__ rms_w, __half* __restrict__ os)
{
    extern __shared__ __align__(16) char sm[];
    __half* qS = (__half*)(sm + CO_QS);
    __half* Ap = (__half*)(sm + CO_AP);
    __half* vP = (__half*)(sm + CO_VP);
    __half* sP = (__half*)(sm + CO_SP);
    __half* kSm = (__half*)(sm + CO_SP);
    float* oS = (float*)(sm + CO_SP);
    const uint32_t qB = smem_u32(qS);
    const uint32_t aB = smem_u32(Ap);
    const uint32_t vB = smem_u32(vP);
    const uint32_t sB = smem_u32(sP);
    const uint32_t kB2 = sB;

    const int bid = blockIdx.x;
    const int h = bid % HH, n = (bid / HH) % NCH, b = bid / (HH * NCH);
    const size_t base = (((size_t)b * TT + (size_t)n * CHUNK) * HH + h) * DKV;
    const int tid = threadIdx.x;
    const int lane = tid & 31;
    const int wid = tid >> 5;

    // ---- phase 1: load q, k -> fp16 splits ----
    for (int off = tid * 4; off < 64 * 128; off += 1024) {
        int c = off >> 7, d = off & 127;
        float4 qq = *(const float4*)&q[base + (size_t)c * (HH * DKV) + d];
        float4 kk = *(const float4*)&k[base + (size_t)c * (HH * DKV) + d];
        __half2 qh0 = __floats2half2_rn(qq.x, qq.y);
        __half2 qh1 = __floats2half2_rn(qq.z, qq.w);
        __half2 ql0 = __floats2half2_rn(qq.x - __low2float(qh0), qq.y - __high2float(qh0));
        __half2 ql1 = __floats2half2_rn(qq.z - __low2float(qh1), qq.w - __high2float(qh1));
        __half2 kh0 = __floats2half2_rn(kk.x, kk.y);
        __half2 kh1 = __floats2half2_rn(kk.z, kk.w);
        __half2 kl0 = __floats2half2_rn(kk.x - __low2float(kh0), kk.y - __high2float(kh0));
        __half2 kl1 = __floats2half2_rn(kk.z - __low2float(kh1), kk.w - __high2float(kh1));
        *(__half2*)(qS + c * 264 + d)           = qh0;
        *(__half2*)(qS + c * 264 + d + 2)       = qh1;
        *(__half2*)(qS + c * 264 + 128 + d)     = ql0;
        *(__half2*)(qS + c * 264 + 128 + d + 2) = ql1;
        *(__half2*)(kSm + c * 264 + d)           = kh0;
        *(__half2*)(kSm + c * 264 + d + 2)       = kh1;
        *(__half2*)(kSm + c * 264 + 128 + d)     = kl0;
        *(__half2*)(kSm + c * 264 + 128 + d + 2) = kl1;
    }
    __syncthreads();

    const int krl = ((lane >> 4) << 3) + (lane & 7);
    const int mco = ((lane >> 3) & 1) << 3;

    // ---- phase 2: A = q.k^T ----
    {
        const int wmA = (wid & 1) * 32;
        const int wnA = (wid >> 1) * 16;
        float accA[2][2][4];
#pragma unroll
        for (int mt = 0; mt < 2; mt++)
#pragma unroll
            for (int nt = 0; nt < 2; nt++)
#pragma unroll
                for (int j = 0; j < 4; j++) accA[mt][nt][j] = 0.f;

#pragma unroll
        for (int kc = 0; kc < 24; kc++) {
            const int t = kc >> 3;
            const int cb = (kc & 7) << 4;
            const int qc = ((t == 1) ? 128 : 0) + cb;
            const int kc2 = ((t == 2) ? 128 : 0) + cb;
            uint32_t a[2][4], bf[4];
#pragma unroll
            for (int mt = 0; mt < 2; mt++) {
                uint32_t ad = qB + (uint32_t)(((wmA + mt * 16 + (lane & 15)) * 264
                                               + qc + ((lane >> 4) << 3)) * 2);
                LDSM(a[mt][0], a[mt][1], a[mt][2], a[mt][3], ad);
            }
            uint32_t bd = kB2 + (uint32_t)(((wnA + (lane & 15)) * 264
                                            + kc2 + ((lane >> 4) << 3)) * 2);
            LDSM(bf[0], bf[1], bf[2], bf[3], bd);
#pragma unroll
            for (int mt = 0; mt < 2; mt++)
#pragma unroll
                for (int nt = 0; nt < 2; nt++)
                    MMA16816(accA[mt][nt], a[mt][0], a[mt][1], a[mt][2], a[mt][3],
                             bf[nt], bf[nt + 2]);
        }

        const int er = wmA + (lane >> 2);
        const int ec = wnA + (lane & 3) * 2;
#pragma unroll
        for (int mt = 0; mt < 2; mt++)
#pragma unroll
            for (int nt = 0; nt < 2; nt++)
#pragma unroll
                for (int half = 0; half < 2; half++) {
                    int r = er + mt * 16 + half * 8;
                    int c = ec + nt * 8;
                    float v0 = (c     <= r) ? accA[mt][nt][half * 2 + 0] : 0.f;
                    float v1 = (c + 1 <= r) ? accA[mt][nt][half * 2 + 1] : 0.f;
                    __half h0 = __float2half(v0);
                    __half h1 = __float2half(v1);
                    __half2 hv; hv.x = h0; hv.y = h1;
                    __half2 lv;
                    lv.x = __float2half(v0 - __half2float(h0));
                    lv.y = __float2half(v1 - __half2float(h1));
                    *(__half2*)(Ap + r * 136 + c)      = hv;
                    *(__half2*)(Ap + r * 136 + 64 + c) = lv;
                }
    }
    __syncthreads();

    // ---- phase 3: load v, S -> fp16 splits ----
    for (int off = tid * 4; off < 64 * 128; off += 1024) {
        int c = off >> 7, d = off & 127;
        float4 vv = *(const float4*)&v[base + (size_t)c * (HH * DKV) + d];
        __half2 vh0 = __floats2half2_rn(vv.x, vv.y);
        __half2 vh1 = __floats2half2_rn(vv.z, vv.w);
        __half2 vl0 = __floats2half2_rn(vv.x - __low2float(vh0), vv.y - __high2float(vh0));
        __half2 vl1 = __floats2half2_rn(vv.z - __low2float(vh1), vv.w - __high2float(vh1));
        *(__half2*)(vP + c * 136 + d)            = vh0;
        *(__half2*)(vP + c * 136 + d + 2)        = vh1;
        *(__half2*)(vP + (c + 64) * 136 + d)     = vl0;
        *(__half2*)(vP + (c + 64) * 136 + d + 2) = vl1;
    }
    {
        const float* Sg = kvS + (size_t)bid * (DKV * DKV);
        for (int off = tid * 4; off < 128 * 128; off += 1024) {
            int dr = off >> 7, dv = off & 127;
            float4 ss = *(const float4*)&Sg[dr * 128 + dv];
            __half2 sh0 = __floats2half2_rn(ss.x, ss.y);
            __half2 sh1 = __floats2half2_rn(ss.z, ss.w);
            __half2 sl0 = __floats2half2_rn(ss.x - __low2float(sh0), ss.y - __high2float(sh0));
            __half2 sl1 = __floats2half2_rn(ss.z - __low2float(sh1), ss.w - __high2float(sh1));
            *(__half2*)(sP + dr * 136 + dv)             = sh0;
            *(__half2*)(sP + dr * 136 + dv + 2)         = sh1;
            *(__half2*)(sP + (dr + 128) * 136 + dv)     = sl0;
            *(__half2*)(sP + (dr + 128) * 136 + dv + 2) = sl1;
        }
    }
    __syncthreads();

    // ---- phase 4: o = A'.v' + q.S' ----
    const int warp_m = (wid & 1) * 32;
    const int warp_n = (wid >> 1) * 32;
    float acc[2][4][4];
#pragma unroll
    for (int mt = 0; mt < 2; mt++)
#pragma unroll
        for (int nt = 0; nt < 4; nt++)
#pragma unroll
            for (int j = 0; j < 4; j++) acc[mt][nt][j] = 0.f;

#pragma unroll
    for (int kc = 0; kc < 12; kc++) {
        const int t = kc >> 2;
        const int cb = (kc & 3) << 4;
        const int ac = ((t == 1) ? 64 : 0) + cb;
        const int br = ((t == 2) ? 64 : 0) + cb;
        uint32_t a[2][4], bf[2][4];
#pragma unroll
        for (int mt = 0; mt < 2; mt++) {
            uint32_t ad = aB + (uint32_t)(((warp_m + mt * 16 + (lane & 15)) * 136
                                           + ac + ((lane >> 4) << 3)) * 2);
            LDSM(a[mt][0], a[mt][1], a[mt][2], a[mt][3], ad);
        }
#pragma unroll
        for (int ng = 0; ng < 2; ng++) {
            uint32_t bd = vB + (uint32_t)(((br + krl) * 136 + warp_n + ng * 16 + mco) * 2);
            LDSM_T(bf[ng][0], bf[ng][1], bf[ng][2], bf[ng][3], bd);
        }
#pragma unroll
        for (int mt = 0; mt < 2; mt++)
#pragma unroll
            for (int nt = 0; nt < 4; nt++) {
                const int g = nt >> 1, sel = nt & 1;
                MMA16816(acc[mt][nt], a[mt][0], a[mt][1], a[mt][2], a[mt][3],
                         bf[g][sel], bf[g][sel + 2]);
            }
    }
#pragma unroll
    for (int kc = 0; kc < 24; kc++) {
        const int t = kc >> 3;
        const int cb = (kc & 7) << 4;
        const int qc = ((t == 1) ? 128 : 0) + cb;
        const int sr = ((t == 2) ? 128 : 0) + cb;
        uint32_t a[2][4], bf[2][4];
#pragma unroll
        for (int mt = 0; mt < 2; mt++) {
            uint32_t ad = qB + (uint32_t)(((warp_m + mt * 16 + (lane & 15)) * 264
                                           + qc + ((lane >> 4) << 3)) * 2);
            LDSM(a[mt][0], a[mt][1], a[mt][2], a[mt][3], ad);
        }
#pragma unroll
        for (int ng = 0; ng < 2; ng++) {
            uint32_t bd = sB + (uint32_t)(((sr + krl) * 136 + warp_n + ng * 16 + mco) * 2);
            LDSM_T(bf[ng][0], bf[ng][1], bf[ng][2], bf[ng][3], bd);
        }
#pragma unroll
        for (int mt = 0; mt < 2; mt++)
#pragma unroll
            for (int nt = 0; nt < 4; nt++) {
                const int g = nt >> 1, sel = nt & 1;
                MMA16816(acc[mt][nt], a[mt][0], a[mt][1], a[mt][2], a[mt][3],
                         bf[g][sel], bf[g][sel + 2]);
            }
    }

    // ---- phase 5: stage o to smem fp32 ----
    __syncthreads();
    {
        const int er = warp_m + (lane >> 2);
        const int ec = warp_n + (lane & 3) * 2;
#pragma unroll
        for (int mt = 0; mt < 2; mt++)
#pragma unroll
            for (int nt = 0; nt < 4; nt++)
#pragma unroll
                for (int half = 0; half < 2; half++) {
                    int r = er + mt * 16 + half * 8;
                    *(float2*)(oS + r * 132 + ec + nt * 8) =
                        make_float2(acc[mt][nt][half * 2], acc[mt][nt][half * 2 + 1]);
                }
    }
    __syncthreads();

    // ---- phase 6: RMSNorm + fp16 write to os (stride 1024) ----
    {
        const int r = tid >> 2;
        const int part = tid & 3;
        float vals[32];
        float s = 0.f;
#pragma unroll
        for (int j = 0; j < 32; j += 4) {
            float4 x = *(const float4*)(oS + r * 132 + part * 32 + j);
            vals[j] = x.x; vals[j+1] = x.y; vals[j+2] = x.z; vals[j+3] = x.w;
            s += x.x*x.x + x.y*x.y + x.z*x.z + x.w*x.w;
        }
        s += __shfl_xor_sync(0xffffffffu, s, 1);
        s += __shfl_xor_sync(0xffffffffu, s, 2);
        float scale = rsqrtf(s * (1.0f / 128.0f) + EPS);
        size_t R = (size_t)b * TT + (size_t)n * CHUNK + r;
        __half* p = os + R * 1024 + h * 128 + part * 32;
#pragma unroll
        for (int j = 0; j < 32; j += 2) {
            float vx = vals[j]   * scale * rms_w[part * 32 + j];
            float vy = vals[j+1] * scale * rms_w[part * 32 + j + 1];
            __half2 hv;
            hv.x = __float2half(vx);
            hv.y = __float2half(vy);
            *(__half2*)(p + j) = hv;
        }
    }
}

// ============================================================
// Launch
// ============================================================
extern "C" void kernel_launch(void* const* d_in, const int* in_sizes, int n_in,
                              void* d_out, int out_size)
{
    const float* x      = (const float*)d_in[0];
    const float* Wq     = (const float*)d_in[1];
    const float* Wk     = (const float*)d_in[2];
    const float* Wv     = (const float*)d_in[3];
    const float* fmq_w1 = (const float*)d_in[4];
    const float* fmq_b1 = (const float*)d_in[5];
    const float* fmq_w2 = (const float*)d_in[6];
    const float* fmq_b2 = (const float*)d_in[7];
    const float* fmk_w1 = (const float*)d_in[8];
    const float* fmk_b1 = (const float*)d_in[9];
    const float* fmk_w2 = (const float*)d_in[10];
    const float* fmk_b2 = (const float*)d_in[11];
    const float* rms_w  = (const float*)d_in[12];
    const float* Wo     = (const float*)d_in[13];
    float* out = (float*)d_out;

    float *bQ, *bK, *bV, *bKV, *bcq, *bck;
    cudaGetSymbolAddress((void**)&bQ, g_bufQ);
    cudaGetSymbolAddress((void**)&bK, g_bufK);
    cudaGetSymbolAddress((void**)&bV, g_bufV);
    cudaGetSymbolAddress((void**)&bKV, g_kv);
    cudaGetSymbolAddress((void**)&bcq, g_bcq);
    cudaGetSymbolAddress((void**)&bck, g_bck);

    __half *x16, *wv16, *wo16, *os, *wcq, *wck;
    cudaGetSymbolAddress((void**)&x16,  g_x16);
    cudaGetSymbolAddress((void**)&wv16, g_wv16);
    cudaGetSymbolAddress((void**)&wo16, g_wo16);
    cudaGetSymbolAddress((void**)&os,   g_os);
    cudaGetSymbolAddress((void**)&wcq,  g_wcq);
    cudaGetSymbolAddress((void**)&wck,  g_wck);

    cudaFuncSetAttribute(composite_kernel, cudaFuncAttributeMaxDynamicSharedMemorySize, COMP_SMEM);
    cudaFuncSetAttribute(chunk_kv_mma,  cudaFuncAttributeMaxDynamicSharedMemorySize, KV_SMEM);
    cudaFuncSetAttribute(chunk_out_mma, cudaFuncAttributeMaxDynamicSharedMemorySize, CO_SMEM);
    cudaFuncSetAttribute(mma_gemm_kernel<0>, cudaFuncAttributeMaxDynamicSharedMemorySize, GEMM_SMEM);
    cudaFuncSetAttribute(mma_gemm_kernel<3>, cudaFuncAttributeMaxDynamicSharedMemorySize, GEMM_SMEM);

    // ---- converts ----
    tof16_kernel<<<(MROWS * HID) / 512, 256>>>(x, x16, (size_t)MROWS * HID);
    tof16_kernel<<<(HID * HID) / 512, 256>>>(Wv, wv16, (size_t)HID * HID);
    tof16_kernel<<<(HID * HID) / 512, 256>>>(Wo, wo16, (size_t)HID * HID);

    // ---- composite fm∘proj weights (q-scale folded into branch1) ----
    const float scale = 0.08838834764831845f; // 128^-0.5
    dim3 gComp(8, 4, 8);
    composite_kernel<<<gComp, 256, COMP_SMEM>>>(fmq_w1, fmq_w2, fmq_b1, fmq_b2, Wq, wcq, bcq, scale);
    composite_kernel<<<gComp, 256, COMP_SMEM>>>(fmk_w1, fmk_w2, fmk_b1, fmk_b2, Wk, wck, bck, 1.0f);

    // ---- composed projections (hadamard epilogue -> bQ/bK fp32) ----
    dim3 gQK(2 * HID / 128, MROWS / 128);   // (16, 128)
    dim3 gBig(HID / 128, MROWS / 128);      // (8, 128)
    mma_gemm_kernel<3><<<gQK, 256, GEMM_SMEM>>>(x16, wcq, bcq, bQ, 2 * HID, HID, HID);
    mma_gemm_kernel<3><<<gQK, 256, GEMM_SMEM>>>(x16, wck, bck, bK, 2 * HID, HID, HID);
    mma_gemm_kernel<0><<<gBig, 256, GEMM_SMEM>>>(x16, wv16, nullptr, bV, HID, HID, HID);

    // ---- chunked linear attention (HMMA) ----
    const int nBlk = BB * NCH * HH;
    chunk_kv_mma<<<nBlk, 256, KV_SMEM>>>(bK, bV, bKV);
    scan_kv_kernel<<<(BB * HH * 16384) / 256, 256>>>(bKV);
    chunk_out_mma<<<nBlk, 256, CO_SMEM>>>(bQ, bK, bV, bKV, rms_w, os);

    // ---- output projection (fp16 x fp16-hi, K=1024) ----
    mma_gemm_kernel<0><<<gBig, 256, GEMM_SMEM>>>(os, wo16, nullptr, out, HID, HID, HID);
}

// round 16
// speedup vs baseline: 4.0891x; 1.3616x over previous
#include <cuda_runtime.h>
#include <cuda_fp16.h>
#include <cstddef>
#include <cstdint>

// Problem constants
#define BB 2
#define TT 8192
#define HH 8
#define DKV 128
#define HID 1024
#define CHUNK 64
#define NCH 128           // TT / CHUNK
#define MROWS (BB*TT)     // 16384
#define EPS 1e-5f

// -------- scratch --------
__device__ float  g_kv[(size_t)BB * NCH * HH * DKV * DKV];      // fp32 chunk kv sums
__device__ __half g_x16 [(size_t)MROWS * HID];                  // x fp16
__device__ __half g_wv16[(size_t)HID * HID];                    // Wv hi
__device__ __half g_wo16[(size_t)HID * HID];                    // Wo hi
__device__ __half g_os  [(size_t)MROWS * HID];                  // attention out fp16
__device__ __half g_wcq [(size_t)2 * HID * HID];                // composite q weights
__device__ __half g_wck [(size_t)2 * HID * HID];                // composite k weights
__device__ float  g_bcq[2 * HID];
__device__ float  g_bck[2 * HID];
// pre-split tiles: per (b,n,h): [hi rows 0-63 | lo rows 64-127] x 128 d, 16384 halfs
__device__ __half g_qs[(size_t)BB * NCH * HH * 16384];
__device__ __half g_ks[(size_t)BB * NCH * HH * 16384];
__device__ __half g_vs[(size_t)BB * NCH * HH * 16384];
// S tiles: per (b,n,h): [Sh rows 0-127 | Sl rows 128-255] x 128, 32768 halfs
__device__ __half g_ss[(size_t)BB * NCH * HH * 32768];

__device__ __forceinline__ uint32_t smem_u32(const void* p) {
    uint32_t a;
    asm("{ .reg .u64 t; cvta.to.shared.u64 t, %1; cvt.u32.u64 %0, t; }"
        : "=r"(a) : "l"(p));
    return a;
}

#define CPA16(dst, src) \
    asm volatile("cp.async.cg.shared.global [%0], [%1], 16;" :: "r"(dst), "l"(src))
#define LDSM(r0,r1,r2,r3,addr) \
    asm volatile("ldmatrix.sync.aligned.m8n8.x4.shared.b16 {%0,%1,%2,%3}, [%4];" \
                 : "=r"(r0),"=r"(r1),"=r"(r2),"=r"(r3) : "r"(addr))
#define LDSM_T(r0,r1,r2,r3,addr) \
    asm volatile("ldmatrix.sync.aligned.m8n8.x4.trans.shared.b16 {%0,%1,%2,%3}, [%4];" \
                 : "=r"(r0),"=r"(r1),"=r"(r2),"=r"(r3) : "r"(addr))
#define MMA16816(acc,a0,a1,a2,a3,b0,b1) \
    asm volatile("mma.sync.aligned.m16n8k16.row.col.f32.f16.f16.f32 " \
                 "{%0,%1,%2,%3}, {%4,%5,%6,%7}, {%8,%9}, {%0,%1,%2,%3};" \
                 : "+f"((acc)[0]), "+f"((acc)[1]), "+f"((acc)[2]), "+f"((acc)[3]) \
                 : "r"(a0), "r"(a1), "r"(a2), "r"(a3), "r"(b0), "r"(b1))

// ============================================================
// tof16
// ============================================================
__global__ void tof16_kernel(const float* __restrict__ in,
                             __half* __restrict__ out, size_t total)
{
    size_t i = ((size_t)blockIdx.x * blockDim.x + threadIdx.x) * 2;
    if (i >= total) return;
    float2 x = *(const float2*)(in + i);
    __half2 hv;
    hv.x = __float2half(x.x);
    hv.y = __float2half(x.y);
    *(__half2*)(out + i) = hv;
}

// ============================================================
// composite_kernel (register-tiled)
// ============================================================
#define COMP_SMEM ((128 * 132 + 64 * 132) * 4)   // 101376

__global__ __launch_bounds__(256) void composite_kernel(
    const float* __restrict__ w1, const float* __restrict__ w2,
    const float* __restrict__ b1, const float* __restrict__ b2,
    const float* __restrict__ Wp,
    __half* __restrict__ Wc, float* __restrict__ bc, float s1)
{
    extern __shared__ float smco[];
    float* Wqs = smco;
    float* Ws  = smco + 128 * 132;
    const int nt = blockIdx.x;
    const int rpg = blockIdx.y;
    const int h = blockIdx.z;
    const int tid = threadIdx.x;

    for (int i = tid; i < 128 * 128; i += 256) {
        int d = i >> 7, c = i & 127;
        Wqs[d * 132 + c] = Wp[(size_t)(h * 128 + d) * 1024 + nt * 128 + c];
    }
    for (int i = tid; i < 64 * 128; i += 256) {
        int l = i >> 7, d = i & 127;
        int rpl = rpg * 64 + l;
        int j = rpl >> 1, br = rpl & 1;
        float wv = (br ? w2 : w1)[j * 128 + d];
        if (br == 0) wv *= s1;
        Ws[l * 132 + d] = wv;
    }
    __syncthreads();

    const int tidm = tid >> 4;
    const int tidn = tid & 15;
    float acc[4][8];
#pragma unroll
    for (int i = 0; i < 4; i++)
#pragma unroll
        for (int c = 0; c < 8; c++) acc[i][c] = 0.f;

    for (int d = 0; d < 128; d++) {
        float a[4];
#pragma unroll
        for (int i = 0; i < 4; i++) a[i] = Ws[(tidm * 4 + i) * 132 + d];
        float bb[8];
        *(float4*)(bb)     = *(const float4*)&Wqs[d * 132 + tidn * 8];
        *(float4*)(bb + 4) = *(const float4*)&Wqs[d * 132 + tidn * 8 + 4];
#pragma unroll
        for (int i = 0; i < 4; i++)
#pragma unroll
            for (int c = 0; c < 8; c++)
                acc[i][c] += a[i] * bb[c];
    }

#pragma unroll
    for (int i = 0; i < 4; i++) {
        int rp = h * 256 + rpg * 64 + tidm * 4 + i;
        __half* o = Wc + (size_t)rp * 1024 + nt * 128 + tidn * 8;
#pragma unroll
        for (int c = 0; c < 8; c++)
            o[c] = __float2half(acc[i][c]);
        if (nt == 0 && tidn == 0) {
            int rpl = rpg * 64 + tidm * 4 + i;
            int j = rpl >> 1, br = rpl & 1;
            float bv = (br ? b2 : b1)[j];
            bc[rp] = br ? bv : bv * s1;
        }
    }
}

// ============================================================
// Tensor-core GEMM: C = A @ B^T (+bias)
// EPI==0: C fp32. EPI==3: hadamard pairs -> split fp16 tiles (N=2048).
// EPI==4: split fp16 tiles direct (N=1024, V path).
// ============================================================
#define ASTAGE 10240
#define STAGEB 20480
#define NSTG 4
#define GEMM_SMEM (NSTG * STAGEB)

template<int EPI>
__global__ __launch_bounds__(256, 2) void mma_gemm_kernel(
    const __half* __restrict__ A,
    const __half* __restrict__ B,
    const float* __restrict__ bias,
    float* __restrict__ Cf,
    __half* __restrict__ Ct,
    int N, int K, int ldA)
{
    extern __shared__ __align__(16) char dynsm[];
    const uint32_t sBase = smem_u32(dynsm);

    const int tid = threadIdx.x;
    const int lane = tid & 31;
    const int wid = tid >> 5;
    const int warp_m = (wid & 3) * 32;
    const int warp_n = (wid >> 2) * 64;
    const int bm0 = blockIdx.y * 128;
    const int bn0 = blockIdx.x * 128;
    const int NC = K >> 5;

    const size_t rowbA = (size_t)ldA * 2;
    const size_t rowbB = (size_t)K * 2;
    const char* Ag = (const char*)A + (size_t)bm0 * rowbA;
    const char* Bg = (const char*)B + (size_t)bn0 * rowbB;

    const int r0 = tid >> 2, g0 = tid & 3;
    const int r1 = (tid + 256) >> 2, g1 = (tid + 256) & 3;

    auto load_stage = [&](int kc, int s) {
        const size_t koff = (size_t)kc * 64;
        const uint32_t ab = sBase + (uint32_t)(s * STAGEB);
        const uint32_t bb = ab + ASTAGE;
        CPA16(ab + (uint32_t)(r0 * 80 + g0 * 16), Ag + (size_t)r0 * rowbA + koff + g0 * 16);
        CPA16(ab + (uint32_t)(r1 * 80 + g1 * 16), Ag + (size_t)r1 * rowbA + koff + g1 * 16);
        CPA16(bb + (uint32_t)(r0 * 80 + g0 * 16), Bg + (size_t)r0 * rowbB + koff + g0 * 16);
        CPA16(bb + (uint32_t)(r1 * 80 + g1 * 16), Bg + (size_t)r1 * rowbB + koff + g1 * 16);
        asm volatile("cp.async.commit_group;");
    };

    float acc[2][8][4];
#pragma unroll
    for (int mt = 0; mt < 2; mt++)
#pragma unroll
        for (int nt = 0; nt < 8; nt++)
#pragma unroll
            for (int j = 0; j < 4; j++) acc[mt][nt][j] = 0.f;

    load_stage(0, 0);
    load_stage(1, 1);
    load_stage(2, 2);

    const int lm = lane & 15;
    const int lk = lane >> 4;
    const uint32_t aOff = (uint32_t)((warp_m + lm) * 80 + lk * 16);
    const uint32_t bOff = (uint32_t)(ASTAGE + (warp_n + lm) * 80 + lk * 16);

    for (int kc = 0; kc < NC; kc++) {
        const int s = kc & (NSTG - 1);
        if (kc + 3 <= NC)      asm volatile("cp.async.wait_group 2;");
        else if (kc + 2 == NC) asm volatile("cp.async.wait_group 1;");
        else                   asm volatile("cp.async.wait_group 0;");
        __syncthreads();
        if (kc + 3 < NC) load_stage(kc + 3, (kc + 3) & (NSTG - 1));

        const uint32_t aSt = sBase + (uint32_t)(s * STAGEB) + aOff;
        const uint32_t bSt = sBase + (uint32_t)(s * STAGEB) + bOff;

#pragma unroll
        for (int ks = 0; ks < 2; ks++) {
            uint32_t a[2][4], bf[4][4];
#pragma unroll
            for (int mt = 0; mt < 2; mt++) {
                uint32_t ad = aSt + (uint32_t)(mt * 16 * 80 + ks * 32);
                LDSM(a[mt][0], a[mt][1], a[mt][2], a[mt][3], ad);
            }
#pragma unroll
            for (int ng = 0; ng < 4; ng++) {
                uint32_t bd = bSt + (uint32_t)(ng * 16 * 80 + ks * 32);
                LDSM(bf[ng][0], bf[ng][1], bf[ng][2], bf[ng][3], bd);
            }
#pragma unroll
            for (int mt = 0; mt < 2; mt++)
#pragma unroll
                for (int nt = 0; nt < 8; nt++) {
                    const int g = nt >> 1, sel = nt & 1;
                    MMA16816(acc[mt][nt], a[mt][0], a[mt][1], a[mt][2], a[mt][3],
                             bf[g][sel], bf[g][sel + 2]);
                }
        }
    }

    const int erow = bm0 + warp_m + (lane >> 2);
    const int ecol0 = bn0 + warp_n + (lane & 3) * 2;
#pragma unroll
    for (int nt = 0; nt < 8; nt++) {
        const int col = ecol0 + nt * 8;
        float bx = 0.f, by = 0.f;
        if (bias) { bx = bias[col]; by = bias[col + 1]; }
#pragma unroll
        for (int mt = 0; mt < 2; mt++) {
#pragma unroll
            for (int half = 0; half < 2; half++) {
                const int row = erow + mt * 16 + half * 8;
                float vx = acc[mt][nt][half * 2 + 0] + bx;
                float vy = acc[mt][nt][half * 2 + 1] + by;
                const int cc = row & 63;
                const int nn = (row >> 6) & 127;
                const int bb2 = row >> 13;
                if (EPI == 0) {
                    *(float2*)(Cf + (size_t)row * N + col) = make_float2(vx, vy);
                } else if (EPI == 3) {
                    // hadamard: (vx,vy) = (branch1, branch2) of feature j, head h
                    const int hh2 = col >> 8;
                    const int jj = (col & 255) >> 1;
                    size_t tb = ((size_t)((bb2 * 128 + nn) * 8 + hh2)) * 16384
                                + cc * 128 + jj;
                    float p = vx * vy;
                    __half hi = __float2half(p);
                    __half lo = __float2half(p - __half2float(hi));
                    Ct[tb] = hi;
                    Ct[tb + 8192] = lo;
                } else {
                    // V: direct split, cols (d, d+1) contiguous
                    const int hh2 = col >> 7;
                    const int dd = col & 127;
                    size_t tb = ((size_t)((bb2 * 128 + nn) * 8 + hh2)) * 16384
                                + cc * 128 + dd;
                    __half2 hv, lv;
                    hv.x = __float2half(vx);
                    hv.y = __float2half(vy);
                    lv.x = __float2half(vx - __half2float(hv.x));
                    lv.y = __float2half(vy - __half2float(hv.y));
                    *(__half2*)(Ct + tb)        = hv;
                    *(__half2*)(Ct + tb + 8192) = lv;
                }
            }
        }
    }
}

// ============================================================
// chunk_kv_mma: kv = k_c^T @ v_c, pre-split inputs via cp.async.
// smem: kS/vS [128][136] halfs (hi rows 0-63, lo 64-127).
// ============================================================
#define KV_SMEM (2 * 128 * 136 * 2)   // 69632

__global__ __launch_bounds__(256) void chunk_kv_mma(
    const __half* __restrict__ ks, const __half* __restrict__ vs,
    float* __restrict__ kv)
{
    extern __shared__ __align__(16) char sm[];
    __half* kS = (__half*)sm;
    const uint32_t kB = smem_u32(kS);
    const uint32_t vB = kB + 128 * 136 * 2;

    const int bid = blockIdx.x;
    const int tid = threadIdx.x;
    const int lane = tid & 31;
    const int wid = tid >> 5;

    const char* kt = (const char*)(ks + (size_t)bid * 16384);
    const char* vt = (const char*)(vs + (size_t)bid * 16384);
    for (int i = tid; i < 2048; i += 256) {
        int r = i >> 4, seg = i & 15;
        CPA16(kB + (uint32_t)(r * 272 + seg * 16), kt + r * 256 + seg * 16);
        CPA16(vB + (uint32_t)(r * 272 + seg * 16), vt + r * 256 + seg * 16);
    }
    asm volatile("cp.async.commit_group;");
    asm volatile("cp.async.wait_group 0;");
    __syncthreads();

    const int warp_m = (wid & 3) * 32;
    const int warp_n = (wid >> 2) * 64;
    const int krl = ((lane >> 4) << 3) + (lane & 7);
    const int mco = ((lane >> 3) & 1) << 3;

    float acc[2][8][4];
#pragma unroll
    for (int mt = 0; mt < 2; mt++)
#pragma unroll
        for (int nt = 0; nt < 8; nt++)
#pragma unroll
            for (int j = 0; j < 4; j++) acc[mt][nt][j] = 0.f;

#pragma unroll
    for (int kc = 0; kc < 12; kc++) {
        const int t = kc >> 2;
        const int cb = (kc & 3) << 4;
        const int ar = ((t == 1) ? 64 : 0) + cb;   // kh,kl,kh
        const int br = ((t == 2) ? 64 : 0) + cb;   // vh,vh,vl
        uint32_t a[2][4], bf[4][4];
#pragma unroll
        for (int mt = 0; mt < 2; mt++) {
            uint32_t ad = kB + (uint32_t)(((ar + krl) * 136 + warp_m + mt * 16 + mco) * 2);
            LDSM_T(a[mt][0], a[mt][1], a[mt][2], a[mt][3], ad);
        }
#pragma unroll
        for (int ng = 0; ng < 4; ng++) {
            uint32_t bd = vB + (uint32_t)(((br + krl) * 136 + warp_n + ng * 16 + mco) * 2);
            LDSM_T(bf[ng][0], bf[ng][1], bf[ng][2], bf[ng][3], bd);
        }
#pragma unroll
        for (int mt = 0; mt < 2; mt++)
#pragma unroll
            for (int nt = 0; nt < 8; nt++) {
                const int g = nt >> 1, sel = nt & 1;
                MMA16816(acc[mt][nt], a[mt][0], a[mt][1], a[mt][2], a[mt][3],
                         bf[g][sel], bf[g][sel + 2]);
            }
    }

    float* outp = kv + (size_t)bid * (DKV * DKV);
    const int er = warp_m + (lane >> 2);
    const int ec = warp_n + (lane & 3) * 2;
#pragma unroll
    for (int nt = 0; nt < 8; nt++)
#pragma unroll
        for (int mt = 0; mt < 2; mt++)
#pragma unroll
            for (int half = 0; half < 2; half++) {
                int row = er + mt * 16 + half * 8;
                *(float2*)(outp + row * 128 + ec + nt * 8) =
                    make_float2(acc[mt][nt][half * 2], acc[mt][nt][half * 2 + 1]);
            }
}

// ============================================================
// scan: exclusive prefix over chunks; writes split fp16 S tiles.
// ============================================================
__global__ void scan_kv_kernel(const float* __restrict__ kv,
                               __half* __restrict__ ss)
{
    int gid = blockIdx.x * blockDim.x + threadIdx.x;
    int e = gid & 16383;
    int h = (gid >> 14) % HH;
    int b = gid / (16384 * HH);
    size_t idx = (((size_t)b * NCH) * HH + h) * 16384 + e;
    const size_t stride = (size_t)HH * 16384;
    size_t oidx = ((size_t)(b * 128 * 8 + h)) * 32768 + e;
    const size_t ostride = (size_t)8 * 32768;
    float acc = 0.f;
    for (int n = 0; n < NCH; n++) {
        float x = kv[idx];
        __half hi = __float2half(acc);
        ss[oidx] = hi;
        ss[oidx + 16384] = __float2half(acc - __half2float(hi));
        acc += x;
        idx += stride;
        oidx += ostride;
    }
}

// ============================================================
// chunk_out_mma: A = tril(q k^T); o = A.v + q.S; RMSNorm; os fp16.
// All inputs pre-split fp16 tiles, loaded via cp.async. Stacked layouts.
// smem: qS [128][136] @0; Ap [128][136] @34816; vP [128][136] @69632;
//       sP [256][136] @104448 (kSm / oS reuse).
// ============================================================
#define CO_QS   0
#define CO_AP   34816
#define CO_VP   69632
#define CO_SP   104448
#define CO_SMEM (104448 + 256*136*2)   // 174080

__global__ __launch_bounds__(256) void chunk_out_mma(
    const __half* __restrict__ qs, const __half* __restrict__ ksrc,
    const __half* __restrict__ vs, const __half* __restrict__ ss,
    const float* __restrict__ rms_w, __half* __restrict__ os)
{
    extern __shared__ __align__(16) char sm[];
    float* oS = (float*)(sm + CO_SP);
    const uint32_t qB = smem_u32(sm) + CO_QS;
    const uint32_t aB = smem_u32(sm) + CO_AP;
    const uint32_t vB = smem_u32(sm) + CO_VP;
    const uint32_t sB = smem_u32(sm) + CO_SP;
    const uint32_t kB2 = sB;

    const int bid = blockIdx.x;
    const int h = bid % HH, n = (bid / HH) % NCH, b = bid / (HH * NCH);
    const int tid = threadIdx.x;
    const int lane = tid & 31;
    const int wid = tid >> 5;

    // ---- phase 1: cp.async q, k tiles ----
    const char* qt = (const char*)(qs + (size_t)bid * 16384);
    const char* kt = (const char*)(ksrc + (size_t)bid * 16384);
    for (int i = tid; i < 2048; i += 256) {
        int r = i >> 4, seg = i & 15;
        CPA16(qB + (uint32_t)(r * 272 + seg * 16), qt + r * 256 + seg * 16);
        CPA16(kB2 + (uint32_t)(r * 272 + seg * 16), kt + r * 256 + seg * 16);
    }
    asm volatile("cp.async.commit_group;");
    asm volatile("cp.async.wait_group 0;");
    __syncthreads();

    const int krl = ((lane >> 4) << 3) + (lane & 7);
    const int mco = ((lane >> 3) & 1) << 3;

    // ---- phase 2: A = q.k^T (3 products via row offsets) ----
    {
        const int wmA = (wid & 1) * 32;
        const int wnA = (wid >> 1) * 16;
        float accA[2][2][4];
#pragma unroll
        for (int mt = 0; mt < 2; mt++)
#pragma unroll
            for (int nt = 0; nt < 2; nt++)
#pragma unroll
                for (int j = 0; j < 4; j++) accA[mt][nt][j] = 0.f;

#pragma unroll
        for (int kc = 0; kc < 24; kc++) {
            const int t = kc >> 3;
            const int cb = (kc & 7) << 4;
            const int tq = (t == 1) ? 64 : 0;   // qh,ql,qh
            const int tk = (t == 2) ? 64 : 0;   // kh,kh,kl
            uint32_t a[2][4], bf[4];
#pragma unroll
            for (int mt = 0; mt < 2; mt++) {
                uint32_t ad = qB + (uint32_t)(((tq + wmA + mt * 16 + (lane & 15)) * 136
                                               + cb + ((lane >> 4) << 3)) * 2);
                LDSM(a[mt][0], a[mt][1], a[mt][2], a[mt][3], ad);
            }
            uint32_t bd = kB2 + (uint32_t)(((tk + wnA + (lane & 15)) * 136
                                            + cb + ((lane >> 4) << 3)) * 2);
            LDSM(bf[0], bf[1], bf[2], bf[3], bd);
#pragma unroll
            for (int mt = 0; mt < 2; mt++)
#pragma unroll
                for (int nt = 0; nt < 2; nt++)
                    MMA16816(accA[mt][nt], a[mt][0], a[mt][1], a[mt][2], a[mt][3],
                             bf[nt], bf[nt + 2]);
        }

        // masked write, stacked: Ah rows 0-63, Al rows 64-127
        const int er = wmA + (lane >> 2);
        const int ec = wnA + (lane & 3) * 2;
        __half* Ap = (__half*)(sm + CO_AP);
#pragma unroll
        for (int mt = 0; mt < 2; mt++)
#pragma unroll
            for (int nt = 0; nt < 2; nt++)
#pragma unroll
                for (int half = 0; half < 2; half++) {
                    int r = er + mt * 16 + half * 8;
                    int c = ec + nt * 8;
                    float v0 = (c     <= r) ? accA[mt][nt][half * 2 + 0] : 0.f;
                    float v1 = (c + 1 <= r) ? accA[mt][nt][half * 2 + 1] : 0.f;
                    __half2 hv, lv;
                    hv.x = __float2half(v0);
                    hv.y = __float2half(v1);
                    lv.x = __float2half(v0 - __half2float(hv.x));
                    lv.y = __float2half(v1 - __half2float(hv.y));
                    *(__half2*)(Ap + r * 136 + c)        = hv;
                    *(__half2*)(Ap + (r + 64) * 136 + c) = lv;
                }
    }
    __syncthreads();   // A' done; kSm region free

    // ---- phase 3: cp.async v, S tiles ----
    const char* vt = (const char*)(vs + (size_t)bid * 16384);
    const char* st = (const char*)(ss + (size_t)bid * 32768);
    for (int i = tid; i < 2048; i += 256) {
        int r = i >> 4, seg = i & 15;
        CPA16(vB + (uint32_t)(r * 272 + seg * 16), vt + r * 256 + seg * 16);
    }
    for (int i = tid; i < 4096; i += 256) {
        int r = i >> 4, seg = i & 15;
        CPA16(sB + (uint32_t)(r * 272 + seg * 16), st + r * 256 + seg * 16);
    }
    asm volatile("cp.async.commit_group;");
    asm volatile("cp.async.wait_group 0;");
    __syncthreads();

    // ---- phase 4: o = A'.v' + q.S' ----
    const int warp_m = (wid & 1) * 32;
    const int warp_n = (wid >> 1) * 32;
    float acc[2][4][4];
#pragma unroll
    for (int mt = 0; mt < 2; mt++)
#pragma unroll
        for (int nt = 0; nt < 4; nt++)
#pragma unroll
            for (int j = 0; j < 4; j++) acc[mt][nt][j] = 0.f;

#pragma unroll
    for (int kc = 0; kc < 12; kc++) {       // A'.v' : Ah.vh + Al.vh + Ah.vl
        const int t = kc >> 2;
        const int cb = (kc & 3) << 4;
        const int ta = (t == 1) ? 64 : 0;
        const int br = ((t == 2) ? 64 : 0) + cb;
        uint32_t a[2][4], bf[2][4];
#pragma unroll
        for (int mt = 0; mt < 2; mt++) {
            uint32_t ad = aB + (uint32_t)(((ta + warp_m + mt * 16 + (lane & 15)) * 136
                                           + cb + ((lane >> 4) << 3)) * 2);
            LDSM(a[mt][0], a[mt][1], a[mt][2], a[mt][3], ad);
        }
#pragma unroll
        for (int ng = 0; ng < 2; ng++) {
            uint32_t bd = vB + (uint32_t)(((br + krl) * 136 + warp_n + ng * 16 + mco) * 2);
            LDSM_T(bf[ng][0], bf[ng][1], bf[ng][2], bf[ng][3], bd);
        }
#pragma unroll
        for (int mt = 0; mt < 2; mt++)
#pragma unroll
            for (int nt = 0; nt < 4; nt++) {
                const int g = nt >> 1, sel = nt & 1;
                MMA16816(acc[mt][nt], a[mt][0], a[mt][1], a[mt][2], a[mt][3],
                         bf[g][sel], bf[g][sel + 2]);
            }
    }
#pragma unroll
    for (int kc = 0; kc < 24; kc++) {       // q.S' : qh.Sh + ql.Sh + qh.Sl
        const int t = kc >> 3;
        const int cb = (kc & 7) << 4;
        const int tq = (t == 1) ? 64 : 0;
        const int sr = ((t == 2) ? 128 : 0) + cb;
        uint32_t a[2][4], bf[2][4];
#pragma unroll
        for (int mt = 0; mt < 2; mt++) {
            uint32_t ad = qB + (uint32_t)(((tq + warp_m + mt * 16 + (lane & 15)) * 136
                                           + cb + ((lane >> 4) << 3)) * 2);
            LDSM(a[mt][0], a[mt][1], a[mt][2], a[mt][3], ad);
        }
#pragma unroll
        for (int ng = 0; ng < 2; ng++) {
            uint32_t bd = sB + (uint32_t)(((sr + krl) * 136 + warp_n + ng * 16 + mco) * 2);
            LDSM_T(bf[ng][0], bf[ng][1], bf[ng][2], bf[ng][3], bd);
        }
#pragma unroll
        for (int mt = 0; mt < 2; mt++)
#pragma unroll
            for (int nt = 0; nt < 4; nt++) {
                const int g = nt >> 1, sel = nt & 1;
                MMA16816(acc[mt][nt], a[mt][0], a[mt][1], a[mt][2], a[mt][3],
                         bf[g][sel], bf[g][sel + 2]);
            }
    }

    // ---- phase 5: stage o fp32 (reuses S' region) ----
    __syncthreads();
    {
        const int er = warp_m + (lane >> 2);
        const int ec = warp_n + (lane & 3) * 2;
#pragma unroll
        for (int mt = 0; mt < 2; mt++)
#pragma unroll
            for (int nt = 0; nt < 4; nt++)
#pragma unroll
                for (int half = 0; half < 2; half++) {
                    int r = er + mt * 16 + half * 8;
                    *(float2*)(oS + r * 132 + ec + nt * 8) =
                        make_float2(acc[mt][nt][half * 2], acc[mt][nt][half * 2 + 1]);
                }
    }
    __syncthreads();

    // ---- phase 6: RMSNorm + fp16 write ----
    {
        const int r = tid >> 2;
        const int part = tid & 3;
        float vals[32];
        float s = 0.f;
#pragma unroll
        for (int j = 0; j < 32; j += 4) {
            float4 x = *(const float4*)(oS + r * 132 + part * 32 + j);
            vals[j] = x.x; vals[j+1] = x.y; vals[j+2] = x.z; vals[j+3] = x.w;
            s += x.x*x.x + x.y*x.y + x.z*x.z + x.w*x.w;
        }
        s += __shfl_xor_sync(0xffffffffu, s, 1);
        s += __shfl_xor_sync(0xffffffffu, s, 2);
        float scale = rsqrtf(s * (1.0f / 128.0f) + EPS);
        size_t R = (size_t)b * TT + (size_t)n * CHUNK + r;
        __half* p = os + R * 1024 + h * 128 + part * 32;
#pragma unroll
        for (int j = 0; j < 32; j += 2) {
            float vx = vals[j]   * scale * rms_w[part * 32 + j];
            float vy = vals[j+1] * scale * rms_w[part * 32 + j + 1];
            __half2 hv;
            hv.x = __float2half(vx);
            hv.y = __float2half(vy);
            *(__half2*)(p + j) = hv;
        }
    }
}

// ============================================================
// Launch
// ============================================================
extern "C" void kernel_launch(void* const* d_in, const int* in_sizes, int n_in,
                              void* d_out, int out_size)
{
    const float* x      = (const float*)d_in[0];
    const float* Wq     = (const float*)d_in[1];
    const float* Wk     = (const float*)d_in[2];
    const float* Wv     = (const float*)d_in[3];
    const float* fmq_w1 = (const float*)d_in[4];
    const float* fmq_b1 = (const float*)d_in[5];
    const float* fmq_w2 = (const float*)d_in[6];
    const float* fmq_b2 = (const float*)d_in[7];
    const float* fmk_w1 = (const float*)d_in[8];
    const float* fmk_b1 = (const float*)d_in[9];
    const float* fmk_w2 = (const float*)d_in[10];
    const float* fmk_b2 = (const float*)d_in[11];
    const float* rms_w  = (const float*)d_in[12];
    const float* Wo     = (const float*)d_in[13];
    float* out = (float*)d_out;

    float *bKV, *bcq, *bck;
    cudaGetSymbolAddress((void**)&bKV, g_kv);
    cudaGetSymbolAddress((void**)&bcq, g_bcq);
    cudaGetSymbolAddress((void**)&bck, g_bck);

    __half *x16, *wv16, *wo16, *os, *wcq, *wck, *qs, *ks, *vs, *ssb;
    cudaGetSymbolAddress((void**)&x16,  g_x16);
    cudaGetSymbolAddress((void**)&wv16, g_wv16);
    cudaGetSymbolAddress((void**)&wo16, g_wo16);
    cudaGetSymbolAddress((void**)&os,   g_os);
    cudaGetSymbolAddress((void**)&wcq,  g_wcq);
    cudaGetSymbolAddress((void**)&wck,  g_wck);
    cudaGetSymbolAddress((void**)&qs,   g_qs);
    cudaGetSymbolAddress((void**)&ks,   g_ks);
    cudaGetSymbolAddress((void**)&vs,   g_vs);
    cudaGetSymbolAddress((void**)&ssb,  g_ss);

    cudaFuncSetAttribute(composite_kernel, cudaFuncAttributeMaxDynamicSharedMemorySize, COMP_SMEM);
    cudaFuncSetAttribute(chunk_kv_mma,  cudaFuncAttributeMaxDynamicSharedMemorySize, KV_SMEM);
    cudaFuncSetAttribute(chunk_out_mma, cudaFuncAttributeMaxDynamicSharedMemorySize, CO_SMEM);
    cudaFuncSetAttribute(mma_gemm_kernel<0>, cudaFuncAttributeMaxDynamicSharedMemorySize, GEMM_SMEM);
    cudaFuncSetAttribute(mma_gemm_kernel<3>, cudaFuncAttributeMaxDynamicSharedMemorySize, GEMM_SMEM);
    cudaFuncSetAttribute(mma_gemm_kernel<4>, cudaFuncAttributeMaxDynamicSharedMemorySize, GEMM_SMEM);

    // ---- converts ----
    tof16_kernel<<<(MROWS * HID) / 512, 256>>>(x, x16, (size_t)MROWS * HID);
    tof16_kernel<<<(HID * HID) / 512, 256>>>(Wv, wv16, (size_t)HID * HID);
    tof16_kernel<<<(HID * HID) / 512, 256>>>(Wo, wo16, (size_t)HID * HID);

    // ---- composite fm∘proj weights (q-scale folded) ----
    const float scale = 0.08838834764831845f; // 128^-0.5
    dim3 gComp(8, 4, 8);
    composite_kernel<<<gComp, 256, COMP_SMEM>>>(fmq_w1, fmq_w2, fmq_b1, fmq_b2, Wq, wcq, bcq, scale);
    composite_kernel<<<gComp, 256, COMP_SMEM>>>(fmk_w1, fmk_w2, fmk_b1, fmk_b2, Wk, wck, bck, 1.0f);

    // ---- projections: emit pre-split fp16 tiles ----
    dim3 gQK(2 * HID / 128, MROWS / 128);   // (16, 128)
    dim3 gBig(HID / 128, MROWS / 128);      // (8, 128)
    mma_gemm_kernel<3><<<gQK, 256, GEMM_SMEM>>>(x16, wcq, bcq, nullptr, qs, 2 * HID, HID, HID);
    mma_gemm_kernel<3><<<gQK, 256, GEMM_SMEM>>>(x16, wck, bck, nullptr, ks, 2 * HID, HID, HID);
    mma_gemm_kernel<4><<<gBig, 256, GEMM_SMEM>>>(x16, wv16, nullptr, nullptr, vs, HID, HID, HID);

    // ---- chunked linear attention ----
    const int nBlk = BB * NCH * HH;
    chunk_kv_mma<<<nBlk, 256, KV_SMEM>>>(ks, vs, bKV);
    scan_kv_kernel<<<(BB * HH * 16384) / 256, 256>>>(bKV, ssb);
    chunk_out_mma<<<nBlk, 256, CO_SMEM>>>(qs, ks, vs, ssb, rms_w, os);

    // ---- output projection ----
    mma_gemm_kernel<0><<<gBig, 256, GEMM_SMEM>>>(os, wo16, nullptr, out, nullptr, HID, HID, HID);
}

// round 17
// speedup vs baseline: 4.2902x; 1.0492x over previous
#include <cuda_runtime.h>
#include <cuda_fp16.h>
#include <cstddef>
#include <cstdint>

// Problem constants
#define BB 2
#define TT 8192
#define HH 8
#define DKV 128
#define HID 1024
#define CHUNK 64
#define NCH 128           // TT / CHUNK
#define MROWS (BB*TT)     // 16384
#define EPS 1e-5f

// -------- scratch --------
__device__ float  g_kv[(size_t)BB * NCH * HH * DKV * DKV];      // fp32 chunk kv sums
__device__ __half g_x16 [(size_t)MROWS * HID];                  // x fp16
__device__ __half g_wv16[(size_t)HID * HID];                    // Wv hi
__device__ __half g_wo16[(size_t)HID * HID];                    // Wo hi
__device__ __half g_os  [(size_t)MROWS * HID];                  // attention out fp16
__device__ __half g_wc  [(size_t)4 * HID * HID];                // composite q|k weights [4096,1024]
__device__ float  g_bc[4 * HID];                                // composite q|k bias
// pre-split tiles: per (b,n,h): [hi rows 0-63 | lo rows 64-127] x 128 d, 16384 halfs
__device__ __half g_qs[(size_t)BB * NCH * HH * 16384];
__device__ __half g_ks[(size_t)BB * NCH * HH * 16384];
__device__ __half g_vs[(size_t)BB * NCH * HH * 16384];
// S tiles: per (b,n,h): [Sh rows 0-127 | Sl rows 128-255] x 128, 32768 halfs
__device__ __half g_ss[(size_t)BB * NCH * HH * 32768];

__device__ __forceinline__ uint32_t smem_u32(const void* p) {
    uint32_t a;
    asm("{ .reg .u64 t; cvta.to.shared.u64 t, %1; cvt.u32.u64 %0, t; }"
        : "=r"(a) : "l"(p));
    return a;
}

#define CPA16(dst, src) \
    asm volatile("cp.async.cg.shared.global [%0], [%1], 16;" :: "r"(dst), "l"(src))
#define LDSM(r0,r1,r2,r3,addr) \
    asm volatile("ldmatrix.sync.aligned.m8n8.x4.shared.b16 {%0,%1,%2,%3}, [%4];" \
                 : "=r"(r0),"=r"(r1),"=r"(r2),"=r"(r3) : "r"(addr))
#define LDSM_T(r0,r1,r2,r3,addr) \
    asm volatile("ldmatrix.sync.aligned.m8n8.x4.trans.shared.b16 {%0,%1,%2,%3}, [%4];" \
                 : "=r"(r0),"=r"(r1),"=r"(r2),"=r"(r3) : "r"(addr))
#define MMA16816(acc,a0,a1,a2,a3,b0,b1) \
    asm volatile("mma.sync.aligned.m16n8k16.row.col.f32.f16.f16.f32 " \
                 "{%0,%1,%2,%3}, {%4,%5,%6,%7}, {%8,%9}, {%0,%1,%2,%3};" \
                 : "+f"((acc)[0]), "+f"((acc)[1]), "+f"((acc)[2]), "+f"((acc)[3]) \
                 : "r"(a0), "r"(a1), "r"(a2), "r"(a3), "r"(b0), "r"(b1))

// ============================================================
// tof16
// ============================================================
__global__ void tof16_kernel(const float* __restrict__ in,
                             __half* __restrict__ out, size_t total)
{
    size_t i = ((size_t)blockIdx.x * blockDim.x + threadIdx.x) * 2;
    if (i >= total) return;
    float2 x = *(const float2*)(in + i);
    __half2 hv;
    hv.x = __float2half(x.x);
    hv.y = __float2half(x.y);
    *(__half2*)(out + i) = hv;
}

// ============================================================
// composite_kernel (register-tiled)
// ============================================================
#define COMP_SMEM ((128 * 132 + 64 * 132) * 4)   // 101376

__global__ __launch_bounds__(256) void composite_kernel(
    const float* __restrict__ w1, const float* __restrict__ w2,
    const float* __restrict__ b1, const float* __restrict__ b2,
    const float* __restrict__ Wp,
    __half* __restrict__ Wc, float* __restrict__ bc, float s1)
{
    extern __shared__ float smco[];
    float* Wqs = smco;
    float* Ws  = smco + 128 * 132;
    const int nt = blockIdx.x;
    const int rpg = blockIdx.y;
    const int h = blockIdx.z;
    const int tid = threadIdx.x;

    for (int i = tid; i < 128 * 128; i += 256) {
        int d = i >> 7, c = i & 127;
        Wqs[d * 132 + c] = Wp[(size_t)(h * 128 + d) * 1024 + nt * 128 + c];
    }
    for (int i = tid; i < 64 * 128; i += 256) {
        int l = i >> 7, d = i & 127;
        int rpl = rpg * 64 + l;
        int j = rpl >> 1, br = rpl & 1;
        float wv = (br ? w2 : w1)[j * 128 + d];
        if (br == 0) wv *= s1;
        Ws[l * 132 + d] = wv;
    }
    __syncthreads();

    const int tidm = tid >> 4;
    const int tidn = tid & 15;
    float acc[4][8];
#pragma unroll
    for (int i = 0; i < 4; i++)
#pragma unroll
        for (int c = 0; c < 8; c++) acc[i][c] = 0.f;

    for (int d = 0; d < 128; d++) {
        float a[4];
#pragma unroll
        for (int i = 0; i < 4; i++) a[i] = Ws[(tidm * 4 + i) * 132 + d];
        float bb[8];
        *(float4*)(bb)     = *(const float4*)&Wqs[d * 132 + tidn * 8];
        *(float4*)(bb + 4) = *(const float4*)&Wqs[d * 132 + tidn * 8 + 4];
#pragma unroll
        for (int i = 0; i < 4; i++)
#pragma unroll
            for (int c = 0; c < 8; c++)
                acc[i][c] += a[i] * bb[c];
    }

#pragma unroll
    for (int i = 0; i < 4; i++) {
        int rp = h * 256 + rpg * 64 + tidm * 4 + i;
        __half* o = Wc + (size_t)rp * 1024 + nt * 128 + tidn * 8;
#pragma unroll
        for (int c = 0; c < 8; c++)
            o[c] = __float2half(acc[i][c]);
        if (nt == 0 && tidn == 0) {
            int rpl = rpg * 64 + tidm * 4 + i;
            int j = rpl >> 1, br = rpl & 1;
            float bv = (br ? b2 : b1)[j];
            bc[rp] = br ? bv : bv * s1;
        }
    }
}

// ============================================================
// Tensor-core GEMM: C = A @ B^T (+bias)
// EPI==0: C fp32.
// EPI==3: hadamard pairs -> split fp16 tiles (merged q|k, N=4096):
//         head idx 0-7 -> Ct (qs), 8-15 -> Ct2 (ks)
// EPI==4: split fp16 tiles direct (N=1024, V path).
// ============================================================
#define ASTAGE 10240
#define STAGEB 20480
#define NSTG 4
#define GEMM_SMEM (NSTG * STAGEB)

template<int EPI>
__global__ __launch_bounds__(256, 2) void mma_gemm_kernel(
    const __half* __restrict__ A,
    const __half* __restrict__ B,
    const float* __restrict__ bias,
    float* __restrict__ Cf,
    __half* __restrict__ Ct,
    __half* __restrict__ Ct2,
    int N, int K, int ldA)
{
    extern __shared__ __align__(16) char dynsm[];
    const uint32_t sBase = smem_u32(dynsm);

    const int tid = threadIdx.x;
    const int lane = tid & 31;
    const int wid = tid >> 5;
    const int warp_m = (wid & 3) * 32;
    const int warp_n = (wid >> 2) * 64;
    const int bm0 = blockIdx.y * 128;
    const int bn0 = blockIdx.x * 128;
    const int NC = K >> 5;

    const size_t rowbA = (size_t)ldA * 2;
    const size_t rowbB = (size_t)K * 2;
    const char* Ag = (const char*)A + (size_t)bm0 * rowbA;
    const char* Bg = (const char*)B + (size_t)bn0 * rowbB;

    const int r0 = tid >> 2, g0 = tid & 3;
    const int r1 = (tid + 256) >> 2, g1 = (tid + 256) & 3;

    auto load_stage = [&](int kc, int s) {
        const size_t koff = (size_t)kc * 64;
        const uint32_t ab = sBase + (uint32_t)(s * STAGEB);
        const uint32_t bb = ab + ASTAGE;
        CPA16(ab + (uint32_t)(r0 * 80 + g0 * 16), Ag + (size_t)r0 * rowbA + koff + g0 * 16);
        CPA16(ab + (uint32_t)(r1 * 80 + g1 * 16), Ag + (size_t)r1 * rowbA + koff + g1 * 16);
        CPA16(bb + (uint32_t)(r0 * 80 + g0 * 16), Bg + (size_t)r0 * rowbB + koff + g0 * 16);
        CPA16(bb + (uint32_t)(r1 * 80 + g1 * 16), Bg + (size_t)r1 * rowbB + koff + g1 * 16);
        asm volatile("cp.async.commit_group;");
    };

    float acc[2][8][4];
#pragma unroll
    for (int mt = 0; mt < 2; mt++)
#pragma unroll
        for (int nt = 0; nt < 8; nt++)
#pragma unroll
            for (int j = 0; j < 4; j++) acc[mt][nt][j] = 0.f;

    load_stage(0, 0);
    load_stage(1, 1);
    load_stage(2, 2);

    const int lm = lane & 15;
    const int lk = lane >> 4;
    const uint32_t aOff = (uint32_t)((warp_m + lm) * 80 + lk * 16);
    const uint32_t bOff = (uint32_t)(ASTAGE + (warp_n + lm) * 80 + lk * 16);

    for (int kc = 0; kc < NC; kc++) {
        const int s = kc & (NSTG - 1);
        if (kc + 3 <= NC)      asm volatile("cp.async.wait_group 2;");
        else if (kc + 2 == NC) asm volatile("cp.async.wait_group 1;");
        else                   asm volatile("cp.async.wait_group 0;");
        __syncthreads();
        if (kc + 3 < NC) load_stage(kc + 3, (kc + 3) & (NSTG - 1));

        const uint32_t aSt = sBase + (uint32_t)(s * STAGEB) + aOff;
        const uint32_t bSt = sBase + (uint32_t)(s * STAGEB) + bOff;

#pragma unroll
        for (int ks = 0; ks < 2; ks++) {
            uint32_t a[2][4], bf[4][4];
#pragma unroll
            for (int mt = 0; mt < 2; mt++) {
                uint32_t ad = aSt + (uint32_t)(mt * 16 * 80 + ks * 32);
                LDSM(a[mt][0], a[mt][1], a[mt][2], a[mt][3], ad);
            }
#pragma unroll
            for (int ng = 0; ng < 4; ng++) {
                uint32_t bd = bSt + (uint32_t)(ng * 16 * 80 + ks * 32);
                LDSM(bf[ng][0], bf[ng][1], bf[ng][2], bf[ng][3], bd);
            }
#pragma unroll
            for (int mt = 0; mt < 2; mt++)
#pragma unroll
                for (int nt = 0; nt < 8; nt++) {
                    const int g = nt >> 1, sel = nt & 1;
                    MMA16816(acc[mt][nt], a[mt][0], a[mt][1], a[mt][2], a[mt][3],
                             bf[g][sel], bf[g][sel + 2]);
                }
        }
    }

    const int erow = bm0 + warp_m + (lane >> 2);
    const int ecol0 = bn0 + warp_n + (lane & 3) * 2;
#pragma unroll
    for (int nt = 0; nt < 8; nt++) {
        const int col = ecol0 + nt * 8;
        float bx = 0.f, by = 0.f;
        if (bias) { bx = bias[col]; by = bias[col + 1]; }
#pragma unroll
        for (int mt = 0; mt < 2; mt++) {
#pragma unroll
            for (int half = 0; half < 2; half++) {
                const int row = erow + mt * 16 + half * 8;
                float vx = acc[mt][nt][half * 2 + 0] + bx;
                float vy = acc[mt][nt][half * 2 + 1] + by;
                const int cc = row & 63;
                const int nn = (row >> 6) & 127;
                const int bb2 = row >> 13;
                if (EPI == 0) {
                    *(float2*)(Cf + (size_t)row * N + col) = make_float2(vx, vy);
                } else if (EPI == 3) {
                    // merged q|k hadamard: head idx = col>>8 (0-15)
                    const int hh2 = col >> 8;
                    const int jj = (col & 255) >> 1;
                    __half* tp = (hh2 < 8) ? Ct : Ct2;
                    const int hd = hh2 & 7;
                    size_t tb = ((size_t)((bb2 * 128 + nn) * 8 + hd)) * 16384
                                + cc * 128 + jj;
                    float p = vx * vy;
                    __half hi = __float2half(p);
                    __half lo = __float2half(p - __half2float(hi));
                    tp[tb] = hi;
                    tp[tb + 8192] = lo;
                } else {
                    // V: direct split, cols (d, d+1) contiguous
                    const int hh2 = col >> 7;
                    const int dd = col & 127;
                    size_t tb = ((size_t)((bb2 * 128 + nn) * 8 + hh2)) * 16384
                                + cc * 128 + dd;
                    __half2 hv, lv;
                    hv.x = __float2half(vx);
                    hv.y = __float2half(vy);
                    lv.x = __float2half(vx - __half2float(hv.x));
                    lv.y = __float2half(vy - __half2float(hv.y));
                    *(__half2*)(Ct + tb)        = hv;
                    *(__half2*)(Ct + tb + 8192) = lv;
                }
            }
        }
    }
}

// ============================================================
// chunk_kv_mma: kv = k_c^T @ v_c, pre-split inputs via cp.async.
// 2 CTAs/SM for load/MMA overlap across CTAs.
// ============================================================
#define KV_SMEM (2 * 128 * 136 * 2)   // 69632

__global__ __launch_bounds__(256, 2) void chunk_kv_mma(
    const __half* __restrict__ ks, const __half* __restrict__ vs,
    float* __restrict__ kv)
{
    extern __shared__ __align__(16) char sm[];
    const uint32_t kB = smem_u32(sm);
    const uint32_t vB = kB + 128 * 136 * 2;

    const int bid = blockIdx.x;
    const int tid = threadIdx.x;
    const int lane = tid & 31;
    const int wid = tid >> 5;

    const char* kt = (const char*)(ks + (size_t)bid * 16384);
    const char* vt = (const char*)(vs + (size_t)bid * 16384);
    for (int i = tid; i < 2048; i += 256) {
        int r = i >> 4, seg = i & 15;
        CPA16(kB + (uint32_t)(r * 272 + seg * 16), kt + r * 256 + seg * 16);
        CPA16(vB + (uint32_t)(r * 272 + seg * 16), vt + r * 256 + seg * 16);
    }
    asm volatile("cp.async.commit_group;");
    asm volatile("cp.async.wait_group 0;");
    __syncthreads();

    const int warp_m = (wid & 3) * 32;
    const int warp_n = (wid >> 2) * 64;
    const int krl = ((lane >> 4) << 3) + (lane & 7);
    const int mco = ((lane >> 3) & 1) << 3;

    float acc[2][8][4];
#pragma unroll
    for (int mt = 0; mt < 2; mt++)
#pragma unroll
        for (int nt = 0; nt < 8; nt++)
#pragma unroll
            for (int j = 0; j < 4; j++) acc[mt][nt][j] = 0.f;

#pragma unroll
    for (int kc = 0; kc < 12; kc++) {
        const int t = kc >> 2;
        const int cb = (kc & 3) << 4;
        const int ar = ((t == 1) ? 64 : 0) + cb;   // kh,kl,kh
        const int br = ((t == 2) ? 64 : 0) + cb;   // vh,vh,vl
        uint32_t a[2][4], bf[4][4];
#pragma unroll
        for (int mt = 0; mt < 2; mt++) {
            uint32_t ad = kB + (uint32_t)(((ar + krl) * 136 + warp_m + mt * 16 + mco) * 2);
            LDSM_T(a[mt][0], a[mt][1], a[mt][2], a[mt][3], ad);
        }
#pragma unroll
        for (int ng = 0; ng < 4; ng++) {
            uint32_t bd = vB + (uint32_t)(((br + krl) * 136 + warp_n + ng * 16 + mco) * 2);
            LDSM_T(bf[ng][0], bf[ng][1], bf[ng][2], bf[ng][3], bd);
        }
#pragma unroll
        for (int mt = 0; mt < 2; mt++)
#pragma unroll
            for (int nt = 0; nt < 8; nt++) {
                const int g = nt >> 1, sel = nt & 1;
                MMA16816(acc[mt][nt], a[mt][0], a[mt][1], a[mt][2], a[mt][3],
                         bf[g][sel], bf[g][sel + 2]);
            }
    }

    float* outp = kv + (size_t)bid * (DKV * DKV);
    const int er = warp_m + (lane >> 2);
    const int ec = warp_n + (lane & 3) * 2;
#pragma unroll
    for (int nt = 0; nt < 8; nt++)
#pragma unroll
        for (int mt = 0; mt < 2; mt++)
#pragma unroll
            for (int half = 0; half < 2; half++) {
                int row = er + mt * 16 + half * 8;
                *(float2*)(outp + row * 128 + ec + nt * 8) =
                    make_float2(acc[mt][nt][half * 2], acc[mt][nt][half * 2 + 1]);
            }
}

// ============================================================
// scan: exclusive prefix over chunks; writes split fp16 S tiles.
// ============================================================
__global__ void scan_kv_kernel(const float* __restrict__ kv,
                               __half* __restrict__ ss)
{
    int gid = blockIdx.x * blockDim.x + threadIdx.x;
    int e = gid & 16383;
    int h = (gid >> 14) % HH;
    int b = gid / (16384 * HH);
    size_t idx = (((size_t)b * NCH) * HH + h) * 16384 + e;
    const size_t stride = (size_t)HH * 16384;
    size_t oidx = ((size_t)(b * 128 * 8 + h)) * 32768 + e;
    const size_t ostride = (size_t)8 * 32768;
    float acc = 0.f;
    for (int n = 0; n < NCH; n++) {
        float x = kv[idx];
        __half hi = __float2half(acc);
        ss[oidx] = hi;
        ss[oidx + 16384] = __float2half(acc - __half2float(hi));
        acc += x;
        idx += stride;
        oidx += ostride;
    }
}

// ============================================================
// chunk_out_mma: A = tril(q k^T); o = A.v + q.S; RMSNorm; os fp16.
// v/S loads overlapped with A-phase compute (dedicated kS region).
// smem: qS @0 (34816); Ap @34816; vP @69632; sP @104448 (69632, oS reuse);
//       kS @174080 (34816). Total 208896.
// ============================================================
#define CO_QS   0
#define CO_AP   34816
#define CO_VP   69632
#define CO_SP   104448
#define CO_KS   174080
#define CO_SMEM (174080 + 34816)   // 208896

__global__ __launch_bounds__(256) void chunk_out_mma(
    const __half* __restrict__ qs, const __half* __restrict__ ksrc,
    const __half* __restrict__ vs, const __half* __restrict__ ss,
    const float* __restrict__ rms_w, __half* __restrict__ os)
{
    extern __shared__ __align__(16) char sm[];
    float* oS = (float*)(sm + CO_SP);
    const uint32_t base_s = smem_u32(sm);
    const uint32_t qB = base_s + CO_QS;
    const uint32_t aB = base_s + CO_AP;
    const uint32_t vB = base_s + CO_VP;
    const uint32_t sB = base_s + CO_SP;
    const uint32_t kB2 = base_s + CO_KS;

    const int bid = blockIdx.x;
    const int h = bid % HH, n = (bid / HH) % NCH, b = bid / (HH * NCH);
    const int tid = threadIdx.x;
    const int lane = tid & 31;
    const int wid = tid >> 5;

    // ---- phase 1: cp.async q,k (group 0), then v,S (group 1) ----
    const char* qt = (const char*)(qs + (size_t)bid * 16384);
    const char* kt = (const char*)(ksrc + (size_t)bid * 16384);
    for (int i = tid; i < 2048; i += 256) {
        int r = i >> 4, seg = i & 15;
        CPA16(qB + (uint32_t)(r * 272 + seg * 16), qt + r * 256 + seg * 16);
        CPA16(kB2 + (uint32_t)(r * 272 + seg * 16), kt + r * 256 + seg * 16);
    }
    asm volatile("cp.async.commit_group;");
    const char* vt = (const char*)(vs + (size_t)bid * 16384);
    const char* st = (const char*)(ss + (size_t)bid * 32768);
    for (int i = tid; i < 2048; i += 256) {
        int r = i >> 4, seg = i & 15;
        CPA16(vB + (uint32_t)(r * 272 + seg * 16), vt + r * 256 + seg * 16);
    }
    for (int i = tid; i < 4096; i += 256) {
        int r = i >> 4, seg = i & 15;
        CPA16(sB + (uint32_t)(r * 272 + seg * 16), st + r * 256 + seg * 16);
    }
    asm volatile("cp.async.commit_group;");
    asm volatile("cp.async.wait_group 1;");   // q,k ready; v,S in flight
    __syncthreads();

    const int krl = ((lane >> 4) << 3) + (lane & 7);
    const int mco = ((lane >> 3) & 1) << 3;

    // ---- phase 2: A = q.k^T (overlapped with v/S loads) ----
    {
        const int wmA = (wid & 1) * 32;
        const int wnA = (wid >> 1) * 16;
        float accA[2][2][4];
#pragma unroll
        for (int mt = 0; mt < 2; mt++)
#pragma unroll
            for (int nt = 0; nt < 2; nt++)
#pragma unroll
                for (int j = 0; j < 4; j++) accA[mt][nt][j] = 0.f;

#pragma unroll
        for (int kc = 0; kc < 24; kc++) {
            const int t = kc >> 3;
            const int cb = (kc & 7) << 4;
            const int tq = (t == 1) ? 64 : 0;   // qh,ql,qh
            const int tk = (t == 2) ? 64 : 0;   // kh,kh,kl
            uint32_t a[2][4], bf[4];
#pragma unroll
            for (int mt = 0; mt < 2; mt++) {
                uint32_t ad = qB + (uint32_t)(((tq + wmA + mt * 16 + (lane & 15)) * 136
                                               + cb + ((lane >> 4) << 3)) * 2);
                LDSM(a[mt][0], a[mt][1], a[mt][2], a[mt][3], ad);
            }
            uint32_t bd = kB2 + (uint32_t)(((tk + wnA + (lane & 15)) * 136
                                            + cb + ((lane >> 4) << 3)) * 2);
            LDSM(bf[0], bf[1], bf[2], bf[3], bd);
#pragma unroll
            for (int mt = 0; mt < 2; mt++)
#pragma unroll
                for (int nt = 0; nt < 2; nt++)
                    MMA16816(accA[mt][nt], a[mt][0], a[mt][1], a[mt][2], a[mt][3],
                             bf[nt], bf[nt + 2]);
        }

        // masked write, stacked: Ah rows 0-63, Al rows 64-127
        const int er = wmA + (lane >> 2);
        const int ec = wnA + (lane & 3) * 2;
        __half* Ap = (__half*)(sm + CO_AP);
#pragma unroll
        for (int mt = 0; mt < 2; mt++)
#pragma unroll
            for (int nt = 0; nt < 2; nt++)
#pragma unroll
                for (int half = 0; half < 2; half++) {
                    int r = er + mt * 16 + half * 8;
                    int c = ec + nt * 8;
                    float v0 = (c     <= r) ? accA[mt][nt][half * 2 + 0] : 0.f;
                    float v1 = (c + 1 <= r) ? accA[mt][nt][half * 2 + 1] : 0.f;
                    __half2 hv, lv;
                    hv.x = __float2half(v0);
                    hv.y = __float2half(v1);
                    lv.x = __float2half(v0 - __half2float(hv.x));
                    lv.y = __float2half(v1 - __half2float(hv.y));
                    *(__half2*)(Ap + r * 136 + c)        = hv;
                    *(__half2*)(Ap + (r + 64) * 136 + c) = lv;
                }
    }
    asm volatile("cp.async.wait_group 0;");   // v,S landed
    __syncthreads();

    // ---- phase 3: o = A'.v' + q.S' ----
    const int warp_m = (wid & 1) * 32;
    const int warp_n = (wid >> 1) * 32;
    float acc[2][4][4];
#pragma unroll
    for (int mt = 0; mt < 2; mt++)
#pragma unroll
        for (int nt = 0; nt < 4; nt++)
#pragma unroll
            for (int j = 0; j < 4; j++) acc[mt][nt][j] = 0.f;

#pragma unroll
    for (int kc = 0; kc < 12; kc++) {       // A'.v' : Ah.vh + Al.vh + Ah.vl
        const int t = kc >> 2;
        const int cb = (kc & 3) << 4;
        const int ta = (t == 1) ? 64 : 0;
        const int br = ((t == 2) ? 64 : 0) + cb;
        uint32_t a[2][4], bf[2][4];
#pragma unroll
        for (int mt = 0; mt < 2; mt++) {
            uint32_t ad = aB + (uint32_t)(((ta + warp_m + mt * 16 + (lane & 15)) * 136
                                           + cb + ((lane >> 4) << 3)) * 2);
            LDSM(a[mt][0], a[mt][1], a[mt][2], a[mt][3], ad);
        }
#pragma unroll
        for (int ng = 0; ng < 2; ng++) {
            uint32_t bd = vB + (uint32_t)(((br + krl) * 136 + warp_n + ng * 16 + mco) * 2);
            LDSM_T(bf[ng][0], bf[ng][1], bf[ng][2], bf[ng][3], bd);
        }
#pragma unroll
        for (int mt = 0; mt < 2; mt++)
#pragma unroll
            for (int nt = 0; nt < 4; nt++) {
                const int g = nt >> 1, sel = nt & 1;
                MMA16816(acc[mt][nt], a[mt][0], a[mt][1], a[mt][2], a[mt][3],
                         bf[g][sel], bf[g][sel + 2]);
            }
    }
#pragma unroll
    for (int kc = 0; kc < 24; kc++) {       // q.S' : qh.Sh + ql.Sh + qh.Sl
        const int t = kc >> 3;
        const int cb = (kc & 7) << 4;
        const int tq = (t == 1) ? 64 : 0;
        const int sr = ((t == 2) ? 128 : 0) + cb;
        uint32_t a[2][4], bf[2][4];
#pragma unroll
        for (int mt = 0; mt < 2; mt++) {
            uint32_t ad = qB + (uint32_t)(((tq + warp_m + mt * 16 + (lane & 15)) * 136
                                           + cb + ((lane >> 4) << 3)) * 2);
            LDSM(a[mt][0], a[mt][1], a[mt][2], a[mt][3], ad);
        }
#pragma unroll
        for (int ng = 0; ng < 2; ng++) {
            uint32_t bd = sB + (uint32_t)(((sr + krl) * 136 + warp_n + ng * 16 + mco) * 2);
            LDSM_T(bf[ng][0], bf[ng][1], bf[ng][2], bf[ng][3], bd);
        }
#pragma unroll
        for (int mt = 0; mt < 2; mt++)
#pragma unroll
            for (int nt = 0; nt < 4; nt++) {
                const int g = nt >> 1, sel = nt & 1;
                MMA16816(acc[mt][nt], a[mt][0], a[mt][1], a[mt][2], a[mt][3],
                         bf[g][sel], bf[g][sel + 2]);
            }
    }

    // ---- phase 4: stage o fp32 (reuses sP region) ----
    __syncthreads();
    {
        const int er = warp_m + (lane >> 2);
        const int ec = warp_n + (lane & 3) * 2;
#pragma unroll
        for (int mt = 0; mt < 2; mt++)
#pragma unroll
            for (int nt = 0; nt < 4; nt++)
#pragma unroll
                for (int half = 0; half < 2; half++) {
                    int r = er + mt * 16 + half * 8;
                    *(float2*)(oS + r * 132 + ec + nt * 8) =
                        make_float2(acc[mt][nt][half * 2], acc[mt][nt][half * 2 + 1]);
                }
    }
    __syncthreads();

    // ---- phase 5: RMSNorm + fp16 write ----
    {
        const int r = tid >> 2;
        const int part = tid & 3;
        float vals[32];
        float s = 0.f;
#pragma unroll
        for (int j = 0; j < 32; j += 4) {
            float4 x = *(const float4*)(oS + r * 132 + part * 32 + j);
            vals[j] = x.x; vals[j+1] = x.y; vals[j+2] = x.z; vals[j+3] = x.w;
            s += x.x*x.x + x.y*x.y + x.z*x.z + x.w*x.w;
        }
        s += __shfl_xor_sync(0xffffffffu, s, 1);
        s += __shfl_xor_sync(0xffffffffu, s, 2);
        float scale = rsqrtf(s * (1.0f / 128.0f) + EPS);
        size_t R = (size_t)b * TT + (size_t)n * CHUNK + r;
        __half* p = os + R * 1024 + h * 128 + part * 32;
#pragma unroll
        for (int j = 0; j < 32; j += 2) {
            float vx = vals[j]   * scale * rms_w[part * 32 + j];
            float vy = vals[j+1] * scale * rms_w[part * 32 + j + 1];
            __half2 hv;
            hv.x = __float2half(vx);
            hv.y = __float2half(vy);
            *(__half2*)(p + j) = hv;
        }
    }
}

// ============================================================
// Launch
// ============================================================
extern "C" void kernel_launch(void* const* d_in, const int* in_sizes, int n_in,
                              void* d_out, int out_size)
{
    const float* x      = (const float*)d_in[0];
    const float* Wq     = (const float*)d_in[1];
    const float* Wk     = (const float*)d_in[2];
    const float* Wv     = (const float*)d_in[3];
    const float* fmq_w1 = (const float*)d_in[4];
    const float* fmq_b1 = (const float*)d_in[5];
    const float* fmq_w2 = (const float*)d_in[6];
    const float* fmq_b2 = (const float*)d_in[7];
    const float* fmk_w1 = (const float*)d_in[8];
    const float* fmk_b1 = (const float*)d_in[9];
    const float* fmk_w2 = (const float*)d_in[10];
    const float* fmk_b2 = (const float*)d_in[11];
    const float* rms_w  = (const float*)d_in[12];
    const float* Wo     = (const float*)d_in[13];
    float* out = (float*)d_out;

    float *bKV, *bc;
    cudaGetSymbolAddress((void**)&bKV, g_kv);
    cudaGetSymbolAddress((void**)&bc,  g_bc);

    __half *x16, *wv16, *wo16, *os, *wc, *qs, *ks, *vs, *ssb;
    cudaGetSymbolAddress((void**)&x16,  g_x16);
    cudaGetSymbolAddress((void**)&wv16, g_wv16);
    cudaGetSymbolAddress((void**)&wo16, g_wo16);
    cudaGetSymbolAddress((void**)&os,   g_os);
    cudaGetSymbolAddress((void**)&wc,   g_wc);
    cudaGetSymbolAddress((void**)&qs,   g_qs);
    cudaGetSymbolAddress((void**)&ks,   g_ks);
    cudaGetSymbolAddress((void**)&vs,   g_vs);
    cudaGetSymbolAddress((void**)&ssb,  g_ss);

    cudaFuncSetAttribute(composite_kernel, cudaFuncAttributeMaxDynamicSharedMemorySize, COMP_SMEM);
    cudaFuncSetAttribute(chunk_kv_mma,  cudaFuncAttributeMaxDynamicSharedMemorySize, KV_SMEM);
    cudaFuncSetAttribute(chunk_out_mma, cudaFuncAttributeMaxDynamicSharedMemorySize, CO_SMEM);
    cudaFuncSetAttribute(mma_gemm_kernel<0>, cudaFuncAttributeMaxDynamicSharedMemorySize, GEMM_SMEM);
    cudaFuncSetAttribute(mma_gemm_kernel<3>, cudaFuncAttributeMaxDynamicSharedMemorySize, GEMM_SMEM);
    cudaFuncSetAttribute(mma_gemm_kernel<4>, cudaFuncAttributeMaxDynamicSharedMemorySize, GEMM_SMEM);

    // ---- converts ----
    tof16_kernel<<<(MROWS * HID) / 512, 256>>>(x, x16, (size_t)MROWS * HID);
    tof16_kernel<<<(HID * HID) / 512, 256>>>(Wv, wv16, (size_t)HID * HID);
    tof16_kernel<<<(HID * HID) / 512, 256>>>(Wo, wo16, (size_t)HID * HID);

    // ---- composite fm∘proj weights: q rows 0-2047, k rows 2048-4095 ----
    const float scale = 0.08838834764831845f; // 128^-0.5
    dim3 gComp(8, 4, 8);
    composite_kernel<<<gComp, 256, COMP_SMEM>>>(fmq_w1, fmq_w2, fmq_b1, fmq_b2, Wq, wc, bc, scale);
    composite_kernel<<<gComp, 256, COMP_SMEM>>>(fmk_w1, fmk_w2, fmk_b1, fmk_b2, Wk,
                                                wc + (size_t)2 * HID * HID, bc + 2 * HID, 1.0f);

    // ---- merged q|k projection + V, emit pre-split fp16 tiles ----
    dim3 gQK(4 * HID / 128, MROWS / 128);   // (32, 128)
    dim3 gBig(HID / 128, MROWS / 128);      // (8, 128)
    mma_gemm_kernel<3><<<gQK, 256, GEMM_SMEM>>>(x16, wc, bc, nullptr, qs, ks, 4 * HID, HID, HID);
    mma_gemm_kernel<4><<<gBig, 256, GEMM_SMEM>>>(x16, wv16, nullptr, nullptr, vs, nullptr, HID, HID, HID);

    // ---- chunked linear attention ----
    const int nBlk = BB * NCH * HH;
    chunk_kv_mma<<<nBlk, 256, KV_SMEM>>>(ks, vs, bKV);
    scan_kv_kernel<<<(BB * HH * 16384) / 256, 256>>>(bKV, ssb);
    chunk_out_mma<<<nBlk, 256, CO_SMEM>>>(qs, ks, vs, ssb, rms_w, os);

    // ---- output projection ----
    mma_gemm_kernel<0><<<gBig, 256, GEMM_SMEM>>>(os, wo16, nullptr, out, nullptr, nullptr, HID, HID, HID);
}